// round 5
// baseline (speedup 1.0000x reference)
#include <cuda_runtime.h>
#include <cuda_fp16.h>

#define NN 2048
#define EE 65536
#define WORDS 64
#define NBMAX 2048
#define C_IN 128
#define H1D 3200
#define H2D 1600
#define ODIM 32
#define SK3 4

// ---------------- scratch (device globals) ----------------
__device__ unsigned g_adj[NN * WORDS];
__device__ unsigned g_rA [NN * WORDS];
__device__ unsigned g_rB [NN * WORDS];
__device__ int      g_nbr[(size_t)NN * NBMAX];
__device__ int      g_cnt[NN];
__device__ float    g_dvec[NN];
__device__ float    g_u  [NN * H2D];
__device__ float    g_va [NN * H2D];
__device__ float    g_vb [NN * H2D];
__device__ float    g_z  [NN * C_IN];
__device__ float    g_gg [NN * H2D];
__device__ float    g_h2 [NN * H2D];
__device__ float    g_g3 [NN * ODIM];
__device__ float    g_g3p[SK3 * NN * ODIM];
// fp16 operands
__device__ __half g_zhi[NN * C_IN],  g_zlo[NN * C_IN];
__device__ __half g_w1h[C_IN * H1D];
__device__ __half g_w2h[H1D * H2D];
__device__ __half g_h1hi[(size_t)NN * H1D], g_h1lo[(size_t)NN * H1D];

// ---------------- utility kernels ----------------
__global__ void k_zero_u32(unsigned* p, int n) {
    int i = blockIdx.x * blockDim.x + threadIdx.x;
    if (i < n) p[i] = 0u;
}

__global__ void k_build_adj(const int* __restrict__ ei, unsigned* __restrict__ adj) {
    int e = blockIdx.x * blockDim.x + threadIdx.x;
    if (e < EE) {
        int src = ei[e];
        int dst = ei[EE + e];
        atomicOr(&adj[dst * WORDS + (src >> 5)], 1u << (src & 31));
    }
}

__global__ void k_build_list(const unsigned* __restrict__ adj,
                             int* __restrict__ nbr, int* __restrict__ cnt) {
    int u = blockIdx.x * blockDim.x + threadIdx.x;
    if (u >= NN) return;
    int c = 0;
    int* out = nbr + (size_t)u * NBMAX;
    for (int w = 0; w < WORDS; ++w) {
        unsigned bits = adj[u * WORDS + w];
        while (bits) {
            int b = __ffs(bits) - 1;
            bits &= bits - 1;
            if (c < NBMAX) out[c] = w * 32 + b;
            ++c;
        }
    }
    cnt[u] = (c < NBMAX) ? c : NBMAX;
}

__global__ void k_reach_init(const unsigned* __restrict__ adj, unsigned* __restrict__ R) {
    int i = blockIdx.x * blockDim.x + threadIdx.x;
    if (i < NN * WORDS) {
        int u = i >> 6, w = i & 63;
        unsigned v = adj[i];
        if ((u >> 5) == w) v |= 1u << (u & 31);
        R[i] = v;
    }
}

__global__ void k_reach_iter(const int* __restrict__ nbr, const int* __restrict__ cnt,
                             const unsigned* __restrict__ Rold, unsigned* __restrict__ Rnew) {
    int u = blockIdx.x;
    int w = threadIdx.x;
    int n = __ldg(&cnt[u]);
    const int* list = nbr + (size_t)u * NBMAX;
    unsigned acc = ((u >> 5) == w) ? (1u << (u & 31)) : 0u;
    int j = 0;
    for (; j + 4 <= n; j += 4) {
        int v0 = __ldg(list + j + 0), v1 = __ldg(list + j + 1);
        int v2 = __ldg(list + j + 2), v3 = __ldg(list + j + 3);
        unsigned r0 = Rold[v0 * WORDS + w];
        unsigned r1 = Rold[v1 * WORDS + w];
        unsigned r2 = Rold[v2 * WORDS + w];
        unsigned r3 = Rold[v3 * WORDS + w];
        acc |= (r0 | r1) | (r2 | r3);
    }
    for (; j < n; ++j) acc |= Rold[__ldg(list + j) * WORDS + w];
    Rnew[u * WORDS + w] = acc;
}

__global__ void k_deg(const unsigned* __restrict__ R, float* __restrict__ d) {
    int u = blockIdx.x * blockDim.x + threadIdx.x;
    if (u < NN) {
        int c = 0;
        #pragma unroll 8
        for (int w = 0; w < WORDS; ++w) c += __popc(R[u * WORDS + w]);
        d[u] = (c > 0) ? rsqrtf((float)c) : 0.0f;
    }
}

__global__ void k_scale_u(const float* __restrict__ feat, const float* __restrict__ d,
                          float* __restrict__ u, float* __restrict__ v, int C) {
    int i = blockIdx.x * blockDim.x + threadIdx.x;
    if (i < NN * C) {
        float val = d[i / C] * feat[i];
        u[i] = val;
        v[i] = val;
    }
}

// ---- SpMM for small C (layers 1/3): neighbor-list gather from L2 ----
template <int NV>
__global__ __launch_bounds__(256)
void k_spmm(const int* __restrict__ nbr, const int* __restrict__ cnt,
            const float* __restrict__ vin, const float* __restrict__ uvec,
            float* __restrict__ vout,
            const float* __restrict__ wvec, int widx, int C) {
    int u = blockIdx.x;
    int t = threadIdx.x;
    int n = __ldg(&cnt[u]);
    const int* list = nbr + (size_t)u * NBMAX;
    const int C4 = C >> 2;
    float wk = __ldg(&wvec[widx]);

    float4 acc[NV];
    #pragma unroll
    for (int q = 0; q < NV; ++q) acc[q] = make_float4(0.f, 0.f, 0.f, 0.f);

    int j = 0;
    for (; j + 4 <= n; j += 4) {
        int v0 = __ldg(list + j + 0), v1 = __ldg(list + j + 1);
        int v2 = __ldg(list + j + 2), v3 = __ldg(list + j + 3);
        const float4* r0 = reinterpret_cast<const float4*>(vin + (size_t)v0 * C);
        const float4* r1 = reinterpret_cast<const float4*>(vin + (size_t)v1 * C);
        const float4* r2 = reinterpret_cast<const float4*>(vin + (size_t)v2 * C);
        const float4* r3 = reinterpret_cast<const float4*>(vin + (size_t)v3 * C);
        #pragma unroll
        for (int q = 0; q < NV; ++q) {
            int idx = t + q * 256;
            if (idx < C4) {
                float4 x0 = __ldg(r0 + idx);
                float4 x1 = __ldg(r1 + idx);
                float4 x2 = __ldg(r2 + idx);
                float4 x3 = __ldg(r3 + idx);
                acc[q].x += (x0.x + x1.x) + (x2.x + x3.x);
                acc[q].y += (x0.y + x1.y) + (x2.y + x3.y);
                acc[q].z += (x0.z + x1.z) + (x2.z + x3.z);
                acc[q].w += (x0.w + x1.w) + (x2.w + x3.w);
            }
        }
    }
    for (; j < n; ++j) {
        int v = __ldg(list + j);
        const float4* r = reinterpret_cast<const float4*>(vin + (size_t)v * C);
        #pragma unroll
        for (int q = 0; q < NV; ++q) {
            int idx = t + q * 256;
            if (idx < C4) {
                float4 x = __ldg(r + idx);
                acc[q].x += x.x; acc[q].y += x.y; acc[q].z += x.z; acc[q].w += x.w;
            }
        }
    }
    const float4* urow = reinterpret_cast<const float4*>(uvec + (size_t)u * C);
    float4* orow = reinterpret_cast<float4*>(vout + (size_t)u * C);
    #pragma unroll
    for (int q = 0; q < NV; ++q) {
        int idx = t + q * 256;
        if (idx < C4) {
            float4 uu = urow[idx];
            float4 o;
            o.x = uu.x + wk * acc[q].x;
            o.y = uu.y + wk * acc[q].y;
            o.z = uu.z + wk * acc[q].z;
            o.w = uu.w + wk * acc[q].w;
            orow[idx] = o;
        }
    }
}

// ---- SpMM for large C: smem-resident channel slice (16 ch / CTA) ----
// smem layout channel-major: sm[c * SPLN + row], SPLN=2049 -> bank=(c+row)%32.
#define SCH 16
#define SPLN 2049
#define SPMM_SMEM (SCH * SPLN * 4)

__global__ __launch_bounds__(512)
void k_spmm_l2(const int* __restrict__ nbr, const int* __restrict__ cnt,
               const float* __restrict__ vin, const float* __restrict__ uvec,
               float* __restrict__ vout,
               const float* __restrict__ wvec, int widx, int C) {
    extern __shared__ float sm[];
    const int c0 = blockIdx.x * SCH;
    const int tid = threadIdx.x;
    const float wk = __ldg(&wvec[widx]);

    // load + transpose slice: vin[:, c0:c0+16] -> sm[c][row]
    for (int idx = tid; idx < NN * (SCH / 4); idx += 512) {
        int row = idx >> 2;
        int cq = (idx & 3) << 2;
        float4 v = *reinterpret_cast<const float4*>(vin + (size_t)row * C + c0 + cq);
        sm[(cq + 0) * SPLN + row] = v.x;
        sm[(cq + 1) * SPLN + row] = v.y;
        sm[(cq + 2) * SPLN + row] = v.z;
        sm[(cq + 3) * SPLN + row] = v.w;
    }
    __syncthreads();

    const int wid = tid >> 5, lane = tid & 31;
    const int half = lane >> 4, c = lane & 15;
    const float* plane = sm + c * SPLN;

    for (int r = wid; r < NN; r += 16) {
        int n = __ldg(&cnt[r]);
        const int* list = nbr + (size_t)r * NBMAX;
        float s0 = 0.f, s1 = 0.f, s2 = 0.f, s3 = 0.f;
        int j = half;
        for (; j + 6 < n; j += 8) {
            int v0 = __ldg(list + j),     v1 = __ldg(list + j + 2);
            int v2 = __ldg(list + j + 4), v3 = __ldg(list + j + 6);
            s0 += plane[v0]; s1 += plane[v1]; s2 += plane[v2]; s3 += plane[v3];
        }
        for (; j < n; j += 2) s0 += plane[__ldg(list + j)];
        float s = (s0 + s1) + (s2 + s3);
        s += __shfl_down_sync(0xffffffffu, s, 16);
        if (half == 0) {
            size_t o = (size_t)r * C + c0 + c;
            vout[o] = uvec[o] + wk * s;
        }
    }
}

__global__ void k_scale_z(const float* __restrict__ v, const float* __restrict__ d,
                          const float* __restrict__ wvec, float* __restrict__ z, int C) {
    int i = blockIdx.x * blockDim.x + threadIdx.x;
    if (i < NN * C) z[i] = wvec[0] * d[i / C] * v[i];
}

__global__ void k_final(const float* __restrict__ v, const float* __restrict__ d,
                        const float* __restrict__ wvec, const float* __restrict__ bias,
                        float* __restrict__ out, int C) {
    int i = blockIdx.x * blockDim.x + threadIdx.x;
    if (i < NN * C) {
        float val = wvec[0] * d[i / C] * v[i] + bias[i % C];
        out[i] = fmaxf(val, 0.0f);
    }
}

__global__ void k_reduce_sk(const float* __restrict__ p, float* __restrict__ out, int n) {
    int i = blockIdx.x * blockDim.x + threadIdx.x;
    if (i < n) {
        float s = 0.f;
        #pragma unroll
        for (int k = 0; k < SK3; ++k) s += p[(size_t)k * n + i];
        out[i] = s;
    }
}

// fp32 -> (hi, lo) fp16
__global__ void k_split_h(const float* __restrict__ s, __half* __restrict__ hi,
                          __half* __restrict__ lo, int n) {
    int i = blockIdx.x * blockDim.x + threadIdx.x;
    if (i < n) {
        float x = s[i];
        __half h = __float2half_rn(x);
        hi[i] = h;
        lo[i] = __float2half_rn(x - __half2float(h));
    }
}

// fp32 -> fp16
__global__ void k_tohalf(const float* __restrict__ s, __half* __restrict__ h, int n) {
    int i = blockIdx.x * blockDim.x + threadIdx.x;
    if (i < n) h[i] = __float2half_rn(s[i]);
}

// ---------------- cp.async helpers ----------------
__device__ __forceinline__ void cpasync16(void* s, const void* g, bool p) {
    unsigned sa = (unsigned)__cvta_generic_to_shared(s);
    asm volatile("cp.async.cg.shared.global [%0], [%1], 16, %2;"
                 :: "r"(sa), "l"(g), "r"(p ? 16 : 0));
}
__device__ __forceinline__ void cp_commit() { asm volatile("cp.async.commit_group;" ::: "memory"); }
__device__ __forceinline__ void cp_wait0()  { asm volatile("cp.async.wait_group 0;" ::: "memory"); }
__device__ __forceinline__ void cp_wait1()  { asm volatile("cp.async.wait_group 1;" ::: "memory"); }

// ---------------- fp16 2-term tensor-core GEMM ----------------
// D = (Ahi + Alo) * Bh  (A split fp16, B single fp16; fp32 accumulate)
#define TBM 128
#define TBN 128
#define TBK 32
#define ASTR 40
#define BSTR 136
#define ABUF (TBM * ASTR)
#define BBUF (TBK * BSTR)
#define SMEM_ELEMS (4 * ABUF + 2 * BBUF)
#define SMEM_BYTES (SMEM_ELEMS * 2)

__device__ __forceinline__ unsigned sptr(const void* p) {
    return (unsigned)__cvta_generic_to_shared(p);
}
__device__ __forceinline__ void ldsm4(unsigned& r0, unsigned& r1, unsigned& r2, unsigned& r3, unsigned a) {
    asm volatile("ldmatrix.sync.aligned.m8n8.x4.shared.b16 {%0,%1,%2,%3}, [%4];"
                 : "=r"(r0), "=r"(r1), "=r"(r2), "=r"(r3) : "r"(a));
}
__device__ __forceinline__ void ldsm4t(unsigned& r0, unsigned& r1, unsigned& r2, unsigned& r3, unsigned a) {
    asm volatile("ldmatrix.sync.aligned.m8n8.x4.trans.shared.b16 {%0,%1,%2,%3}, [%4];"
                 : "=r"(r0), "=r"(r1), "=r"(r2), "=r"(r3) : "r"(a));
}
__device__ __forceinline__ void mma16816h(float* c, const unsigned* a, unsigned b0, unsigned b1) {
    asm volatile("mma.sync.aligned.m16n8k16.row.col.f32.f16.f16.f32 "
                 "{%0,%1,%2,%3},{%4,%5,%6,%7},{%8,%9},{%0,%1,%2,%3};"
                 : "+f"(c[0]), "+f"(c[1]), "+f"(c[2]), "+f"(c[3])
                 : "r"(a[0]), "r"(a[1]), "r"(a[2]), "r"(a[3]), "r"(b0), "r"(b1));
}

// EPI=1: +bias, relu, write split fp16 (Chi/Clo, ld=Nd).  EPI=0: fp32 out Cf (ldc), col<Nd guard.
template<int EPI>
__global__ __launch_bounds__(256, 1)
void k_gemm_h(const __half* __restrict__ Ahi, const __half* __restrict__ Alo, int lda,
              const __half* __restrict__ Bh, int ldb,
              const float* __restrict__ bias,
              float* __restrict__ Cf, __half* __restrict__ Chi, __half* __restrict__ Clo,
              int ldc, int Nd, int K) {
    extern __shared__ __half smh[];
    __half* sAh = smh;
    __half* sAl = sAh + 2 * ABUF;
    __half* sBh = sAl + 2 * ABUF;

    const int tid = threadIdx.x;
    const int wid = tid >> 5, lane = tid & 31;
    const int wm = (wid & 1) * 64;
    const int wn = (wid >> 1) * 32;
    const int m0 = blockIdx.y * TBM, n0 = blockIdx.x * TBN;

    const int a_r = tid >> 2;
    const int a_c = (tid & 3) << 3;
    const int b_r = tid >> 4;
    const int b_c = (tid & 15) << 3;
    const bool pb = (n0 + b_c) < Nd;

    const __half* gAh0 = Ahi + (size_t)(m0 + a_r) * lda + a_c;
    const __half* gAh1 = Ahi + (size_t)(m0 + a_r + 64) * lda + a_c;
    const __half* gAl0 = Alo + (size_t)(m0 + a_r) * lda + a_c;
    const __half* gAl1 = Alo + (size_t)(m0 + a_r + 64) * lda + a_c;
    const __half* gB0  = Bh + (size_t)b_r * ldb + n0 + b_c;
    const __half* gB1  = Bh + (size_t)(b_r + 16) * ldb + n0 + b_c;

    float acc[4][4][4];
    #pragma unroll
    for (int i = 0; i < 4; ++i)
        #pragma unroll
        for (int j = 0; j < 4; ++j)
            #pragma unroll
            for (int q = 0; q < 4; ++q) acc[i][j][q] = 0.f;

    const int KT = K / TBK;

    cpasync16(sAh + a_r * ASTR + a_c, gAh0, true);
    cpasync16(sAh + (a_r + 64) * ASTR + a_c, gAh1, true);
    cpasync16(sAl + a_r * ASTR + a_c, gAl0, true);
    cpasync16(sAl + (a_r + 64) * ASTR + a_c, gAl1, true);
    cpasync16(sBh + b_r * BSTR + b_c, gB0, pb);
    cpasync16(sBh + (b_r + 16) * BSTR + b_c, gB1, pb);
    cp_commit();

    const int l16 = lane & 15;
    const int hsel = (lane >> 4) << 3;
    const int bg = lane >> 3, bl8 = lane & 7;
    const int bkoff = ((bg & 1) << 3) + bl8;
    const int bnoff = wn + ((bg >> 1) << 3);

    int buf = 0;
    for (int kt = 0; kt < KT; ++kt) {
        if (kt + 1 < KT) {
            int ko = (kt + 1) * TBK;
            int ob = (buf ^ 1);
            cpasync16(sAh + ob * ABUF + a_r * ASTR + a_c, gAh0 + ko, true);
            cpasync16(sAh + ob * ABUF + (a_r + 64) * ASTR + a_c, gAh1 + ko, true);
            cpasync16(sAl + ob * ABUF + a_r * ASTR + a_c, gAl0 + ko, true);
            cpasync16(sAl + ob * ABUF + (a_r + 64) * ASTR + a_c, gAl1 + ko, true);
            cpasync16(sBh + ob * BBUF + b_r * BSTR + b_c, gB0 + (size_t)ko * ldb, pb);
            cpasync16(sBh + ob * BBUF + (b_r + 16) * BSTR + b_c, gB1 + (size_t)ko * ldb, pb);
            cp_commit();
            cp_wait1();
        } else {
            cp_wait0();
        }
        __syncthreads();

        #pragma unroll
        for (int ks = 0; ks < 2; ++ks) {
            const int ko = ks * 16;
            unsigned bh[8];
            {
                unsigned ab = sptr(sBh + buf * BBUF + (ko + bkoff) * BSTR + bnoff);
                ldsm4t(bh[0], bh[1], bh[2], bh[3], ab);
                ldsm4t(bh[4], bh[5], bh[6], bh[7], ab + 32);
            }
            #pragma unroll
            for (int mi = 0; mi < 4; ++mi) {
                unsigned ah[4], alr[4];
                unsigned aa = sptr(sAh + buf * ABUF + (wm + mi * 16 + l16) * ASTR + ko + hsel);
                ldsm4(ah[0], ah[1], ah[2], ah[3], aa);
                unsigned aal = sptr(sAl + buf * ABUF + (wm + mi * 16 + l16) * ASTR + ko + hsel);
                ldsm4(alr[0], alr[1], alr[2], alr[3], aal);
                #pragma unroll
                for (int nj = 0; nj < 4; ++nj) {
                    int bi = (nj >> 1) * 4 + (nj & 1) * 2;
                    mma16816h(acc[mi][nj], ah, bh[bi], bh[bi + 1]);
                    mma16816h(acc[mi][nj], alr, bh[bi], bh[bi + 1]);
                }
            }
        }
        __syncthreads();
        buf ^= 1;
    }

    const int er = lane >> 2;
    const int ec = (lane & 3) << 1;
    #pragma unroll
    for (int mi = 0; mi < 4; ++mi) {
        #pragma unroll
        for (int nj = 0; nj < 4; ++nj) {
            int row = m0 + wm + mi * 16 + er;
            int col = n0 + wn + nj * 8 + ec;
            float* a = acc[mi][nj];
            if (EPI) {
                float bv0 = bias[col], bv1 = bias[col + 1];
                #pragma unroll
                for (int h = 0; h < 2; ++h) {
                    int r = row + h * 8;
                    float v0 = fmaxf(a[h * 2 + 0] + bv0, 0.f);
                    float v1 = fmaxf(a[h * 2 + 1] + bv1, 0.f);
                    __half h0 = __float2half_rn(v0);
                    __half h1 = __float2half_rn(v1);
                    __half2 hp; hp.x = h0; hp.y = h1;
                    __half2 lp;
                    lp.x = __float2half_rn(v0 - __half2float(h0));
                    lp.y = __float2half_rn(v1 - __half2float(h1));
                    *reinterpret_cast<__half2*>(&Chi[(size_t)r * Nd + col]) = hp;
                    *reinterpret_cast<__half2*>(&Clo[(size_t)r * Nd + col]) = lp;
                }
            } else {
                if (col < Nd) {
                    *reinterpret_cast<float2*>(&Cf[(size_t)row * ldc + col]) = make_float2(a[0], a[1]);
                    *reinterpret_cast<float2*>(&Cf[(size_t)(row + 8) * ldc + col]) = make_float2(a[2], a[3]);
                }
            }
        }
    }
}

// ---------------- fp32 GEMM (tiny GEMM3, split-K) ----------------
#define BM 128
#define BK 16

template<int BN_, int TN_>
__global__ __launch_bounds__(256)
void k_gemm(const float* __restrict__ A, int lda,
            const float* __restrict__ B, int ldb,
            float* __restrict__ Cout, int ldc,
            int Nd, int Kloop, int partStride) {
    __shared__ float As[2][BM][BK];
    __shared__ float Bs[2][BK][BN_];

    const int tid = threadIdx.x;
    const int tx = tid & 15;
    const int ty = tid >> 4;
    const int m0 = blockIdx.y * BM;
    const int n0 = blockIdx.x * BN_;

    A += (size_t)blockIdx.z * Kloop;
    B += (size_t)blockIdx.z * Kloop * ldb;
    Cout += (size_t)blockIdx.z * partStride;

    const int arow0 = tid >> 2;
    const int arow1 = arow0 + 64;
    const int ac4 = (tid & 3) * 4;
    const float* gA0 = A + (size_t)(m0 + arow0) * lda + ac4;
    const float* gA1 = A + (size_t)(m0 + arow1) * lda + ac4;

    const int BQ = BN_ / 4;
    const int bkr0 = tid / BQ;
    const int bc0 = (tid % BQ) * 4;
    const float* gB0 = B + (size_t)bkr0 * ldb + n0 + bc0;
    const bool bp0 = (n0 + bc0) < Nd;

    float acc[8][TN_];
    #pragma unroll
    for (int i = 0; i < 8; ++i)
        #pragma unroll
        for (int j = 0; j < TN_; ++j) acc[i][j] = 0.f;

    const int KT = Kloop / BK;

    cpasync16(&As[0][arow0][ac4], gA0, true);
    cpasync16(&As[0][arow1][ac4], gA1, true);
    cpasync16(&Bs[0][bkr0][bc0], gB0, bp0);
    cp_commit();

    int buf = 0;
    for (int kt = 0; kt < KT; ++kt) {
        if (kt + 1 < KT) {
            int ko = (kt + 1) * BK;
            cpasync16(&As[buf ^ 1][arow0][ac4], gA0 + ko, true);
            cpasync16(&As[buf ^ 1][arow1][ac4], gA1 + ko, true);
            cpasync16(&Bs[buf ^ 1][bkr0][bc0], gB0 + (size_t)ko * ldb, bp0);
            cp_commit();
            cp_wait1();
        } else {
            cp_wait0();
        }
        __syncthreads();

        #pragma unroll
        for (int k = 0; k < BK; ++k) {
            float a[8];
            #pragma unroll
            for (int i = 0; i < 8; ++i) a[i] = As[buf][ty * 8 + i][k];
            float b[TN_];
            #pragma unroll
            for (int j = 0; j < TN_; j += 4) {
                float4 v = *reinterpret_cast<const float4*>(&Bs[buf][k][tx * TN_ + j]);
                b[j] = v.x; b[j + 1] = v.y; b[j + 2] = v.z; b[j + 3] = v.w;
            }
            #pragma unroll
            for (int i = 0; i < 8; ++i)
                #pragma unroll
                for (int j = 0; j < TN_; ++j)
                    acc[i][j] += a[i] * b[j];
        }
        __syncthreads();
        buf ^= 1;
    }

    #pragma unroll
    for (int i = 0; i < 8; ++i) {
        int m = m0 + ty * 8 + i;
        #pragma unroll
        for (int j = 0; j < TN_; j += 4) {
            int n = n0 + tx * TN_ + j;
            if (n < Nd) {
                float4 v = make_float4(acc[i][j], acc[i][j + 1], acc[i][j + 2], acc[i][j + 3]);
                *reinterpret_cast<float4*>(&Cout[(size_t)m * ldc + n]) = v;
            }
        }
    }
}

// ---------------- host orchestration ----------------
static float* run_prop(const int* nbr, const int* cnt, const float* dvec,
                       const float* feat, const float* w, int C,
                       float* u, float* va, float* vb) {
    int total = NN * C;
    k_scale_u<<<(total + 255) / 256, 256>>>(feat, dvec, u, va, C);
    float* vin = va;
    float* vout = vb;
    for (int k = 5; k >= 1; --k) {
        if (C >= 1024) k_spmm_l2<<<C / SCH, 512, SPMM_SMEM>>>(nbr, cnt, vin, u, vout, w, k, C);
        else           k_spmm<1><<<NN, 256>>>(nbr, cnt, vin, u, vout, w, k, C);
        float* t = vin; vin = vout; vout = t;
    }
    return vin;
}

extern "C" void kernel_launch(void* const* d_in, const int* in_sizes, int n_in,
                              void* d_out, int out_size) {
    const float* x  = (const float*)d_in[0];
    const int*   ei = (const int*)  d_in[1];
    const float* w1 = (const float*)d_in[2];
    const float* w2 = (const float*)d_in[3];
    const float* w3 = (const float*)d_in[4];
    const float* W1 = (const float*)d_in[5];
    const float* b1 = (const float*)d_in[6];
    const float* W2 = (const float*)d_in[7];
    const float* b2 = (const float*)d_in[8];
    const float* W3 = (const float*)d_in[9];
    const float* b3 = (const float*)d_in[10];
    float* out = (float*)d_out;

    unsigned *adj, *rA, *rB;
    int *nbr, *cnt;
    float *dvec, *u, *va, *vb, *z, *gg, *h2, *g3, *g3p;
    __half *zhi, *zlo, *w1h, *w2h, *h1hi, *h1lo;
    cudaGetSymbolAddress((void**)&adj,  g_adj);
    cudaGetSymbolAddress((void**)&rA,   g_rA);
    cudaGetSymbolAddress((void**)&rB,   g_rB);
    cudaGetSymbolAddress((void**)&nbr,  g_nbr);
    cudaGetSymbolAddress((void**)&cnt,  g_cnt);
    cudaGetSymbolAddress((void**)&dvec, g_dvec);
    cudaGetSymbolAddress((void**)&u,    g_u);
    cudaGetSymbolAddress((void**)&va,   g_va);
    cudaGetSymbolAddress((void**)&vb,   g_vb);
    cudaGetSymbolAddress((void**)&z,    g_z);
    cudaGetSymbolAddress((void**)&gg,   g_gg);
    cudaGetSymbolAddress((void**)&h2,   g_h2);
    cudaGetSymbolAddress((void**)&g3,   g_g3);
    cudaGetSymbolAddress((void**)&g3p,  g_g3p);
    cudaGetSymbolAddress((void**)&zhi,  g_zhi);
    cudaGetSymbolAddress((void**)&zlo,  g_zlo);
    cudaGetSymbolAddress((void**)&w1h,  g_w1h);
    cudaGetSymbolAddress((void**)&w2h,  g_w2h);
    cudaGetSymbolAddress((void**)&h1hi, g_h1hi);
    cudaGetSymbolAddress((void**)&h1lo, g_h1lo);

    cudaFuncSetAttribute(k_gemm_h<0>, cudaFuncAttributeMaxDynamicSharedMemorySize, SMEM_BYTES);
    cudaFuncSetAttribute(k_gemm_h<1>, cudaFuncAttributeMaxDynamicSharedMemorySize, SMEM_BYTES);
    cudaFuncSetAttribute(k_spmm_l2, cudaFuncAttributeMaxDynamicSharedMemorySize, SPMM_SMEM);

    // ---- adjacency + neighbor lists + reach + deg ----
    k_zero_u32<<<(NN * WORDS + 255) / 256, 256>>>(adj, NN * WORDS);
    k_build_adj<<<EE / 256, 256>>>(ei, adj);
    k_build_list<<<NN / 256, 256>>>(adj, nbr, cnt);
    k_reach_init<<<(NN * WORDS + 255) / 256, 256>>>(adj, rA);
    k_reach_iter<<<NN, 64>>>(nbr, cnt, rA, rB);
    k_reach_iter<<<NN, 64>>>(nbr, cnt, rB, rA);
    k_reach_iter<<<NN, 64>>>(nbr, cnt, rA, rB);
    k_reach_iter<<<NN, 64>>>(nbr, cnt, rB, rA);
    k_deg<<<(NN + 255) / 256, 256>>>(rA, dvec);

    // weight conversions (independent; issue early)
    k_tohalf<<<(C_IN * H1D + 255) / 256, 256>>>(W1, w1h, C_IN * H1D);
    k_tohalf<<<(H1D * H2D + 255) / 256, 256>>>(W2, w2h, H1D * H2D);

    // ---- layer 1: h1 = relu((M1_hat x) W1 + b1), split-fp16 output ----
    {
        float* v = run_prop(nbr, cnt, dvec, x, w1, C_IN, u, va, vb);
        k_scale_z<<<(NN * C_IN + 255) / 256, 256>>>(v, dvec, w1, z, C_IN);
        k_split_h<<<(NN * C_IN + 255) / 256, 256>>>(z, zhi, zlo, NN * C_IN);
        dim3 grid(H1D / TBN, NN / TBM, 1);
        k_gemm_h<1><<<grid, 256, SMEM_BYTES>>>(zhi, zlo, C_IN, w1h, H1D,
                                               b1, (float*)0, h1hi, h1lo, H1D, H1D, C_IN);
    }

    // ---- layer 2: h2 = relu(M2_hat (h1 W2) + b2) ----
    {
        dim3 grid((H2D + TBN - 1) / TBN, NN / TBM, 1);
        k_gemm_h<0><<<grid, 256, SMEM_BYTES>>>(h1hi, h1lo, H1D, w2h, H2D,
                                               (const float*)0, gg, (__half*)0, (__half*)0,
                                               H2D, H2D, H1D);
        float* v = run_prop(nbr, cnt, dvec, gg, w2, H2D, u, va, vb);
        k_final<<<(NN * H2D + 255) / 256, 256>>>(v, dvec, w2, b2, h2, H2D);
    }

    // ---- layer 3: out = relu(M3_hat (h2 W3) + b3), fp32 split-K GEMM ----
    {
        dim3 grid(1, NN / BM, SK3);
        k_gemm<64, 4><<<grid, 256>>>(h2, H2D, W3, ODIM, g3p, ODIM, ODIM, H2D / SK3, NN * ODIM);
        k_reduce_sk<<<(NN * ODIM + 255) / 256, 256>>>(g3p, g3, NN * ODIM);
        float* v = run_prop(nbr, cnt, dvec, g3, w3, ODIM, u, va, vb);
        k_final<<<(NN * ODIM + 255) / 256, 256>>>(v, dvec, w3, b3, out, ODIM);
    }
}

// round 6
// speedup vs baseline: 2.2295x; 2.2295x over previous
#include <cuda_runtime.h>
#include <cuda_fp16.h>

#define NN 2048
#define EE 65536
#define WORDS 64
#define NBMAX 2048
#define C_IN 128
#define H1D 3200
#define H2D 1600
#define ODIM 32
#define SK3 4

// ---------------- scratch (device globals) ----------------
__device__ unsigned g_adj[NN * WORDS];
__device__ unsigned g_rA [NN * WORDS];
__device__ unsigned g_rB [NN * WORDS];
__device__ int      g_nbr[(size_t)NN * NBMAX];
__device__ int      g_cnt[NN];
__device__ float    g_dvec[NN];
__device__ float    g_u  [NN * H2D];
__device__ float    g_va [NN * H2D];
__device__ float    g_vb [NN * H2D];
__device__ float    g_z  [NN * C_IN];
__device__ float    g_gg [NN * H2D];
__device__ float    g_h2 [NN * H2D];
__device__ float    g_g3 [NN * ODIM];
__device__ float    g_g3p[SK3 * NN * ODIM];
// fp16 operands
__device__ __half g_zhi[NN * C_IN],  g_zlo[NN * C_IN];
__device__ __half g_w1h[C_IN * H1D];
__device__ __half g_w2h[H1D * H2D];
__device__ __half g_h1hi[(size_t)NN * H1D], g_h1lo[(size_t)NN * H1D];

// ---------------- utility kernels ----------------
__global__ void k_zero_u32(unsigned* p, int n) {
    int i = blockIdx.x * blockDim.x + threadIdx.x;
    if (i < n) p[i] = 0u;
}

__global__ void k_build_adj(const int* __restrict__ ei, unsigned* __restrict__ adj) {
    int e = blockIdx.x * blockDim.x + threadIdx.x;
    if (e < EE) {
        int src = ei[e];
        int dst = ei[EE + e];
        atomicOr(&adj[dst * WORDS + (src >> 5)], 1u << (src & 31));
    }
}

__global__ void k_build_list(const unsigned* __restrict__ adj,
                             int* __restrict__ nbr, int* __restrict__ cnt) {
    int u = blockIdx.x * blockDim.x + threadIdx.x;
    if (u >= NN) return;
    int c = 0;
    int* out = nbr + (size_t)u * NBMAX;
    for (int w = 0; w < WORDS; ++w) {
        unsigned bits = adj[u * WORDS + w];
        while (bits) {
            int b = __ffs(bits) - 1;
            bits &= bits - 1;
            if (c < NBMAX) out[c] = w * 32 + b;
            ++c;
        }
    }
    cnt[u] = (c < NBMAX) ? c : NBMAX;
}

__global__ void k_reach_init(const unsigned* __restrict__ adj, unsigned* __restrict__ R) {
    int i = blockIdx.x * blockDim.x + threadIdx.x;
    if (i < NN * WORDS) {
        int u = i >> 6, w = i & 63;
        unsigned v = adj[i];
        if ((u >> 5) == w) v |= 1u << (u & 31);
        R[i] = v;
    }
}

__global__ void k_reach_iter(const int* __restrict__ nbr, const int* __restrict__ cnt,
                             const unsigned* __restrict__ Rold, unsigned* __restrict__ Rnew) {
    int u = blockIdx.x;
    int w = threadIdx.x;
    int n = __ldg(&cnt[u]);
    const int* list = nbr + (size_t)u * NBMAX;
    unsigned acc = ((u >> 5) == w) ? (1u << (u & 31)) : 0u;
    int j = 0;
    for (; j + 4 <= n; j += 4) {
        int v0 = __ldg(list + j + 0), v1 = __ldg(list + j + 1);
        int v2 = __ldg(list + j + 2), v3 = __ldg(list + j + 3);
        unsigned r0 = Rold[v0 * WORDS + w];
        unsigned r1 = Rold[v1 * WORDS + w];
        unsigned r2 = Rold[v2 * WORDS + w];
        unsigned r3 = Rold[v3 * WORDS + w];
        acc |= (r0 | r1) | (r2 | r3);
    }
    for (; j < n; ++j) acc |= Rold[__ldg(list + j) * WORDS + w];
    Rnew[u * WORDS + w] = acc;
}

__global__ void k_deg(const unsigned* __restrict__ R, float* __restrict__ d) {
    int u = blockIdx.x * blockDim.x + threadIdx.x;
    if (u < NN) {
        int c = 0;
        #pragma unroll 8
        for (int w = 0; w < WORDS; ++w) c += __popc(R[u * WORDS + w]);
        d[u] = (c > 0) ? rsqrtf((float)c) : 0.0f;
    }
}

__global__ void k_scale_u(const float* __restrict__ feat, const float* __restrict__ d,
                          float* __restrict__ u, float* __restrict__ v, int C) {
    int i = blockIdx.x * blockDim.x + threadIdx.x;
    if (i < NN * C) {
        float val = d[i / C] * feat[i];
        u[i] = val;
        v[i] = val;
    }
}

// ---- SpMM for large C (1600): block-per-row float4 gather (LTS-bound) ----
template <int NV>
__global__ __launch_bounds__(256)
void k_spmm(const int* __restrict__ nbr, const int* __restrict__ cnt,
            const float* __restrict__ vin, const float* __restrict__ uvec,
            float* __restrict__ vout,
            const float* __restrict__ wvec, int widx, int C) {
    int u = blockIdx.x;
    int t = threadIdx.x;
    int n = __ldg(&cnt[u]);
    const int* list = nbr + (size_t)u * NBMAX;
    const int C4 = C >> 2;
    float wk = __ldg(&wvec[widx]);

    float4 acc[NV];
    #pragma unroll
    for (int q = 0; q < NV; ++q) acc[q] = make_float4(0.f, 0.f, 0.f, 0.f);

    int j = 0;
    for (; j + 4 <= n; j += 4) {
        int v0 = __ldg(list + j + 0), v1 = __ldg(list + j + 1);
        int v2 = __ldg(list + j + 2), v3 = __ldg(list + j + 3);
        const float4* r0 = reinterpret_cast<const float4*>(vin + (size_t)v0 * C);
        const float4* r1 = reinterpret_cast<const float4*>(vin + (size_t)v1 * C);
        const float4* r2 = reinterpret_cast<const float4*>(vin + (size_t)v2 * C);
        const float4* r3 = reinterpret_cast<const float4*>(vin + (size_t)v3 * C);
        #pragma unroll
        for (int q = 0; q < NV; ++q) {
            int idx = t + q * 256;
            if (idx < C4) {
                float4 x0 = __ldg(r0 + idx);
                float4 x1 = __ldg(r1 + idx);
                float4 x2 = __ldg(r2 + idx);
                float4 x3 = __ldg(r3 + idx);
                acc[q].x += (x0.x + x1.x) + (x2.x + x3.x);
                acc[q].y += (x0.y + x1.y) + (x2.y + x3.y);
                acc[q].z += (x0.z + x1.z) + (x2.z + x3.z);
                acc[q].w += (x0.w + x1.w) + (x2.w + x3.w);
            }
        }
    }
    for (; j < n; ++j) {
        int v = __ldg(list + j);
        const float4* r = reinterpret_cast<const float4*>(vin + (size_t)v * C);
        #pragma unroll
        for (int q = 0; q < NV; ++q) {
            int idx = t + q * 256;
            if (idx < C4) {
                float4 x = __ldg(r + idx);
                acc[q].x += x.x; acc[q].y += x.y; acc[q].z += x.z; acc[q].w += x.w;
            }
        }
    }
    const float4* urow = reinterpret_cast<const float4*>(uvec + (size_t)u * C);
    float4* orow = reinterpret_cast<float4*>(vout + (size_t)u * C);
    #pragma unroll
    for (int q = 0; q < NV; ++q) {
        int idx = t + q * 256;
        if (idx < C4) {
            float4 uu = urow[idx];
            float4 o;
            o.x = uu.x + wk * acc[q].x;
            o.y = uu.y + wk * acc[q].y;
            o.z = uu.z + wk * acc[q].z;
            o.w = uu.w + wk * acc[q].w;
            orow[idx] = o;
        }
    }
}

// ---- SpMM for small C: LPR float4-lanes per row, 256/LPR rows per block ----
// Requires C == 4*LPR.  Full thread utilization (R4 wasted 224-248/256 threads).
template <int LPR>
__global__ __launch_bounds__(256)
void k_spmm_s(const int* __restrict__ nbr, const int* __restrict__ cnt,
              const float* __restrict__ vin, const float* __restrict__ uvec,
              float* __restrict__ vout,
              const float* __restrict__ wvec, int widx, int C) {
    const int rpb = 256 / LPR;
    const int r = blockIdx.x * rpb + threadIdx.x / LPR;
    const int lane = threadIdx.x % LPR;
    int n = __ldg(&cnt[r]);
    const int* list = nbr + (size_t)r * NBMAX;
    float wk = __ldg(&wvec[widx]);

    float4 a0 = make_float4(0.f, 0.f, 0.f, 0.f);
    float4 a1 = make_float4(0.f, 0.f, 0.f, 0.f);
    float4 a2 = make_float4(0.f, 0.f, 0.f, 0.f);
    float4 a3 = make_float4(0.f, 0.f, 0.f, 0.f);

    int j = 0;
    for (; j + 4 <= n; j += 4) {
        int v0 = __ldg(list + j + 0), v1 = __ldg(list + j + 1);
        int v2 = __ldg(list + j + 2), v3 = __ldg(list + j + 3);
        float4 x0 = __ldg(reinterpret_cast<const float4*>(vin + (size_t)v0 * C) + lane);
        float4 x1 = __ldg(reinterpret_cast<const float4*>(vin + (size_t)v1 * C) + lane);
        float4 x2 = __ldg(reinterpret_cast<const float4*>(vin + (size_t)v2 * C) + lane);
        float4 x3 = __ldg(reinterpret_cast<const float4*>(vin + (size_t)v3 * C) + lane);
        a0.x += x0.x; a0.y += x0.y; a0.z += x0.z; a0.w += x0.w;
        a1.x += x1.x; a1.y += x1.y; a1.z += x1.z; a1.w += x1.w;
        a2.x += x2.x; a2.y += x2.y; a2.z += x2.z; a2.w += x2.w;
        a3.x += x3.x; a3.y += x3.y; a3.z += x3.z; a3.w += x3.w;
    }
    for (; j < n; ++j) {
        int v = __ldg(list + j);
        float4 x = __ldg(reinterpret_cast<const float4*>(vin + (size_t)v * C) + lane);
        a0.x += x.x; a0.y += x.y; a0.z += x.z; a0.w += x.w;
    }
    float4 s;
    s.x = (a0.x + a1.x) + (a2.x + a3.x);
    s.y = (a0.y + a1.y) + (a2.y + a3.y);
    s.z = (a0.z + a1.z) + (a2.z + a3.z);
    s.w = (a0.w + a1.w) + (a2.w + a3.w);

    float4 uu = *(reinterpret_cast<const float4*>(uvec + (size_t)r * C) + lane);
    float4 o;
    o.x = uu.x + wk * s.x;
    o.y = uu.y + wk * s.y;
    o.z = uu.z + wk * s.z;
    o.w = uu.w + wk * s.w;
    *(reinterpret_cast<float4*>(vout + (size_t)r * C) + lane) = o;
}

__global__ void k_scale_z(const float* __restrict__ v, const float* __restrict__ d,
                          const float* __restrict__ wvec, float* __restrict__ z, int C) {
    int i = blockIdx.x * blockDim.x + threadIdx.x;
    if (i < NN * C) z[i] = wvec[0] * d[i / C] * v[i];
}

__global__ void k_final(const float* __restrict__ v, const float* __restrict__ d,
                        const float* __restrict__ wvec, const float* __restrict__ bias,
                        float* __restrict__ out, int C) {
    int i = blockIdx.x * blockDim.x + threadIdx.x;
    if (i < NN * C) {
        float val = wvec[0] * d[i / C] * v[i] + bias[i % C];
        out[i] = fmaxf(val, 0.0f);
    }
}

__global__ void k_reduce_sk(const float* __restrict__ p, float* __restrict__ out, int n) {
    int i = blockIdx.x * blockDim.x + threadIdx.x;
    if (i < n) {
        float s = 0.f;
        #pragma unroll
        for (int k = 0; k < SK3; ++k) s += p[(size_t)k * n + i];
        out[i] = s;
    }
}

// fp32 -> (hi, lo) fp16
__global__ void k_split_h(const float* __restrict__ s, __half* __restrict__ hi,
                          __half* __restrict__ lo, int n) {
    int i = blockIdx.x * blockDim.x + threadIdx.x;
    if (i < n) {
        float x = s[i];
        __half h = __float2half_rn(x);
        hi[i] = h;
        lo[i] = __float2half_rn(x - __half2float(h));
    }
}

// fp32 -> fp16
__global__ void k_tohalf(const float* __restrict__ s, __half* __restrict__ h, int n) {
    int i = blockIdx.x * blockDim.x + threadIdx.x;
    if (i < n) h[i] = __float2half_rn(s[i]);
}

// ---------------- cp.async helpers ----------------
__device__ __forceinline__ void cpasync16(void* s, const void* g, bool p) {
    unsigned sa = (unsigned)__cvta_generic_to_shared(s);
    asm volatile("cp.async.cg.shared.global [%0], [%1], 16, %2;"
                 :: "r"(sa), "l"(g), "r"(p ? 16 : 0));
}
__device__ __forceinline__ void cp_commit() { asm volatile("cp.async.commit_group;" ::: "memory"); }
__device__ __forceinline__ void cp_wait0()  { asm volatile("cp.async.wait_group 0;" ::: "memory"); }
__device__ __forceinline__ void cp_wait1()  { asm volatile("cp.async.wait_group 1;" ::: "memory"); }

// ---------------- fp16 2-term tensor-core GEMM ----------------
// D = (Ahi + Alo) * Bh  (A split fp16, B single fp16; fp32 accumulate)
#define TBM 128
#define TBN 128
#define TBK 32
#define ASTR 40
#define BSTR 136
#define ABUF (TBM * ASTR)
#define BBUF (TBK * BSTR)
#define SMEM_ELEMS (4 * ABUF + 2 * BBUF)
#define SMEM_BYTES (SMEM_ELEMS * 2)

__device__ __forceinline__ unsigned sptr(const void* p) {
    return (unsigned)__cvta_generic_to_shared(p);
}
__device__ __forceinline__ void ldsm4(unsigned& r0, unsigned& r1, unsigned& r2, unsigned& r3, unsigned a) {
    asm volatile("ldmatrix.sync.aligned.m8n8.x4.shared.b16 {%0,%1,%2,%3}, [%4];"
                 : "=r"(r0), "=r"(r1), "=r"(r2), "=r"(r3) : "r"(a));
}
__device__ __forceinline__ void ldsm4t(unsigned& r0, unsigned& r1, unsigned& r2, unsigned& r3, unsigned a) {
    asm volatile("ldmatrix.sync.aligned.m8n8.x4.trans.shared.b16 {%0,%1,%2,%3}, [%4];"
                 : "=r"(r0), "=r"(r1), "=r"(r2), "=r"(r3) : "r"(a));
}
__device__ __forceinline__ void mma16816h(float* c, const unsigned* a, unsigned b0, unsigned b1) {
    asm volatile("mma.sync.aligned.m16n8k16.row.col.f32.f16.f16.f32 "
                 "{%0,%1,%2,%3},{%4,%5,%6,%7},{%8,%9},{%0,%1,%2,%3};"
                 : "+f"(c[0]), "+f"(c[1]), "+f"(c[2]), "+f"(c[3])
                 : "r"(a[0]), "r"(a[1]), "r"(a[2]), "r"(a[3]), "r"(b0), "r"(b1));
}

// EPI=1: +bias, relu, write split fp16 (Chi/Clo, ld=Nd).  EPI=0: fp32 out Cf (ldc), col<Nd guard.
template<int EPI>
__global__ __launch_bounds__(256, 1)
void k_gemm_h(const __half* __restrict__ Ahi, const __half* __restrict__ Alo, int lda,
              const __half* __restrict__ Bh, int ldb,
              const float* __restrict__ bias,
              float* __restrict__ Cf, __half* __restrict__ Chi, __half* __restrict__ Clo,
              int ldc, int Nd, int K) {
    extern __shared__ __half smh[];
    __half* sAh = smh;
    __half* sAl = sAh + 2 * ABUF;
    __half* sBh = sAl + 2 * ABUF;

    const int tid = threadIdx.x;
    const int wid = tid >> 5, lane = tid & 31;
    const int wm = (wid & 1) * 64;
    const int wn = (wid >> 1) * 32;
    const int m0 = blockIdx.y * TBM, n0 = blockIdx.x * TBN;

    const int a_r = tid >> 2;
    const int a_c = (tid & 3) << 3;
    const int b_r = tid >> 4;
    const int b_c = (tid & 15) << 3;
    const bool pb = (n0 + b_c) < Nd;

    const __half* gAh0 = Ahi + (size_t)(m0 + a_r) * lda + a_c;
    const __half* gAh1 = Ahi + (size_t)(m0 + a_r + 64) * lda + a_c;
    const __half* gAl0 = Alo + (size_t)(m0 + a_r) * lda + a_c;
    const __half* gAl1 = Alo + (size_t)(m0 + a_r + 64) * lda + a_c;
    const __half* gB0  = Bh + (size_t)b_r * ldb + n0 + b_c;
    const __half* gB1  = Bh + (size_t)(b_r + 16) * ldb + n0 + b_c;

    float acc[4][4][4];
    #pragma unroll
    for (int i = 0; i < 4; ++i)
        #pragma unroll
        for (int j = 0; j < 4; ++j)
            #pragma unroll
            for (int q = 0; q < 4; ++q) acc[i][j][q] = 0.f;

    const int KT = K / TBK;

    cpasync16(sAh + a_r * ASTR + a_c, gAh0, true);
    cpasync16(sAh + (a_r + 64) * ASTR + a_c, gAh1, true);
    cpasync16(sAl + a_r * ASTR + a_c, gAl0, true);
    cpasync16(sAl + (a_r + 64) * ASTR + a_c, gAl1, true);
    cpasync16(sBh + b_r * BSTR + b_c, gB0, pb);
    cpasync16(sBh + (b_r + 16) * BSTR + b_c, gB1, pb);
    cp_commit();

    const int l16 = lane & 15;
    const int hsel = (lane >> 4) << 3;
    const int bg = lane >> 3, bl8 = lane & 7;
    const int bkoff = ((bg & 1) << 3) + bl8;
    const int bnoff = wn + ((bg >> 1) << 3);

    int buf = 0;
    for (int kt = 0; kt < KT; ++kt) {
        if (kt + 1 < KT) {
            int ko = (kt + 1) * TBK;
            int ob = (buf ^ 1);
            cpasync16(sAh + ob * ABUF + a_r * ASTR + a_c, gAh0 + ko, true);
            cpasync16(sAh + ob * ABUF + (a_r + 64) * ASTR + a_c, gAh1 + ko, true);
            cpasync16(sAl + ob * ABUF + a_r * ASTR + a_c, gAl0 + ko, true);
            cpasync16(sAl + ob * ABUF + (a_r + 64) * ASTR + a_c, gAl1 + ko, true);
            cpasync16(sBh + ob * BBUF + b_r * BSTR + b_c, gB0 + (size_t)ko * ldb, pb);
            cpasync16(sBh + ob * BBUF + (b_r + 16) * BSTR + b_c, gB1 + (size_t)ko * ldb, pb);
            cp_commit();
            cp_wait1();
        } else {
            cp_wait0();
        }
        __syncthreads();

        #pragma unroll
        for (int ks = 0; ks < 2; ++ks) {
            const int ko = ks * 16;
            unsigned bh[8];
            {
                unsigned ab = sptr(sBh + buf * BBUF + (ko + bkoff) * BSTR + bnoff);
                ldsm4t(bh[0], bh[1], bh[2], bh[3], ab);
                ldsm4t(bh[4], bh[5], bh[6], bh[7], ab + 32);
            }
            #pragma unroll
            for (int mi = 0; mi < 4; ++mi) {
                unsigned ah[4], alr[4];
                unsigned aa = sptr(sAh + buf * ABUF + (wm + mi * 16 + l16) * ASTR + ko + hsel);
                ldsm4(ah[0], ah[1], ah[2], ah[3], aa);
                unsigned aal = sptr(sAl + buf * ABUF + (wm + mi * 16 + l16) * ASTR + ko + hsel);
                ldsm4(alr[0], alr[1], alr[2], alr[3], aal);
                #pragma unroll
                for (int nj = 0; nj < 4; ++nj) {
                    int bi = (nj >> 1) * 4 + (nj & 1) * 2;
                    mma16816h(acc[mi][nj], ah, bh[bi], bh[bi + 1]);
                    mma16816h(acc[mi][nj], alr, bh[bi], bh[bi + 1]);
                }
            }
        }
        __syncthreads();
        buf ^= 1;
    }

    const int er = lane >> 2;
    const int ec = (lane & 3) << 1;
    #pragma unroll
    for (int mi = 0; mi < 4; ++mi) {
        #pragma unroll
        for (int nj = 0; nj < 4; ++nj) {
            int row = m0 + wm + mi * 16 + er;
            int col = n0 + wn + nj * 8 + ec;
            float* a = acc[mi][nj];
            if (EPI) {
                float bv0 = bias[col], bv1 = bias[col + 1];
                #pragma unroll
                for (int h = 0; h < 2; ++h) {
                    int r = row + h * 8;
                    float v0 = fmaxf(a[h * 2 + 0] + bv0, 0.f);
                    float v1 = fmaxf(a[h * 2 + 1] + bv1, 0.f);
                    __half h0 = __float2half_rn(v0);
                    __half h1 = __float2half_rn(v1);
                    __half2 hp; hp.x = h0; hp.y = h1;
                    __half2 lp;
                    lp.x = __float2half_rn(v0 - __half2float(h0));
                    lp.y = __float2half_rn(v1 - __half2float(h1));
                    *reinterpret_cast<__half2*>(&Chi[(size_t)r * Nd + col]) = hp;
                    *reinterpret_cast<__half2*>(&Clo[(size_t)r * Nd + col]) = lp;
                }
            } else {
                if (col < Nd) {
                    *reinterpret_cast<float2*>(&Cf[(size_t)row * ldc + col]) = make_float2(a[0], a[1]);
                    *reinterpret_cast<float2*>(&Cf[(size_t)(row + 8) * ldc + col]) = make_float2(a[2], a[3]);
                }
            }
        }
    }
}

// ---------------- fp32 GEMM (tiny GEMM3, split-K) ----------------
#define BM 128
#define BK 16

template<int BN_, int TN_>
__global__ __launch_bounds__(256)
void k_gemm(const float* __restrict__ A, int lda,
            const float* __restrict__ B, int ldb,
            float* __restrict__ Cout, int ldc,
            int Nd, int Kloop, int partStride) {
    __shared__ float As[2][BM][BK];
    __shared__ float Bs[2][BK][BN_];

    const int tid = threadIdx.x;
    const int tx = tid & 15;
    const int ty = tid >> 4;
    const int m0 = blockIdx.y * BM;
    const int n0 = blockIdx.x * BN_;

    A += (size_t)blockIdx.z * Kloop;
    B += (size_t)blockIdx.z * Kloop * ldb;
    Cout += (size_t)blockIdx.z * partStride;

    const int arow0 = tid >> 2;
    const int arow1 = arow0 + 64;
    const int ac4 = (tid & 3) * 4;
    const float* gA0 = A + (size_t)(m0 + arow0) * lda + ac4;
    const float* gA1 = A + (size_t)(m0 + arow1) * lda + ac4;

    const int BQ = BN_ / 4;
    const int bkr0 = tid / BQ;
    const int bc0 = (tid % BQ) * 4;
    const float* gB0 = B + (size_t)bkr0 * ldb + n0 + bc0;
    const bool bp0 = (n0 + bc0) < Nd;

    float acc[8][TN_];
    #pragma unroll
    for (int i = 0; i < 8; ++i)
        #pragma unroll
        for (int j = 0; j < TN_; ++j) acc[i][j] = 0.f;

    const int KT = Kloop / BK;

    cpasync16(&As[0][arow0][ac4], gA0, true);
    cpasync16(&As[0][arow1][ac4], gA1, true);
    cpasync16(&Bs[0][bkr0][bc0], gB0, bp0);
    cp_commit();

    int buf = 0;
    for (int kt = 0; kt < KT; ++kt) {
        if (kt + 1 < KT) {
            int ko = (kt + 1) * BK;
            cpasync16(&As[buf ^ 1][arow0][ac4], gA0 + ko, true);
            cpasync16(&As[buf ^ 1][arow1][ac4], gA1 + ko, true);
            cpasync16(&Bs[buf ^ 1][bkr0][bc0], gB0 + (size_t)ko * ldb, bp0);
            cp_commit();
            cp_wait1();
        } else {
            cp_wait0();
        }
        __syncthreads();

        #pragma unroll
        for (int k = 0; k < BK; ++k) {
            float a[8];
            #pragma unroll
            for (int i = 0; i < 8; ++i) a[i] = As[buf][ty * 8 + i][k];
            float b[TN_];
            #pragma unroll
            for (int j = 0; j < TN_; j += 4) {
                float4 v = *reinterpret_cast<const float4*>(&Bs[buf][k][tx * TN_ + j]);
                b[j] = v.x; b[j + 1] = v.y; b[j + 2] = v.z; b[j + 3] = v.w;
            }
            #pragma unroll
            for (int i = 0; i < 8; ++i)
                #pragma unroll
                for (int j = 0; j < TN_; ++j)
                    acc[i][j] += a[i] * b[j];
        }
        __syncthreads();
        buf ^= 1;
    }

    #pragma unroll
    for (int i = 0; i < 8; ++i) {
        int m = m0 + ty * 8 + i;
        #pragma unroll
        for (int j = 0; j < TN_; j += 4) {
            int n = n0 + tx * TN_ + j;
            if (n < Nd) {
                float4 v = make_float4(acc[i][j], acc[i][j + 1], acc[i][j + 2], acc[i][j + 3]);
                *reinterpret_cast<float4*>(&Cout[(size_t)m * ldc + n]) = v;
            }
        }
    }
}

// ---------------- host orchestration ----------------
static float* run_prop(const int* nbr, const int* cnt, const float* dvec,
                       const float* feat, const float* w, int C,
                       float* u, float* va, float* vb) {
    int total = NN * C;
    k_scale_u<<<(total + 255) / 256, 256>>>(feat, dvec, u, va, C);
    float* vin = va;
    float* vout = vb;
    for (int k = 5; k >= 1; --k) {
        if (C == H2D)       k_spmm<2><<<NN, 256>>>(nbr, cnt, vin, u, vout, w, k, C);
        else if (C == C_IN) k_spmm_s<32><<<NN / 8, 256>>>(nbr, cnt, vin, u, vout, w, k, C);
        else                k_spmm_s<8><<<NN / 32, 256>>>(nbr, cnt, vin, u, vout, w, k, C);
        float* t = vin; vin = vout; vout = t;
    }
    return vin;
}

extern "C" void kernel_launch(void* const* d_in, const int* in_sizes, int n_in,
                              void* d_out, int out_size) {
    const float* x  = (const float*)d_in[0];
    const int*   ei = (const int*)  d_in[1];
    const float* w1 = (const float*)d_in[2];
    const float* w2 = (const float*)d_in[3];
    const float* w3 = (const float*)d_in[4];
    const float* W1 = (const float*)d_in[5];
    const float* b1 = (const float*)d_in[6];
    const float* W2 = (const float*)d_in[7];
    const float* b2 = (const float*)d_in[8];
    const float* W3 = (const float*)d_in[9];
    const float* b3 = (const float*)d_in[10];
    float* out = (float*)d_out;

    unsigned *adj, *rA, *rB;
    int *nbr, *cnt;
    float *dvec, *u, *va, *vb, *z, *gg, *h2, *g3, *g3p;
    __half *zhi, *zlo, *w1h, *w2h, *h1hi, *h1lo;
    cudaGetSymbolAddress((void**)&adj,  g_adj);
    cudaGetSymbolAddress((void**)&rA,   g_rA);
    cudaGetSymbolAddress((void**)&rB,   g_rB);
    cudaGetSymbolAddress((void**)&nbr,  g_nbr);
    cudaGetSymbolAddress((void**)&cnt,  g_cnt);
    cudaGetSymbolAddress((void**)&dvec, g_dvec);
    cudaGetSymbolAddress((void**)&u,    g_u);
    cudaGetSymbolAddress((void**)&va,   g_va);
    cudaGetSymbolAddress((void**)&vb,   g_vb);
    cudaGetSymbolAddress((void**)&z,    g_z);
    cudaGetSymbolAddress((void**)&gg,   g_gg);
    cudaGetSymbolAddress((void**)&h2,   g_h2);
    cudaGetSymbolAddress((void**)&g3,   g_g3);
    cudaGetSymbolAddress((void**)&g3p,  g_g3p);
    cudaGetSymbolAddress((void**)&zhi,  g_zhi);
    cudaGetSymbolAddress((void**)&zlo,  g_zlo);
    cudaGetSymbolAddress((void**)&w1h,  g_w1h);
    cudaGetSymbolAddress((void**)&w2h,  g_w2h);
    cudaGetSymbolAddress((void**)&h1hi, g_h1hi);
    cudaGetSymbolAddress((void**)&h1lo, g_h1lo);

    cudaFuncSetAttribute(k_gemm_h<0>, cudaFuncAttributeMaxDynamicSharedMemorySize, SMEM_BYTES);
    cudaFuncSetAttribute(k_gemm_h<1>, cudaFuncAttributeMaxDynamicSharedMemorySize, SMEM_BYTES);

    // ---- adjacency + neighbor lists + reach + deg ----
    k_zero_u32<<<(NN * WORDS + 255) / 256, 256>>>(adj, NN * WORDS);
    k_build_adj<<<EE / 256, 256>>>(ei, adj);
    k_build_list<<<NN / 256, 256>>>(adj, nbr, cnt);
    k_reach_init<<<(NN * WORDS + 255) / 256, 256>>>(adj, rA);
    k_reach_iter<<<NN, 64>>>(nbr, cnt, rA, rB);
    k_reach_iter<<<NN, 64>>>(nbr, cnt, rB, rA);
    k_reach_iter<<<NN, 64>>>(nbr, cnt, rA, rB);
    k_reach_iter<<<NN, 64>>>(nbr, cnt, rB, rA);
    k_deg<<<(NN + 255) / 256, 256>>>(rA, dvec);

    // weight conversions (independent; issue early)
    k_tohalf<<<(C_IN * H1D + 255) / 256, 256>>>(W1, w1h, C_IN * H1D);
    k_tohalf<<<(H1D * H2D + 255) / 256, 256>>>(W2, w2h, H1D * H2D);

    // ---- layer 1: h1 = relu((M1_hat x) W1 + b1), split-fp16 output ----
    {
        float* v = run_prop(nbr, cnt, dvec, x, w1, C_IN, u, va, vb);
        k_scale_z<<<(NN * C_IN + 255) / 256, 256>>>(v, dvec, w1, z, C_IN);
        k_split_h<<<(NN * C_IN + 255) / 256, 256>>>(z, zhi, zlo, NN * C_IN);
        dim3 grid(H1D / TBN, NN / TBM, 1);
        k_gemm_h<1><<<grid, 256, SMEM_BYTES>>>(zhi, zlo, C_IN, w1h, H1D,
                                               b1, (float*)0, h1hi, h1lo, H1D, H1D, C_IN);
    }

    // ---- layer 2: h2 = relu(M2_hat (h1 W2) + b2) ----
    {
        dim3 grid((H2D + TBN - 1) / TBN, NN / TBM, 1);
        k_gemm_h<0><<<grid, 256, SMEM_BYTES>>>(h1hi, h1lo, H1D, w2h, H2D,
                                               (const float*)0, gg, (__half*)0, (__half*)0,
                                               H2D, H2D, H1D);
        float* v = run_prop(nbr, cnt, dvec, gg, w2, H2D, u, va, vb);
        k_final<<<(NN * H2D + 255) / 256, 256>>>(v, dvec, w2, b2, h2, H2D);
    }

    // ---- layer 3: out = relu(M3_hat (h2 W3) + b3), fp32 split-K GEMM ----
    {
        dim3 grid(1, NN / BM, SK3);
        k_gemm<64, 4><<<grid, 256>>>(h2, H2D, W3, ODIM, g3p, ODIM, ODIM, H2D / SK3, NN * ODIM);
        k_reduce_sk<<<(NN * ODIM + 255) / 256, 256>>>(g3p, g3, NN * ODIM);
        float* v = run_prop(nbr, cnt, dvec, g3, w3, ODIM, u, va, vb);
        k_final<<<(NN * ODIM + 255) / 256, 256>>>(v, dvec, w3, b3, out, ODIM);
    }
}

// round 7
// speedup vs baseline: 2.4566x; 1.1019x over previous
#include <cuda_runtime.h>
#include <cuda_fp16.h>

#define NN 2048
#define EE 65536
#define WORDS 64
#define NBMAX 2048
#define C_IN 128
#define H1D 3200
#define H2D 1600
#define ODIM 32
#define SK3 4

// ---------------- scratch (device globals) ----------------
__device__ unsigned g_adj[NN * WORDS];
__device__ unsigned g_rA [NN * WORDS];
__device__ unsigned g_rB [NN * WORDS];
__device__ int      g_nbr[(size_t)NN * NBMAX];
__device__ int      g_cnt[NN];
__device__ float    g_dvec[NN];
__device__ float    g_u  [NN * H2D];
__device__ float    g_va [NN * H2D];
__device__ float    g_vb [NN * H2D];
__device__ float    g_gg [NN * H2D];
__device__ float    g_h2 [NN * H2D];
__device__ float    g_g3 [NN * ODIM];
__device__ float    g_g3p[SK3 * NN * ODIM];
// fp16 operands / iterates
__device__ __half g_vha[NN * H2D], g_vhb[NN * H2D];
__device__ __half g_zhi[NN * C_IN],  g_zlo[NN * C_IN];
__device__ __half g_w1h[C_IN * H1D];
__device__ __half g_w2h[H1D * H2D];
__device__ __half g_h1hi[(size_t)NN * H1D], g_h1lo[(size_t)NN * H1D];

// ---------------- utility kernels ----------------
__global__ void k_zero_u32(unsigned* p, int n) {
    int i = blockIdx.x * blockDim.x + threadIdx.x;
    if (i < n) p[i] = 0u;
}

__global__ void k_build_adj(const int* __restrict__ ei, unsigned* __restrict__ adj) {
    int e = blockIdx.x * blockDim.x + threadIdx.x;
    if (e < EE) {
        int src = ei[e];
        int dst = ei[EE + e];
        atomicOr(&adj[dst * WORDS + (src >> 5)], 1u << (src & 31));
    }
}

__global__ void k_build_list(const unsigned* __restrict__ adj,
                             int* __restrict__ nbr, int* __restrict__ cnt) {
    int u = blockIdx.x * blockDim.x + threadIdx.x;
    if (u >= NN) return;
    int c = 0;
    int* out = nbr + (size_t)u * NBMAX;
    for (int w = 0; w < WORDS; ++w) {
        unsigned bits = adj[u * WORDS + w];
        while (bits) {
            int b = __ffs(bits) - 1;
            bits &= bits - 1;
            if (c < NBMAX) out[c] = w * 32 + b;
            ++c;
        }
    }
    cnt[u] = (c < NBMAX) ? c : NBMAX;
}

__global__ void k_reach_init(const unsigned* __restrict__ adj, unsigned* __restrict__ R) {
    int i = blockIdx.x * blockDim.x + threadIdx.x;
    if (i < NN * WORDS) {
        int u = i >> 6, w = i & 63;
        unsigned v = adj[i];
        if ((u >> 5) == w) v |= 1u << (u & 31);
        R[i] = v;
    }
}

__global__ void k_reach_iter(const int* __restrict__ nbr, const int* __restrict__ cnt,
                             const unsigned* __restrict__ Rold, unsigned* __restrict__ Rnew) {
    int u = blockIdx.x;
    int w = threadIdx.x;
    int n = __ldg(&cnt[u]);
    const int* list = nbr + (size_t)u * NBMAX;
    unsigned acc = ((u >> 5) == w) ? (1u << (u & 31)) : 0u;
    int j = 0;
    for (; j + 4 <= n; j += 4) {
        int v0 = __ldg(list + j + 0), v1 = __ldg(list + j + 1);
        int v2 = __ldg(list + j + 2), v3 = __ldg(list + j + 3);
        unsigned r0 = Rold[v0 * WORDS + w];
        unsigned r1 = Rold[v1 * WORDS + w];
        unsigned r2 = Rold[v2 * WORDS + w];
        unsigned r3 = Rold[v3 * WORDS + w];
        acc |= (r0 | r1) | (r2 | r3);
    }
    for (; j < n; ++j) acc |= Rold[__ldg(list + j) * WORDS + w];
    Rnew[u * WORDS + w] = acc;
}

__global__ void k_deg(const unsigned* __restrict__ R, float* __restrict__ d) {
    int u = blockIdx.x * blockDim.x + threadIdx.x;
    if (u < NN) {
        int c = 0;
        #pragma unroll 8
        for (int w = 0; w < WORDS; ++w) c += __popc(R[u * WORDS + w]);
        d[u] = (c > 0) ? rsqrtf((float)c) : 0.0f;
    }
}

__global__ void k_scale_u(const float* __restrict__ feat, const float* __restrict__ d,
                          float* __restrict__ u, float* __restrict__ v, int C) {
    int i = blockIdx.x * blockDim.x + threadIdx.x;
    if (i < NN * C) {
        float val = d[i / C] * feat[i];
        u[i] = val;
        v[i] = val;
    }
}

// u fp32 + seed fp16 (layer-2)
__global__ void k_scale_u_h(const float* __restrict__ feat, const float* __restrict__ d,
                            float* __restrict__ u, __half* __restrict__ v, int C) {
    int i = blockIdx.x * blockDim.x + threadIdx.x;
    if (i < NN * C) {
        float val = d[i / C] * feat[i];
        u[i] = val;
        v[i] = __float2half_rn(val);
    }
}

// ---- SpMM large C, fp32 gather (hops 2,1) ----
template <int NV>
__global__ __launch_bounds__(256)
void k_spmm(const int* __restrict__ nbr, const int* __restrict__ cnt,
            const float* __restrict__ vin, const float* __restrict__ uvec,
            float* __restrict__ vout,
            const float* __restrict__ wvec, int widx, int C) {
    int u = blockIdx.x;
    int t = threadIdx.x;
    int n = __ldg(&cnt[u]);
    const int* list = nbr + (size_t)u * NBMAX;
    const int C4 = C >> 2;
    float wk = __ldg(&wvec[widx]);

    float4 acc[NV];
    #pragma unroll
    for (int q = 0; q < NV; ++q) acc[q] = make_float4(0.f, 0.f, 0.f, 0.f);

    int j = 0;
    for (; j + 4 <= n; j += 4) {
        int v0 = __ldg(list + j + 0), v1 = __ldg(list + j + 1);
        int v2 = __ldg(list + j + 2), v3 = __ldg(list + j + 3);
        const float4* r0 = reinterpret_cast<const float4*>(vin + (size_t)v0 * C);
        const float4* r1 = reinterpret_cast<const float4*>(vin + (size_t)v1 * C);
        const float4* r2 = reinterpret_cast<const float4*>(vin + (size_t)v2 * C);
        const float4* r3 = reinterpret_cast<const float4*>(vin + (size_t)v3 * C);
        #pragma unroll
        for (int q = 0; q < NV; ++q) {
            int idx = t + q * 256;
            if (idx < C4) {
                float4 x0 = __ldg(r0 + idx);
                float4 x1 = __ldg(r1 + idx);
                float4 x2 = __ldg(r2 + idx);
                float4 x3 = __ldg(r3 + idx);
                acc[q].x += (x0.x + x1.x) + (x2.x + x3.x);
                acc[q].y += (x0.y + x1.y) + (x2.y + x3.y);
                acc[q].z += (x0.z + x1.z) + (x2.z + x3.z);
                acc[q].w += (x0.w + x1.w) + (x2.w + x3.w);
            }
        }
    }
    for (; j < n; ++j) {
        int v = __ldg(list + j);
        const float4* r = reinterpret_cast<const float4*>(vin + (size_t)v * C);
        #pragma unroll
        for (int q = 0; q < NV; ++q) {
            int idx = t + q * 256;
            if (idx < C4) {
                float4 x = __ldg(r + idx);
                acc[q].x += x.x; acc[q].y += x.y; acc[q].z += x.z; acc[q].w += x.w;
            }
        }
    }
    const float4* urow = reinterpret_cast<const float4*>(uvec + (size_t)u * C);
    float4* orow = reinterpret_cast<float4*>(vout + (size_t)u * C);
    #pragma unroll
    for (int q = 0; q < NV; ++q) {
        int idx = t + q * 256;
        if (idx < C4) {
            float4 uu = urow[idx];
            float4 o;
            o.x = uu.x + wk * acc[q].x;
            o.y = uu.y + wk * acc[q].y;
            o.z = uu.z + wk * acc[q].z;
            o.w = uu.w + wk * acc[q].w;
            orow[idx] = o;
        }
    }
}

// ---- SpMM large C, fp16 gather (hops 5,4,3). OUT16: write fp16 iterate. ----
// Thread t handles 8 channels (one uint4 of halves); C/8 <= 256.
template <int OUT16>
__global__ __launch_bounds__(256)
void k_spmm_h(const int* __restrict__ nbr, const int* __restrict__ cnt,
              const __half* __restrict__ vin, const float* __restrict__ uvec,
              __half* __restrict__ vout16, float* __restrict__ vout32,
              const float* __restrict__ wvec, int widx, int C) {
    int u = blockIdx.x;
    int t = threadIdx.x;
    const int L = C >> 3;
    if (t >= L) return;
    int n = __ldg(&cnt[u]);
    const int* list = nbr + (size_t)u * NBMAX;
    float wk = __ldg(&wvec[widx]);

    float acc[8];
    #pragma unroll
    for (int q = 0; q < 8; ++q) acc[q] = 0.f;

    int j = 0;
    for (; j + 4 <= n; j += 4) {
        int v0 = __ldg(list + j + 0), v1 = __ldg(list + j + 1);
        int v2 = __ldg(list + j + 2), v3 = __ldg(list + j + 3);
        uint4 x0 = __ldg(reinterpret_cast<const uint4*>(vin + (size_t)v0 * C) + t);
        uint4 x1 = __ldg(reinterpret_cast<const uint4*>(vin + (size_t)v1 * C) + t);
        uint4 x2 = __ldg(reinterpret_cast<const uint4*>(vin + (size_t)v2 * C) + t);
        uint4 x3 = __ldg(reinterpret_cast<const uint4*>(vin + (size_t)v3 * C) + t);
        const __half2* h0 = reinterpret_cast<const __half2*>(&x0);
        const __half2* h1 = reinterpret_cast<const __half2*>(&x1);
        const __half2* h2 = reinterpret_cast<const __half2*>(&x2);
        const __half2* h3 = reinterpret_cast<const __half2*>(&x3);
        #pragma unroll
        for (int q = 0; q < 4; ++q) {
            float2 f0 = __half22float2(h0[q]);
            float2 f1 = __half22float2(h1[q]);
            float2 f2 = __half22float2(h2[q]);
            float2 f3 = __half22float2(h3[q]);
            acc[2 * q + 0] += (f0.x + f1.x) + (f2.x + f3.x);
            acc[2 * q + 1] += (f0.y + f1.y) + (f2.y + f3.y);
        }
    }
    for (; j < n; ++j) {
        int v = __ldg(list + j);
        uint4 x = __ldg(reinterpret_cast<const uint4*>(vin + (size_t)v * C) + t);
        const __half2* h = reinterpret_cast<const __half2*>(&x);
        #pragma unroll
        for (int q = 0; q < 4; ++q) {
            float2 f = __half22float2(h[q]);
            acc[2 * q + 0] += f.x;
            acc[2 * q + 1] += f.y;
        }
    }

    size_t base = (size_t)u * C + t * 8;
    float4 u0 = *reinterpret_cast<const float4*>(uvec + base);
    float4 u1 = *reinterpret_cast<const float4*>(uvec + base + 4);
    float o[8];
    o[0] = u0.x + wk * acc[0]; o[1] = u0.y + wk * acc[1];
    o[2] = u0.z + wk * acc[2]; o[3] = u0.w + wk * acc[3];
    o[4] = u1.x + wk * acc[4]; o[5] = u1.y + wk * acc[5];
    o[6] = u1.z + wk * acc[6]; o[7] = u1.w + wk * acc[7];
    if (OUT16) {
        __half2 hp[4];
        #pragma unroll
        for (int q = 0; q < 4; ++q)
            hp[q] = __floats2half2_rn(o[2 * q], o[2 * q + 1]);
        *(reinterpret_cast<uint4*>(vout16 + base)) = *reinterpret_cast<uint4*>(hp);
    } else {
        *reinterpret_cast<float4*>(vout32 + base) = make_float4(o[0], o[1], o[2], o[3]);
        *reinterpret_cast<float4*>(vout32 + base + 4) = make_float4(o[4], o[5], o[6], o[7]);
    }
}

// ---- SpMM small C: LPR float4-lanes per row ----
template <int LPR>
__global__ __launch_bounds__(256)
void k_spmm_s(const int* __restrict__ nbr, const int* __restrict__ cnt,
              const float* __restrict__ vin, const float* __restrict__ uvec,
              float* __restrict__ vout,
              const float* __restrict__ wvec, int widx, int C) {
    const int rpb = 256 / LPR;
    const int r = blockIdx.x * rpb + threadIdx.x / LPR;
    const int lane = threadIdx.x % LPR;
    int n = __ldg(&cnt[r]);
    const int* list = nbr + (size_t)r * NBMAX;
    float wk = __ldg(&wvec[widx]);

    float4 a0 = make_float4(0.f, 0.f, 0.f, 0.f);
    float4 a1 = make_float4(0.f, 0.f, 0.f, 0.f);
    float4 a2 = make_float4(0.f, 0.f, 0.f, 0.f);
    float4 a3 = make_float4(0.f, 0.f, 0.f, 0.f);

    int j = 0;
    for (; j + 4 <= n; j += 4) {
        int v0 = __ldg(list + j + 0), v1 = __ldg(list + j + 1);
        int v2 = __ldg(list + j + 2), v3 = __ldg(list + j + 3);
        float4 x0 = __ldg(reinterpret_cast<const float4*>(vin + (size_t)v0 * C) + lane);
        float4 x1 = __ldg(reinterpret_cast<const float4*>(vin + (size_t)v1 * C) + lane);
        float4 x2 = __ldg(reinterpret_cast<const float4*>(vin + (size_t)v2 * C) + lane);
        float4 x3 = __ldg(reinterpret_cast<const float4*>(vin + (size_t)v3 * C) + lane);
        a0.x += x0.x; a0.y += x0.y; a0.z += x0.z; a0.w += x0.w;
        a1.x += x1.x; a1.y += x1.y; a1.z += x1.z; a1.w += x1.w;
        a2.x += x2.x; a2.y += x2.y; a2.z += x2.z; a2.w += x2.w;
        a3.x += x3.x; a3.y += x3.y; a3.z += x3.z; a3.w += x3.w;
    }
    for (; j < n; ++j) {
        int v = __ldg(list + j);
        float4 x = __ldg(reinterpret_cast<const float4*>(vin + (size_t)v * C) + lane);
        a0.x += x.x; a0.y += x.y; a0.z += x.z; a0.w += x.w;
    }
    float4 s;
    s.x = (a0.x + a1.x) + (a2.x + a3.x);
    s.y = (a0.y + a1.y) + (a2.y + a3.y);
    s.z = (a0.z + a1.z) + (a2.z + a3.z);
    s.w = (a0.w + a1.w) + (a2.w + a3.w);

    float4 uu = *(reinterpret_cast<const float4*>(uvec + (size_t)r * C) + lane);
    float4 o;
    o.x = uu.x + wk * s.x;
    o.y = uu.y + wk * s.y;
    o.z = uu.z + wk * s.z;
    o.w = uu.w + wk * s.w;
    *(reinterpret_cast<float4*>(vout + (size_t)r * C) + lane) = o;
}

// fused: z = w0*d*v, split to fp16 hi/lo (layer-1 pre-GEMM)
__global__ void k_scale_split(const float* __restrict__ v, const float* __restrict__ d,
                              const float* __restrict__ wvec,
                              __half* __restrict__ hi, __half* __restrict__ lo, int C) {
    int i = blockIdx.x * blockDim.x + threadIdx.x;
    if (i < NN * C) {
        float x = wvec[0] * d[i / C] * v[i];
        __half h = __float2half_rn(x);
        hi[i] = h;
        lo[i] = __float2half_rn(x - __half2float(h));
    }
}

__global__ void k_final(const float* __restrict__ v, const float* __restrict__ d,
                        const float* __restrict__ wvec, const float* __restrict__ bias,
                        float* __restrict__ out, int C) {
    int i = blockIdx.x * blockDim.x + threadIdx.x;
    if (i < NN * C) {
        float val = wvec[0] * d[i / C] * v[i] + bias[i % C];
        out[i] = fmaxf(val, 0.0f);
    }
}

__global__ void k_reduce_sk(const float* __restrict__ p, float* __restrict__ out, int n) {
    int i = blockIdx.x * blockDim.x + threadIdx.x;
    if (i < n) {
        float s = 0.f;
        #pragma unroll
        for (int k = 0; k < SK3; ++k) s += p[(size_t)k * n + i];
        out[i] = s;
    }
}

__global__ void k_tohalf(const float* __restrict__ s, __half* __restrict__ h, int n) {
    int i = blockIdx.x * blockDim.x + threadIdx.x;
    if (i < n) h[i] = __float2half_rn(s[i]);
}

// ---------------- cp.async helpers ----------------
__device__ __forceinline__ void cpasync16(void* s, const void* g, bool p) {
    unsigned sa = (unsigned)__cvta_generic_to_shared(s);
    asm volatile("cp.async.cg.shared.global [%0], [%1], 16, %2;"
                 :: "r"(sa), "l"(g), "r"(p ? 16 : 0));
}
__device__ __forceinline__ void cp_commit() { asm volatile("cp.async.commit_group;" ::: "memory"); }
__device__ __forceinline__ void cp_wait0()  { asm volatile("cp.async.wait_group 0;" ::: "memory"); }
__device__ __forceinline__ void cp_wait1()  { asm volatile("cp.async.wait_group 1;" ::: "memory"); }

// ---------------- fp16 2-term tensor-core GEMM ----------------
#define TBM 128
#define TBN 128
#define TBK 32
#define ASTR 40
#define BSTR 136
#define ABUF (TBM * ASTR)
#define BBUF (TBK * BSTR)
#define SMEM_ELEMS (4 * ABUF + 2 * BBUF)
#define SMEM_BYTES (SMEM_ELEMS * 2)

__device__ __forceinline__ unsigned sptr(const void* p) {
    return (unsigned)__cvta_generic_to_shared(p);
}
__device__ __forceinline__ void ldsm4(unsigned& r0, unsigned& r1, unsigned& r2, unsigned& r3, unsigned a) {
    asm volatile("ldmatrix.sync.aligned.m8n8.x4.shared.b16 {%0,%1,%2,%3}, [%4];"
                 : "=r"(r0), "=r"(r1), "=r"(r2), "=r"(r3) : "r"(a));
}
__device__ __forceinline__ void ldsm4t(unsigned& r0, unsigned& r1, unsigned& r2, unsigned& r3, unsigned a) {
    asm volatile("ldmatrix.sync.aligned.m8n8.x4.trans.shared.b16 {%0,%1,%2,%3}, [%4];"
                 : "=r"(r0), "=r"(r1), "=r"(r2), "=r"(r3) : "r"(a));
}
__device__ __forceinline__ void mma16816h(float* c, const unsigned* a, unsigned b0, unsigned b1) {
    asm volatile("mma.sync.aligned.m16n8k16.row.col.f32.f16.f16.f32 "
                 "{%0,%1,%2,%3},{%4,%5,%6,%7},{%8,%9},{%0,%1,%2,%3};"
                 : "+f"(c[0]), "+f"(c[1]), "+f"(c[2]), "+f"(c[3])
                 : "r"(a[0]), "r"(a[1]), "r"(a[2]), "r"(a[3]), "r"(b0), "r"(b1));
}

// EPI=1: +bias, relu, write split fp16.  EPI=0: fp32 out, col<Nd guard.
template<int EPI>
__global__ __launch_bounds__(256, 2)
void k_gemm_h(const __half* __restrict__ Ahi, const __half* __restrict__ Alo, int lda,
              const __half* __restrict__ Bh, int ldb,
              const float* __restrict__ bias,
              float* __restrict__ Cf, __half* __restrict__ Chi, __half* __restrict__ Clo,
              int ldc, int Nd, int K) {
    extern __shared__ __half smh[];
    __half* sAh = smh;
    __half* sAl = sAh + 2 * ABUF;
    __half* sBh = sAl + 2 * ABUF;

    const int tid = threadIdx.x;
    const int wid = tid >> 5, lane = tid & 31;
    const int wm = (wid & 1) * 64;
    const int wn = (wid >> 1) * 32;
    const int m0 = blockIdx.y * TBM, n0 = blockIdx.x * TBN;

    const int a_r = tid >> 2;
    const int a_c = (tid & 3) << 3;
    const int b_r = tid >> 4;
    const int b_c = (tid & 15) << 3;
    const bool pb = (n0 + b_c) < Nd;

    const __half* gAh0 = Ahi + (size_t)(m0 + a_r) * lda + a_c;
    const __half* gAh1 = Ahi + (size_t)(m0 + a_r + 64) * lda + a_c;
    const __half* gAl0 = Alo + (size_t)(m0 + a_r) * lda + a_c;
    const __half* gAl1 = Alo + (size_t)(m0 + a_r + 64) * lda + a_c;
    const __half* gB0  = Bh + (size_t)b_r * ldb + n0 + b_c;
    const __half* gB1  = Bh + (size_t)(b_r + 16) * ldb + n0 + b_c;

    float acc[4][4][4];
    #pragma unroll
    for (int i = 0; i < 4; ++i)
        #pragma unroll
        for (int j = 0; j < 4; ++j)
            #pragma unroll
            for (int q = 0; q < 4; ++q) acc[i][j][q] = 0.f;

    const int KT = K / TBK;

    cpasync16(sAh + a_r * ASTR + a_c, gAh0, true);
    cpasync16(sAh + (a_r + 64) * ASTR + a_c, gAh1, true);
    cpasync16(sAl + a_r * ASTR + a_c, gAl0, true);
    cpasync16(sAl + (a_r + 64) * ASTR + a_c, gAl1, true);
    cpasync16(sBh + b_r * BSTR + b_c, gB0, pb);
    cpasync16(sBh + (b_r + 16) * BSTR + b_c, gB1, pb);
    cp_commit();

    const int l16 = lane & 15;
    const int hsel = (lane >> 4) << 3;
    const int bg = lane >> 3, bl8 = lane & 7;
    const int bkoff = ((bg & 1) << 3) + bl8;
    const int bnoff = wn + ((bg >> 1) << 3);

    int buf = 0;
    for (int kt = 0; kt < KT; ++kt) {
        if (kt + 1 < KT) {
            int ko = (kt + 1) * TBK;
            int ob = (buf ^ 1);
            cpasync16(sAh + ob * ABUF + a_r * ASTR + a_c, gAh0 + ko, true);
            cpasync16(sAh + ob * ABUF + (a_r + 64) * ASTR + a_c, gAh1 + ko, true);
            cpasync16(sAl + ob * ABUF + a_r * ASTR + a_c, gAl0 + ko, true);
            cpasync16(sAl + ob * ABUF + (a_r + 64) * ASTR + a_c, gAl1 + ko, true);
            cpasync16(sBh + ob * BBUF + b_r * BSTR + b_c, gB0 + (size_t)ko * ldb, pb);
            cpasync16(sBh + ob * BBUF + (b_r + 16) * BSTR + b_c, gB1 + (size_t)ko * ldb, pb);
            cp_commit();
            cp_wait1();
        } else {
            cp_wait0();
        }
        __syncthreads();

        #pragma unroll
        for (int ks = 0; ks < 2; ++ks) {
            const int ko = ks * 16;
            unsigned bh[8];
            {
                unsigned ab = sptr(sBh + buf * BBUF + (ko + bkoff) * BSTR + bnoff);
                ldsm4t(bh[0], bh[1], bh[2], bh[3], ab);
                ldsm4t(bh[4], bh[5], bh[6], bh[7], ab + 32);
            }
            #pragma unroll
            for (int mi = 0; mi < 4; ++mi) {
                unsigned ah[4], alr[4];
                unsigned aa = sptr(sAh + buf * ABUF + (wm + mi * 16 + l16) * ASTR + ko + hsel);
                ldsm4(ah[0], ah[1], ah[2], ah[3], aa);
                unsigned aal = sptr(sAl + buf * ABUF + (wm + mi * 16 + l16) * ASTR + ko + hsel);
                ldsm4(alr[0], alr[1], alr[2], alr[3], aal);
                #pragma unroll
                for (int nj = 0; nj < 4; ++nj) {
                    int bi = (nj >> 1) * 4 + (nj & 1) * 2;
                    mma16816h(acc[mi][nj], ah, bh[bi], bh[bi + 1]);
                    mma16816h(acc[mi][nj], alr, bh[bi], bh[bi + 1]);
                }
            }
        }
        __syncthreads();
        buf ^= 1;
    }

    const int er = lane >> 2;
    const int ec = (lane & 3) << 1;
    #pragma unroll
    for (int mi = 0; mi < 4; ++mi) {
        #pragma unroll
        for (int nj = 0; nj < 4; ++nj) {
            int row = m0 + wm + mi * 16 + er;
            int col = n0 + wn + nj * 8 + ec;
            float* a = acc[mi][nj];
            if (EPI) {
                float bv0 = bias[col], bv1 = bias[col + 1];
                #pragma unroll
                for (int h = 0; h < 2; ++h) {
                    int r = row + h * 8;
                    float v0 = fmaxf(a[h * 2 + 0] + bv0, 0.f);
                    float v1 = fmaxf(a[h * 2 + 1] + bv1, 0.f);
                    __half h0 = __float2half_rn(v0);
                    __half h1 = __float2half_rn(v1);
                    __half2 hp; hp.x = h0; hp.y = h1;
                    __half2 lp;
                    lp.x = __float2half_rn(v0 - __half2float(h0));
                    lp.y = __float2half_rn(v1 - __half2float(h1));
                    *reinterpret_cast<__half2*>(&Chi[(size_t)r * Nd + col]) = hp;
                    *reinterpret_cast<__half2*>(&Clo[(size_t)r * Nd + col]) = lp;
                }
            } else {
                if (col < Nd) {
                    *reinterpret_cast<float2*>(&Cf[(size_t)row * ldc + col]) = make_float2(a[0], a[1]);
                    *reinterpret_cast<float2*>(&Cf[(size_t)(row + 8) * ldc + col]) = make_float2(a[2], a[3]);
                }
            }
        }
    }
}

// ---------------- fp32 GEMM (tiny GEMM3, split-K) ----------------
#define BM 128
#define BK 16

template<int BN_, int TN_>
__global__ __launch_bounds__(256)
void k_gemm(const float* __restrict__ A, int lda,
            const float* __restrict__ B, int ldb,
            float* __restrict__ Cout, int ldc,
            int Nd, int Kloop, int partStride) {
    __shared__ float As[2][BM][BK];
    __shared__ float Bs[2][BK][BN_];

    const int tid = threadIdx.x;
    const int tx = tid & 15;
    const int ty = tid >> 4;
    const int m0 = blockIdx.y * BM;
    const int n0 = blockIdx.x * BN_;

    A += (size_t)blockIdx.z * Kloop;
    B += (size_t)blockIdx.z * Kloop * ldb;
    Cout += (size_t)blockIdx.z * partStride;

    const int arow0 = tid >> 2;
    const int arow1 = arow0 + 64;
    const int ac4 = (tid & 3) * 4;
    const float* gA0 = A + (size_t)(m0 + arow0) * lda + ac4;
    const float* gA1 = A + (size_t)(m0 + arow1) * lda + ac4;

    const int BQ = BN_ / 4;
    const int bkr0 = tid / BQ;
    const int bc0 = (tid % BQ) * 4;
    const float* gB0 = B + (size_t)bkr0 * ldb + n0 + bc0;
    const bool bp0 = (n0 + bc0) < Nd;

    float acc[8][TN_];
    #pragma unroll
    for (int i = 0; i < 8; ++i)
        #pragma unroll
        for (int j = 0; j < TN_; ++j) acc[i][j] = 0.f;

    const int KT = Kloop / BK;

    cpasync16(&As[0][arow0][ac4], gA0, true);
    cpasync16(&As[0][arow1][ac4], gA1, true);
    cpasync16(&Bs[0][bkr0][bc0], gB0, bp0);
    cp_commit();

    int buf = 0;
    for (int kt = 0; kt < KT; ++kt) {
        if (kt + 1 < KT) {
            int ko = (kt + 1) * BK;
            cpasync16(&As[buf ^ 1][arow0][ac4], gA0 + ko, true);
            cpasync16(&As[buf ^ 1][arow1][ac4], gA1 + ko, true);
            cpasync16(&Bs[buf ^ 1][bkr0][bc0], gB0 + (size_t)ko * ldb, bp0);
            cp_commit();
            cp_wait1();
        } else {
            cp_wait0();
        }
        __syncthreads();

        #pragma unroll
        for (int k = 0; k < BK; ++k) {
            float a[8];
            #pragma unroll
            for (int i = 0; i < 8; ++i) a[i] = As[buf][ty * 8 + i][k];
            float b[TN_];
            #pragma unroll
            for (int j = 0; j < TN_; j += 4) {
                float4 v = *reinterpret_cast<const float4*>(&Bs[buf][k][tx * TN_ + j]);
                b[j] = v.x; b[j + 1] = v.y; b[j + 2] = v.z; b[j + 3] = v.w;
            }
            #pragma unroll
            for (int i = 0; i < 8; ++i)
                #pragma unroll
                for (int j = 0; j < TN_; ++j)
                    acc[i][j] += a[i] * b[j];
        }
        __syncthreads();
        buf ^= 1;
    }

    #pragma unroll
    for (int i = 0; i < 8; ++i) {
        int m = m0 + ty * 8 + i;
        #pragma unroll
        for (int j = 0; j < TN_; j += 4) {
            int n = n0 + tx * TN_ + j;
            if (n < Nd) {
                float4 v = make_float4(acc[i][j], acc[i][j + 1], acc[i][j + 2], acc[i][j + 3]);
                *reinterpret_cast<float4*>(&Cout[(size_t)m * ldc + n]) = v;
            }
        }
    }
}

// ---------------- host orchestration ----------------
// fp32 propagation for small C (layers 1, 3)
static float* run_prop_s(const int* nbr, const int* cnt, const float* dvec,
                         const float* feat, const float* w, int C,
                         float* u, float* va, float* vb) {
    int total = NN * C;
    k_scale_u<<<(total + 255) / 256, 256>>>(feat, dvec, u, va, C);
    float* vin = va;
    float* vout = vb;
    for (int k = 5; k >= 1; --k) {
        if (C == C_IN) k_spmm_s<32><<<NN / 8, 256>>>(nbr, cnt, vin, u, vout, w, k, C);
        else           k_spmm_s<8><<<NN / 32, 256>>>(nbr, cnt, vin, u, vout, w, k, C);
        float* t = vin; vin = vout; vout = t;
    }
    return vin;
}

extern "C" void kernel_launch(void* const* d_in, const int* in_sizes, int n_in,
                              void* d_out, int out_size) {
    const float* x  = (const float*)d_in[0];
    const int*   ei = (const int*)  d_in[1];
    const float* w1 = (const float*)d_in[2];
    const float* w2 = (const float*)d_in[3];
    const float* w3 = (const float*)d_in[4];
    const float* W1 = (const float*)d_in[5];
    const float* b1 = (const float*)d_in[6];
    const float* W2 = (const float*)d_in[7];
    const float* b2 = (const float*)d_in[8];
    const float* W3 = (const float*)d_in[9];
    const float* b3 = (const float*)d_in[10];
    float* out = (float*)d_out;

    unsigned *adj, *rA, *rB;
    int *nbr, *cnt;
    float *dvec, *u, *va, *vb, *gg, *h2, *g3, *g3p;
    __half *vha, *vhb, *zhi, *zlo, *w1h, *w2h, *h1hi, *h1lo;
    cudaGetSymbolAddress((void**)&adj,  g_adj);
    cudaGetSymbolAddress((void**)&rA,   g_rA);
    cudaGetSymbolAddress((void**)&rB,   g_rB);
    cudaGetSymbolAddress((void**)&nbr,  g_nbr);
    cudaGetSymbolAddress((void**)&cnt,  g_cnt);
    cudaGetSymbolAddress((void**)&dvec, g_dvec);
    cudaGetSymbolAddress((void**)&u,    g_u);
    cudaGetSymbolAddress((void**)&va,   g_va);
    cudaGetSymbolAddress((void**)&vb,   g_vb);
    cudaGetSymbolAddress((void**)&gg,   g_gg);
    cudaGetSymbolAddress((void**)&h2,   g_h2);
    cudaGetSymbolAddress((void**)&g3,   g_g3);
    cudaGetSymbolAddress((void**)&g3p,  g_g3p);
    cudaGetSymbolAddress((void**)&vha,  g_vha);
    cudaGetSymbolAddress((void**)&vhb,  g_vhb);
    cudaGetSymbolAddress((void**)&zhi,  g_zhi);
    cudaGetSymbolAddress((void**)&zlo,  g_zlo);
    cudaGetSymbolAddress((void**)&w1h,  g_w1h);
    cudaGetSymbolAddress((void**)&w2h,  g_w2h);
    cudaGetSymbolAddress((void**)&h1hi, g_h1hi);
    cudaGetSymbolAddress((void**)&h1lo, g_h1lo);

    cudaFuncSetAttribute(k_gemm_h<0>, cudaFuncAttributeMaxDynamicSharedMemorySize, SMEM_BYTES);
    cudaFuncSetAttribute(k_gemm_h<1>, cudaFuncAttributeMaxDynamicSharedMemorySize, SMEM_BYTES);

    // ---- adjacency + neighbor lists + reach + deg ----
    k_zero_u32<<<(NN * WORDS + 255) / 256, 256>>>(adj, NN * WORDS);
    k_build_adj<<<EE / 256, 256>>>(ei, adj);
    k_build_list<<<NN / 256, 256>>>(adj, nbr, cnt);
    k_reach_init<<<(NN * WORDS + 255) / 256, 256>>>(adj, rA);
    k_reach_iter<<<NN, 64>>>(nbr, cnt, rA, rB);
    k_reach_iter<<<NN, 64>>>(nbr, cnt, rB, rA);
    k_reach_iter<<<NN, 64>>>(nbr, cnt, rA, rB);
    k_reach_iter<<<NN, 64>>>(nbr, cnt, rB, rA);
    k_deg<<<(NN + 255) / 256, 256>>>(rA, dvec);

    // weight conversions (independent; issue early)
    k_tohalf<<<(C_IN * H1D + 255) / 256, 256>>>(W1, w1h, C_IN * H1D);
    k_tohalf<<<(H1D * H2D + 255) / 256, 256>>>(W2, w2h, H1D * H2D);

    // ---- layer 1: h1 = relu((M1_hat x) W1 + b1), split-fp16 output ----
    {
        float* v = run_prop_s(nbr, cnt, dvec, x, w1, C_IN, u, va, vb);
        k_scale_split<<<(NN * C_IN + 255) / 256, 256>>>(v, dvec, w1, zhi, zlo, C_IN);
        dim3 grid(H1D / TBN, NN / TBM, 1);
        k_gemm_h<1><<<grid, 256, SMEM_BYTES>>>(zhi, zlo, C_IN, w1h, H1D,
                                               b1, (float*)0, h1hi, h1lo, H1D, H1D, C_IN);
    }

    // ---- layer 2: h2 = relu(M2_hat (h1 W2) + b2) ----
    // Horner: hops 5,4 fp16->fp16; hop 3 fp16->fp32; hops 2,1 fp32.
    {
        dim3 grid((H2D + TBN - 1) / TBN, NN / TBM, 1);
        k_gemm_h<0><<<grid, 256, SMEM_BYTES>>>(h1hi, h1lo, H1D, w2h, H2D,
                                               (const float*)0, gg, (__half*)0, (__half*)0,
                                               H2D, H2D, H1D);
        int total = NN * H2D;
        k_scale_u_h<<<(total + 255) / 256, 256>>>(gg, dvec, u, vha, H2D);
        k_spmm_h<1><<<NN, 256>>>(nbr, cnt, vha, u, vhb, (float*)0, w2, 5, H2D);
        k_spmm_h<1><<<NN, 256>>>(nbr, cnt, vhb, u, vha, (float*)0, w2, 4, H2D);
        k_spmm_h<0><<<NN, 256>>>(nbr, cnt, vha, u, (__half*)0, va, w2, 3, H2D);
        k_spmm<2><<<NN, 256>>>(nbr, cnt, va, u, vb, w2, 2, H2D);
        k_spmm<2><<<NN, 256>>>(nbr, cnt, vb, u, va, w2, 1, H2D);
        k_final<<<(total + 255) / 256, 256>>>(va, dvec, w2, b2, h2, H2D);
    }

    // ---- layer 3: out = relu(M3_hat (h2 W3) + b3), fp32 split-K GEMM ----
    {
        dim3 grid(1, NN / BM, SK3);
        k_gemm<64, 4><<<grid, 256>>>(h2, H2D, W3, ODIM, g3p, ODIM, ODIM, H2D / SK3, NN * ODIM);
        k_reduce_sk<<<(NN * ODIM + 255) / 256, 256>>>(g3p, g3, NN * ODIM);
        float* v = run_prop_s(nbr, cnt, dvec, g3, w3, ODIM, u, va, vb);
        k_final<<<(NN * ODIM + 255) / 256, 256>>>(v, dvec, w3, b3, out, ODIM);
    }
}

// round 10
// speedup vs baseline: 2.6250x; 1.0685x over previous
#include <cuda_runtime.h>
#include <cuda_fp16.h>

#define NN 2048
#define EE 65536
#define WORDS 64
#define NBMAX 2048
#define C_IN 128
#define H1D 3200
#define H2D 1600
#define ODIM 32
#define SK3 4

// ---------------- scratch (device globals) ----------------
__device__ unsigned g_adj[NN * WORDS];
__device__ unsigned g_rA [NN * WORDS];
__device__ unsigned g_rB [NN * WORDS];
__device__ int      g_nbr[(size_t)NN * NBMAX];
__device__ int      g_cnt[NN];
__device__ float    g_dvec[NN];
__device__ float    g_u  [NN * H2D];
__device__ float    g_va [NN * H2D];
__device__ float    g_vb [NN * H2D];
__device__ float    g_h2 [NN * H2D];
__device__ float    g_g3 [NN * ODIM];
__device__ float    g_g3p[SK3 * NN * ODIM];
// fp16 operands / iterates
__device__ __half g_vha[NN * H2D], g_vhb[NN * H2D];
__device__ __half g_zhi[NN * C_IN],  g_zlo[NN * C_IN];
__device__ __half g_w1h[C_IN * H1D];
__device__ __half g_w2h[H1D * H2D];
__device__ __half g_h1hi[(size_t)NN * H1D], g_h1lo[(size_t)NN * H1D];

// ---------------- utility kernels ----------------
__global__ void k_zero_u32(unsigned* p, int n) {
    int i = blockIdx.x * blockDim.x + threadIdx.x;
    if (i < n) p[i] = 0u;
}

__global__ void k_build_adj(const int* __restrict__ ei, unsigned* __restrict__ adj) {
    int e = blockIdx.x * blockDim.x + threadIdx.x;
    if (e < EE) {
        int src = ei[e];
        int dst = ei[EE + e];
        atomicOr(&adj[dst * WORDS + (src >> 5)], 1u << (src & 31));
    }
}

__global__ void k_build_list(const unsigned* __restrict__ adj,
                             int* __restrict__ nbr, int* __restrict__ cnt) {
    int u = blockIdx.x * blockDim.x + threadIdx.x;
    if (u >= NN) return;
    int c = 0;
    int* out = nbr + (size_t)u * NBMAX;
    for (int w = 0; w < WORDS; ++w) {
        unsigned bits = adj[u * WORDS + w];
        while (bits) {
            int b = __ffs(bits) - 1;
            bits &= bits - 1;
            if (c < NBMAX) out[c] = w * 32 + b;
            ++c;
        }
    }
    cnt[u] = (c < NBMAX) ? c : NBMAX;
}

__global__ void k_reach_init(const unsigned* __restrict__ adj, unsigned* __restrict__ R) {
    int i = blockIdx.x * blockDim.x + threadIdx.x;
    if (i < NN * WORDS) {
        int u = i >> 6, w = i & 63;
        unsigned v = adj[i];
        if ((u >> 5) == w) v |= 1u << (u & 31);
        R[i] = v;
    }
}

__global__ void k_reach_iter(const int* __restrict__ nbr, const int* __restrict__ cnt,
                             const unsigned* __restrict__ Rold, unsigned* __restrict__ Rnew) {
    int u = blockIdx.x;
    int w = threadIdx.x;
    int n = __ldg(&cnt[u]);
    const int* list = nbr + (size_t)u * NBMAX;
    unsigned acc = ((u >> 5) == w) ? (1u << (u & 31)) : 0u;
    int j = 0;
    for (; j + 4 <= n; j += 4) {
        int v0 = __ldg(list + j + 0), v1 = __ldg(list + j + 1);
        int v2 = __ldg(list + j + 2), v3 = __ldg(list + j + 3);
        unsigned r0 = Rold[v0 * WORDS + w];
        unsigned r1 = Rold[v1 * WORDS + w];
        unsigned r2 = Rold[v2 * WORDS + w];
        unsigned r3 = Rold[v3 * WORDS + w];
        acc |= (r0 | r1) | (r2 | r3);
    }
    for (; j < n; ++j) acc |= Rold[__ldg(list + j) * WORDS + w];
    Rnew[u * WORDS + w] = acc;
}

__global__ void k_deg(const unsigned* __restrict__ R, float* __restrict__ d) {
    int u = blockIdx.x * blockDim.x + threadIdx.x;
    if (u < NN) {
        int c = 0;
        #pragma unroll 8
        for (int w = 0; w < WORDS; ++w) c += __popc(R[u * WORDS + w]);
        d[u] = (c > 0) ? rsqrtf((float)c) : 0.0f;
    }
}

__global__ void k_scale_u(const float* __restrict__ feat, const float* __restrict__ d,
                          float* __restrict__ u, float* __restrict__ v, int C) {
    int i = blockIdx.x * blockDim.x + threadIdx.x;
    if (i < NN * C) {
        float val = d[i / C] * feat[i];
        u[i] = val;
        v[i] = val;
    }
}

// ---- SpMM large C, fp16 gather.  MODE 0: fp16 iterate out.
//      MODE 1: final fused epilogue, fp32 out = relu(w0*d*(u+wk*acc)+bias). ----
// Thread t handles 8 channels; C/8 <= 256.
template <int MODE>
__global__ __launch_bounds__(256)
void k_spmm_h(const int* __restrict__ nbr, const int* __restrict__ cnt,
              const __half* __restrict__ vin, const float* __restrict__ uvec,
              __half* __restrict__ vout16, float* __restrict__ vout32,
              const float* __restrict__ wvec, int widx, int C,
              const float* __restrict__ dvec, const float* __restrict__ bias) {
    int u = blockIdx.x;
    int t = threadIdx.x;
    const int L = C >> 3;
    if (t >= L) return;
    int n = __ldg(&cnt[u]);
    const int* list = nbr + (size_t)u * NBMAX;
    float wk = __ldg(&wvec[widx]);

    float acc[8];
    #pragma unroll
    for (int q = 0; q < 8; ++q) acc[q] = 0.f;

    int j = 0;
    for (; j + 4 <= n; j += 4) {
        int v0 = __ldg(list + j + 0), v1 = __ldg(list + j + 1);
        int v2 = __ldg(list + j + 2), v3 = __ldg(list + j + 3);
        uint4 x0 = __ldg(reinterpret_cast<const uint4*>(vin + (size_t)v0 * C) + t);
        uint4 x1 = __ldg(reinterpret_cast<const uint4*>(vin + (size_t)v1 * C) + t);
        uint4 x2 = __ldg(reinterpret_cast<const uint4*>(vin + (size_t)v2 * C) + t);
        uint4 x3 = __ldg(reinterpret_cast<const uint4*>(vin + (size_t)v3 * C) + t);
        const __half2* h0 = reinterpret_cast<const __half2*>(&x0);
        const __half2* h1 = reinterpret_cast<const __half2*>(&x1);
        const __half2* h2 = reinterpret_cast<const __half2*>(&x2);
        const __half2* h3 = reinterpret_cast<const __half2*>(&x3);
        #pragma unroll
        for (int q = 0; q < 4; ++q) {
            float2 f0 = __half22float2(h0[q]);
            float2 f1 = __half22float2(h1[q]);
            float2 f2 = __half22float2(h2[q]);
            float2 f3 = __half22float2(h3[q]);
            acc[2 * q + 0] += (f0.x + f1.x) + (f2.x + f3.x);
            acc[2 * q + 1] += (f0.y + f1.y) + (f2.y + f3.y);
        }
    }
    for (; j < n; ++j) {
        int v = __ldg(list + j);
        uint4 x = __ldg(reinterpret_cast<const uint4*>(vin + (size_t)v * C) + t);
        const __half2* h = reinterpret_cast<const __half2*>(&x);
        #pragma unroll
        for (int q = 0; q < 4; ++q) {
            float2 f = __half22float2(h[q]);
            acc[2 * q + 0] += f.x;
            acc[2 * q + 1] += f.y;
        }
    }

    size_t base = (size_t)u * C + t * 8;
    float4 u0 = *reinterpret_cast<const float4*>(uvec + base);
    float4 u1 = *reinterpret_cast<const float4*>(uvec + base + 4);
    float o[8];
    o[0] = u0.x + wk * acc[0]; o[1] = u0.y + wk * acc[1];
    o[2] = u0.z + wk * acc[2]; o[3] = u0.w + wk * acc[3];
    o[4] = u1.x + wk * acc[4]; o[5] = u1.y + wk * acc[5];
    o[6] = u1.z + wk * acc[6]; o[7] = u1.w + wk * acc[7];
    if (MODE == 0) {
        __half2 hp[4];
        #pragma unroll
        for (int q = 0; q < 4; ++q)
            hp[q] = __floats2half2_rn(o[2 * q], o[2 * q + 1]);
        *(reinterpret_cast<uint4*>(vout16 + base)) = *reinterpret_cast<uint4*>(hp);
    } else {
        float w0d = __ldg(&wvec[0]) * __ldg(&dvec[u]);
        int cb = t * 8;
        float4 b0 = *reinterpret_cast<const float4*>(bias + cb);
        float4 b1 = *reinterpret_cast<const float4*>(bias + cb + 4);
        float r[8];
        r[0] = fmaxf(w0d * o[0] + b0.x, 0.f); r[1] = fmaxf(w0d * o[1] + b0.y, 0.f);
        r[2] = fmaxf(w0d * o[2] + b0.z, 0.f); r[3] = fmaxf(w0d * o[3] + b0.w, 0.f);
        r[4] = fmaxf(w0d * o[4] + b1.x, 0.f); r[5] = fmaxf(w0d * o[5] + b1.y, 0.f);
        r[6] = fmaxf(w0d * o[6] + b1.z, 0.f); r[7] = fmaxf(w0d * o[7] + b1.w, 0.f);
        *reinterpret_cast<float4*>(vout32 + base) = make_float4(r[0], r[1], r[2], r[3]);
        *reinterpret_cast<float4*>(vout32 + base + 4) = make_float4(r[4], r[5], r[6], r[7]);
    }
}

// ---- SpMM small C: LPR float4-lanes per row ----
template <int LPR>
__global__ __launch_bounds__(256)
void k_spmm_s(const int* __restrict__ nbr, const int* __restrict__ cnt,
              const float* __restrict__ vin, const float* __restrict__ uvec,
              float* __restrict__ vout,
              const float* __restrict__ wvec, int widx, int C) {
    const int rpb = 256 / LPR;
    const int r = blockIdx.x * rpb + threadIdx.x / LPR;
    const int lane = threadIdx.x % LPR;
    int n = __ldg(&cnt[r]);
    const int* list = nbr + (size_t)r * NBMAX;
    float wk = __ldg(&wvec[widx]);

    float4 a0 = make_float4(0.f, 0.f, 0.f, 0.f);
    float4 a1 = make_float4(0.f, 0.f, 0.f, 0.f);
    float4 a2 = make_float4(0.f, 0.f, 0.f, 0.f);
    float4 a3 = make_float4(0.f, 0.f, 0.f, 0.f);

    int j = 0;
    for (; j + 4 <= n; j += 4) {
        int v0 = __ldg(list + j + 0), v1 = __ldg(list + j + 1);
        int v2 = __ldg(list + j + 2), v3 = __ldg(list + j + 3);
        float4 x0 = __ldg(reinterpret_cast<const float4*>(vin + (size_t)v0 * C) + lane);
        float4 x1 = __ldg(reinterpret_cast<const float4*>(vin + (size_t)v1 * C) + lane);
        float4 x2 = __ldg(reinterpret_cast<const float4*>(vin + (size_t)v2 * C) + lane);
        float4 x3 = __ldg(reinterpret_cast<const float4*>(vin + (size_t)v3 * C) + lane);
        a0.x += x0.x; a0.y += x0.y; a0.z += x0.z; a0.w += x0.w;
        a1.x += x1.x; a1.y += x1.y; a1.z += x1.z; a1.w += x1.w;
        a2.x += x2.x; a2.y += x2.y; a2.z += x2.z; a2.w += x2.w;
        a3.x += x3.x; a3.y += x3.y; a3.z += x3.z; a3.w += x3.w;
    }
    for (; j < n; ++j) {
        int v = __ldg(list + j);
        float4 x = __ldg(reinterpret_cast<const float4*>(vin + (size_t)v * C) + lane);
        a0.x += x.x; a0.y += x.y; a0.z += x.z; a0.w += x.w;
    }
    float4 s;
    s.x = (a0.x + a1.x) + (a2.x + a3.x);
    s.y = (a0.y + a1.y) + (a2.y + a3.y);
    s.z = (a0.z + a1.z) + (a2.z + a3.z);
    s.w = (a0.w + a1.w) + (a2.w + a3.w);

    float4 uu = *(reinterpret_cast<const float4*>(uvec + (size_t)r * C) + lane);
    float4 o;
    o.x = uu.x + wk * s.x;
    o.y = uu.y + wk * s.y;
    o.z = uu.z + wk * s.z;
    o.w = uu.w + wk * s.w;
    *(reinterpret_cast<float4*>(vout + (size_t)r * C) + lane) = o;
}

// fused: z = w0*d*v, split to fp16 hi/lo (layer-1 pre-GEMM)
__global__ void k_scale_split(const float* __restrict__ v, const float* __restrict__ d,
                              const float* __restrict__ wvec,
                              __half* __restrict__ hi, __half* __restrict__ lo, int C) {
    int i = blockIdx.x * blockDim.x + threadIdx.x;
    if (i < NN * C) {
        float x = wvec[0] * d[i / C] * v[i];
        __half h = __float2half_rn(x);
        hi[i] = h;
        lo[i] = __float2half_rn(x - __half2float(h));
    }
}

__global__ void k_final(const float* __restrict__ v, const float* __restrict__ d,
                        const float* __restrict__ wvec, const float* __restrict__ bias,
                        float* __restrict__ out, int C) {
    int i = blockIdx.x * blockDim.x + threadIdx.x;
    if (i < NN * C) {
        float val = wvec[0] * d[i / C] * v[i] + bias[i % C];
        out[i] = fmaxf(val, 0.0f);
    }
}

__global__ void k_reduce_sk(const float* __restrict__ p, float* __restrict__ out, int n) {
    int i = blockIdx.x * blockDim.x + threadIdx.x;
    if (i < n) {
        float s = 0.f;
        #pragma unroll
        for (int k = 0; k < SK3; ++k) s += p[(size_t)k * n + i];
        out[i] = s;
    }
}

__global__ void k_tohalf(const float* __restrict__ s, __half* __restrict__ h, int n) {
    int i = blockIdx.x * blockDim.x + threadIdx.x;
    if (i < n) h[i] = __float2half_rn(s[i]);
}

// ---------------- cp.async helpers ----------------
__device__ __forceinline__ void cpasync16(void* s, const void* g, bool p) {
    unsigned sa = (unsigned)__cvta_generic_to_shared(s);
    asm volatile("cp.async.cg.shared.global [%0], [%1], 16, %2;"
                 :: "r"(sa), "l"(g), "r"(p ? 16 : 0));
}
__device__ __forceinline__ void cp_commit() { asm volatile("cp.async.commit_group;" ::: "memory"); }
__device__ __forceinline__ void cp_wait0()  { asm volatile("cp.async.wait_group 0;" ::: "memory"); }
__device__ __forceinline__ void cp_wait1()  { asm volatile("cp.async.wait_group 1;" ::: "memory"); }

// ---------------- fp16 2-term tensor-core GEMM ----------------
#define TBM 128
#define TBN 128
#define TBK 32
#define ASTR 40
#define BSTR 136
#define ABUF (TBM * ASTR)
#define BBUF (TBK * BSTR)
#define SMEM_ELEMS (4 * ABUF + 2 * BBUF)
#define SMEM_BYTES (SMEM_ELEMS * 2)

__device__ __forceinline__ unsigned sptr(const void* p) {
    return (unsigned)__cvta_generic_to_shared(p);
}
__device__ __forceinline__ void ldsm4(unsigned& r0, unsigned& r1, unsigned& r2, unsigned& r3, unsigned a) {
    asm volatile("ldmatrix.sync.aligned.m8n8.x4.shared.b16 {%0,%1,%2,%3}, [%4];"
                 : "=r"(r0), "=r"(r1), "=r"(r2), "=r"(r3) : "r"(a));
}
__device__ __forceinline__ void ldsm4t(unsigned& r0, unsigned& r1, unsigned& r2, unsigned& r3, unsigned a) {
    asm volatile("ldmatrix.sync.aligned.m8n8.x4.trans.shared.b16 {%0,%1,%2,%3}, [%4];"
                 : "=r"(r0), "=r"(r1), "=r"(r2), "=r"(r3) : "r"(a));
}
__device__ __forceinline__ void mma16816h(float* c, const unsigned* a, unsigned b0, unsigned b1) {
    asm volatile("mma.sync.aligned.m16n8k16.row.col.f32.f16.f16.f32 "
                 "{%0,%1,%2,%3},{%4,%5,%6,%7},{%8,%9},{%0,%1,%2,%3};"
                 : "+f"(c[0]), "+f"(c[1]), "+f"(c[2]), "+f"(c[3])
                 : "r"(a[0]), "r"(a[1]), "r"(a[2]), "r"(a[3]), "r"(b0), "r"(b1));
}

// EPI=1: +bias, relu, write split fp16 (Chi/Clo).
// EPI=2: val = dv[row]*acc; write Cf (fp32 u) AND Chi (fp16 seed); col<Nd guard.  aux = dvec.
// EPI=0: fp32 out, col<Nd guard.
template<int EPI>
__global__ __launch_bounds__(256, 2)
void k_gemm_h(const __half* __restrict__ Ahi, const __half* __restrict__ Alo, int lda,
              const __half* __restrict__ Bh, int ldb,
              const float* __restrict__ aux,
              float* __restrict__ Cf, __half* __restrict__ Chi, __half* __restrict__ Clo,
              int ldc, int Nd, int K) {
    extern __shared__ __half smh[];
    __half* sAh = smh;
    __half* sAl = sAh + 2 * ABUF;
    __half* sBh = sAl + 2 * ABUF;

    const int tid = threadIdx.x;
    const int wid = tid >> 5, lane = tid & 31;
    const int wm = (wid & 1) * 64;
    const int wn = (wid >> 1) * 32;
    const int m0 = blockIdx.y * TBM, n0 = blockIdx.x * TBN;

    const int a_r = tid >> 2;
    const int a_c = (tid & 3) << 3;
    const int b_r = tid >> 4;
    const int b_c = (tid & 15) << 3;
    const bool pb = (n0 + b_c) < Nd;

    const __half* gAh0 = Ahi + (size_t)(m0 + a_r) * lda + a_c;
    const __half* gAh1 = Ahi + (size_t)(m0 + a_r + 64) * lda + a_c;
    const __half* gAl0 = Alo + (size_t)(m0 + a_r) * lda + a_c;
    const __half* gAl1 = Alo + (size_t)(m0 + a_r + 64) * lda + a_c;
    const __half* gB0  = Bh + (size_t)b_r * ldb + n0 + b_c;
    const __half* gB1  = Bh + (size_t)(b_r + 16) * ldb + n0 + b_c;

    float acc[4][4][4];
    #pragma unroll
    for (int i = 0; i < 4; ++i)
        #pragma unroll
        for (int j = 0; j < 4; ++j)
            #pragma unroll
            for (int q = 0; q < 4; ++q) acc[i][j][q] = 0.f;

    const int KT = K / TBK;

    cpasync16(sAh + a_r * ASTR + a_c, gAh0, true);
    cpasync16(sAh + (a_r + 64) * ASTR + a_c, gAh1, true);
    cpasync16(sAl + a_r * ASTR + a_c, gAl0, true);
    cpasync16(sAl + (a_r + 64) * ASTR + a_c, gAl1, true);
    cpasync16(sBh + b_r * BSTR + b_c, gB0, pb);
    cpasync16(sBh + (b_r + 16) * BSTR + b_c, gB1, pb);
    cp_commit();

    const int l16 = lane & 15;
    const int hsel = (lane >> 4) << 3;
    const int bg = lane >> 3, bl8 = lane & 7;
    const int bkoff = ((bg & 1) << 3) + bl8;
    const int bnoff = wn + ((bg >> 1) << 3);

    int buf = 0;
    for (int kt = 0; kt < KT; ++kt) {
        if (kt + 1 < KT) {
            int ko = (kt + 1) * TBK;
            int ob = (buf ^ 1);
            cpasync16(sAh + ob * ABUF + a_r * ASTR + a_c, gAh0 + ko, true);
            cpasync16(sAh + ob * ABUF + (a_r + 64) * ASTR + a_c, gAh1 + ko, true);
            cpasync16(sAl + ob * ABUF + a_r * ASTR + a_c, gAl0 + ko, true);
            cpasync16(sAl + ob * ABUF + (a_r + 64) * ASTR + a_c, gAl1 + ko, true);
            cpasync16(sBh + ob * BBUF + b_r * BSTR + b_c, gB0 + (size_t)ko * ldb, pb);
            cpasync16(sBh + ob * BBUF + (b_r + 16) * BSTR + b_c, gB1 + (size_t)ko * ldb, pb);
            cp_commit();
            cp_wait1();
        } else {
            cp_wait0();
        }
        __syncthreads();

        #pragma unroll
        for (int ks = 0; ks < 2; ++ks) {
            const int ko = ks * 16;
            unsigned bh[8];
            {
                unsigned ab = sptr(sBh + buf * BBUF + (ko + bkoff) * BSTR + bnoff);
                ldsm4t(bh[0], bh[1], bh[2], bh[3], ab);
                ldsm4t(bh[4], bh[5], bh[6], bh[7], ab + 32);
            }
            #pragma unroll
            for (int mi = 0; mi < 4; ++mi) {
                unsigned ah[4], alr[4];
                unsigned aa = sptr(sAh + buf * ABUF + (wm + mi * 16 + l16) * ASTR + ko + hsel);
                ldsm4(ah[0], ah[1], ah[2], ah[3], aa);
                unsigned aal = sptr(sAl + buf * ABUF + (wm + mi * 16 + l16) * ASTR + ko + hsel);
                ldsm4(alr[0], alr[1], alr[2], alr[3], aal);
                #pragma unroll
                for (int nj = 0; nj < 4; ++nj) {
                    int bi = (nj >> 1) * 4 + (nj & 1) * 2;
                    mma16816h(acc[mi][nj], ah, bh[bi], bh[bi + 1]);
                    mma16816h(acc[mi][nj], alr, bh[bi], bh[bi + 1]);
                }
            }
        }
        __syncthreads();
        buf ^= 1;
    }

    const int er = lane >> 2;
    const int ec = (lane & 3) << 1;
    #pragma unroll
    for (int mi = 0; mi < 4; ++mi) {
        #pragma unroll
        for (int nj = 0; nj < 4; ++nj) {
            int row = m0 + wm + mi * 16 + er;
            int col = n0 + wn + nj * 8 + ec;
            float* a = acc[mi][nj];
            if (EPI == 1) {
                float bv0 = aux[col], bv1 = aux[col + 1];
                #pragma unroll
                for (int h = 0; h < 2; ++h) {
                    int r = row + h * 8;
                    float v0 = fmaxf(a[h * 2 + 0] + bv0, 0.f);
                    float v1 = fmaxf(a[h * 2 + 1] + bv1, 0.f);
                    __half h0 = __float2half_rn(v0);
                    __half h1 = __float2half_rn(v1);
                    __half2 hp; hp.x = h0; hp.y = h1;
                    __half2 lp;
                    lp.x = __float2half_rn(v0 - __half2float(h0));
                    lp.y = __float2half_rn(v1 - __half2float(h1));
                    *reinterpret_cast<__half2*>(&Chi[(size_t)r * Nd + col]) = hp;
                    *reinterpret_cast<__half2*>(&Clo[(size_t)r * Nd + col]) = lp;
                }
            } else if (EPI == 2) {
                if (col < Nd) {    // guard: grid.x overshoots Nd by one partial tile
                    #pragma unroll
                    for (int h = 0; h < 2; ++h) {
                        int r = row + h * 8;
                        float dv = __ldg(&aux[r]);
                        float v0 = dv * a[h * 2 + 0];
                        float v1 = dv * a[h * 2 + 1];
                        *reinterpret_cast<float2*>(&Cf[(size_t)r * ldc + col]) = make_float2(v0, v1);
                        *reinterpret_cast<__half2*>(&Chi[(size_t)r * Nd + col]) = __floats2half2_rn(v0, v1);
                    }
                }
            } else {
                if (col < Nd) {
                    *reinterpret_cast<float2*>(&Cf[(size_t)row * ldc + col]) = make_float2(a[0], a[1]);
                    *reinterpret_cast<float2*>(&Cf[(size_t)(row + 8) * ldc + col]) = make_float2(a[2], a[3]);
                }
            }
        }
    }
}

// ---------------- fp32 GEMM (tiny GEMM3, split-K) ----------------
#define BM 128
#define BK 16

template<int BN_, int TN_>
__global__ __launch_bounds__(256)
void k_gemm(const float* __restrict__ A, int lda,
            const float* __restrict__ B, int ldb,
            float* __restrict__ Cout, int ldc,
            int Nd, int Kloop, int partStride) {
    __shared__ float As[2][BM][BK];
    __shared__ float Bs[2][BK][BN_];

    const int tid = threadIdx.x;
    const int tx = tid & 15;
    const int ty = tid >> 4;
    const int m0 = blockIdx.y * BM;
    const int n0 = blockIdx.x * BN_;

    A += (size_t)blockIdx.z * Kloop;
    B += (size_t)blockIdx.z * Kloop * ldb;
    Cout += (size_t)blockIdx.z * partStride;

    const int arow0 = tid >> 2;
    const int arow1 = arow0 + 64;
    const int ac4 = (tid & 3) * 4;
    const float* gA0 = A + (size_t)(m0 + arow0) * lda + ac4;
    const float* gA1 = A + (size_t)(m0 + arow1) * lda + ac4;

    const int BQ = BN_ / 4;
    const int bkr0 = tid / BQ;
    const int bc0 = (tid % BQ) * 4;
    const float* gB0 = B + (size_t)bkr0 * ldb + n0 + bc0;
    const bool bp0 = (n0 + bc0) < Nd;

    float acc[8][TN_];
    #pragma unroll
    for (int i = 0; i < 8; ++i)
        #pragma unroll
        for (int j = 0; j < TN_; ++j) acc[i][j] = 0.f;

    const int KT = Kloop / BK;

    cpasync16(&As[0][arow0][ac4], gA0, true);
    cpasync16(&As[0][arow1][ac4], gA1, true);
    cpasync16(&Bs[0][bkr0][bc0], gB0, bp0);
    cp_commit();

    int buf = 0;
    for (int kt = 0; kt < KT; ++kt) {
        if (kt + 1 < KT) {
            int ko = (kt + 1) * BK;
            cpasync16(&As[buf ^ 1][arow0][ac4], gA0 + ko, true);
            cpasync16(&As[buf ^ 1][arow1][ac4], gA1 + ko, true);
            cpasync16(&Bs[buf ^ 1][bkr0][bc0], gB0 + (size_t)ko * ldb, bp0);
            cp_commit();
            cp_wait1();
        } else {
            cp_wait0();
        }
        __syncthreads();

        #pragma unroll
        for (int k = 0; k < BK; ++k) {
            float a[8];
            #pragma unroll
            for (int i = 0; i < 8; ++i) a[i] = As[buf][ty * 8 + i][k];
            float b[TN_];
            #pragma unroll
            for (int j = 0; j < TN_; j += 4) {
                float4 v = *reinterpret_cast<const float4*>(&Bs[buf][k][tx * TN_ + j]);
                b[j] = v.x; b[j + 1] = v.y; b[j + 2] = v.z; b[j + 3] = v.w;
            }
            #pragma unroll
            for (int i = 0; i < 8; ++i)
                #pragma unroll
                for (int j = 0; j < TN_; ++j)
                    acc[i][j] += a[i] * b[j];
        }
        __syncthreads();
        buf ^= 1;
    }

    #pragma unroll
    for (int i = 0; i < 8; ++i) {
        int m = m0 + ty * 8 + i;
        #pragma unroll
        for (int j = 0; j < TN_; j += 4) {
            int n = n0 + tx * TN_ + j;
            if (n < Nd) {
                float4 v = make_float4(acc[i][j], acc[i][j + 1], acc[i][j + 2], acc[i][j + 3]);
                *reinterpret_cast<float4*>(&Cout[(size_t)m * ldc + n]) = v;
            }
        }
    }
}

// ---------------- host orchestration ----------------
static float* run_prop_s(const int* nbr, const int* cnt, const float* dvec,
                         const float* feat, const float* w, int C,
                         float* u, float* va, float* vb) {
    int total = NN * C;
    k_scale_u<<<(total + 255) / 256, 256>>>(feat, dvec, u, va, C);
    float* vin = va;
    float* vout = vb;
    for (int k = 5; k >= 1; --k) {
        if (C == C_IN) k_spmm_s<32><<<NN / 8, 256>>>(nbr, cnt, vin, u, vout, w, k, C);
        else           k_spmm_s<8><<<NN / 32, 256>>>(nbr, cnt, vin, u, vout, w, k, C);
        float* t = vin; vin = vout; vout = t;
    }
    return vin;
}

extern "C" void kernel_launch(void* const* d_in, const int* in_sizes, int n_in,
                              void* d_out, int out_size) {
    const float* x  = (const float*)d_in[0];
    const int*   ei = (const int*)  d_in[1];
    const float* w1 = (const float*)d_in[2];
    const float* w2 = (const float*)d_in[3];
    const float* w3 = (const float*)d_in[4];
    const float* W1 = (const float*)d_in[5];
    const float* b1 = (const float*)d_in[6];
    const float* W2 = (const float*)d_in[7];
    const float* b2 = (const float*)d_in[8];
    const float* W3 = (const float*)d_in[9];
    const float* b3 = (const float*)d_in[10];
    float* out = (float*)d_out;

    unsigned *adj, *rA, *rB;
    int *nbr, *cnt;
    float *dvec, *u, *va, *vb, *h2, *g3, *g3p;
    __half *vha, *vhb, *zhi, *zlo, *w1h, *w2h, *h1hi, *h1lo;
    cudaGetSymbolAddress((void**)&adj,  g_adj);
    cudaGetSymbolAddress((void**)&rA,   g_rA);
    cudaGetSymbolAddress((void**)&rB,   g_rB);
    cudaGetSymbolAddress((void**)&nbr,  g_nbr);
    cudaGetSymbolAddress((void**)&cnt,  g_cnt);
    cudaGetSymbolAddress((void**)&dvec, g_dvec);
    cudaGetSymbolAddress((void**)&u,    g_u);
    cudaGetSymbolAddress((void**)&va,   g_va);
    cudaGetSymbolAddress((void**)&vb,   g_vb);
    cudaGetSymbolAddress((void**)&h2,   g_h2);
    cudaGetSymbolAddress((void**)&g3,   g_g3);
    cudaGetSymbolAddress((void**)&g3p,  g_g3p);
    cudaGetSymbolAddress((void**)&vha,  g_vha);
    cudaGetSymbolAddress((void**)&vhb,  g_vhb);
    cudaGetSymbolAddress((void**)&zhi,  g_zhi);
    cudaGetSymbolAddress((void**)&zlo,  g_zlo);
    cudaGetSymbolAddress((void**)&w1h,  g_w1h);
    cudaGetSymbolAddress((void**)&w2h,  g_w2h);
    cudaGetSymbolAddress((void**)&h1hi, g_h1hi);
    cudaGetSymbolAddress((void**)&h1lo, g_h1lo);

    cudaFuncSetAttribute(k_gemm_h<1>, cudaFuncAttributeMaxDynamicSharedMemorySize, SMEM_BYTES);
    cudaFuncSetAttribute(k_gemm_h<2>, cudaFuncAttributeMaxDynamicSharedMemorySize, SMEM_BYTES);

    // ---- adjacency + neighbor lists + reach + deg ----
    k_zero_u32<<<(NN * WORDS + 255) / 256, 256>>>(adj, NN * WORDS);
    k_build_adj<<<EE / 256, 256>>>(ei, adj);
    k_build_list<<<NN / 256, 256>>>(adj, nbr, cnt);
    k_reach_init<<<(NN * WORDS + 255) / 256, 256>>>(adj, rA);
    k_reach_iter<<<NN, 64>>>(nbr, cnt, rA, rB);
    k_reach_iter<<<NN, 64>>>(nbr, cnt, rB, rA);
    k_reach_iter<<<NN, 64>>>(nbr, cnt, rA, rB);
    k_reach_iter<<<NN, 64>>>(nbr, cnt, rB, rA);
    k_deg<<<(NN + 255) / 256, 256>>>(rA, dvec);

    // weight conversions (independent; issue early)
    k_tohalf<<<(C_IN * H1D + 255) / 256, 256>>>(W1, w1h, C_IN * H1D);
    k_tohalf<<<(H1D * H2D + 255) / 256, 256>>>(W2, w2h, H1D * H2D);

    // ---- layer 1: h1 = relu((M1_hat x) W1 + b1), split-fp16 output ----
    {
        float* v = run_prop_s(nbr, cnt, dvec, x, w1, C_IN, u, va, vb);
        k_scale_split<<<(NN * C_IN + 255) / 256, 256>>>(v, dvec, w1, zhi, zlo, C_IN);
        dim3 grid(H1D / TBN, NN / TBM, 1);
        k_gemm_h<1><<<grid, 256, SMEM_BYTES>>>(zhi, zlo, C_IN, w1h, H1D,
                                               b1, (float*)0, h1hi, h1lo, H1D, H1D, C_IN);
    }

    // ---- layer 2: h2 = relu(M2_hat (h1 W2) + b2) ----
    // GEMM2 epilogue writes u (fp32) + vha (fp16 seed). All 5 hops fp16; hop 1
    // fuses the w0*d*. + bias + relu epilogue and writes h2 directly.
    {
        dim3 grid((H2D + TBN - 1) / TBN, NN / TBM, 1);
        k_gemm_h<2><<<grid, 256, SMEM_BYTES>>>(h1hi, h1lo, H1D, w2h, H2D,
                                               dvec, u, vha, (__half*)0, H2D, H2D, H1D);
        k_spmm_h<0><<<NN, 256>>>(nbr, cnt, vha, u, vhb, (float*)0, w2, 5, H2D, (float*)0, (float*)0);
        k_spmm_h<0><<<NN, 256>>>(nbr, cnt, vhb, u, vha, (float*)0, w2, 4, H2D, (float*)0, (float*)0);
        k_spmm_h<0><<<NN, 256>>>(nbr, cnt, vha, u, vhb, (float*)0, w2, 3, H2D, (float*)0, (float*)0);
        k_spmm_h<0><<<NN, 256>>>(nbr, cnt, vhb, u, vha, (float*)0, w2, 2, H2D, (float*)0, (float*)0);
        k_spmm_h<1><<<NN, 256>>>(nbr, cnt, vha, u, (__half*)0, h2, w2, 1, H2D, dvec, b2);
    }

    // ---- layer 3: out = relu(M3_hat (h2 W3) + b3), fp32 split-K GEMM ----
    {
        dim3 grid(1, NN / BM, SK3);
        k_gemm<64, 4><<<grid, 256>>>(h2, H2D, W3, ODIM, g3p, ODIM, ODIM, H2D / SK3, NN * ODIM);
        k_reduce_sk<<<(NN * ODIM + 255) / 256, 256>>>(g3p, g3, NN * ODIM);
        float* v = run_prop_s(nbr, cnt, dvec, g3, w3, ODIM, u, va, vb);
        k_final<<<(NN * ODIM + 255) / 256, 256>>>(v, dvec, w3, b3, out, ODIM);
    }
}

// round 11
// speedup vs baseline: 3.0678x; 1.1687x over previous
#include <cuda_runtime.h>
#include <cuda_fp16.h>

#define NN 2048
#define EE 65536
#define WORDS 64
#define NBMAX 2048
#define C_IN 128
#define H1D 3200
#define H2D 1600
#define ODIM 32
#define SK3 4

// ---------------- scratch (device globals) ----------------
__device__ unsigned g_adj[NN * WORDS];
__device__ unsigned g_rA [NN * WORDS];
__device__ unsigned g_rB [NN * WORDS];
__device__ int      g_nbr[(size_t)NN * NBMAX];
__device__ int      g_cnt[NN];
__device__ float    g_dvec[NN];
__device__ float    g_u  [NN * H2D];
__device__ float    g_va [NN * H2D];
__device__ float    g_vb [NN * H2D];
__device__ float    g_h2 [NN * H2D];
__device__ float    g_g3 [NN * ODIM];
__device__ float    g_g3p[SK3 * NN * ODIM];
// fp16 operands / iterates
__device__ __half g_vha[NN * H2D], g_vhb[NN * H2D];
__device__ __half g_zhi[NN * C_IN],  g_zlo[NN * C_IN];
__device__ __half g_w1h[C_IN * H1D];
__device__ __half g_w2h[H1D * H2D];
__device__ __half g_h1h[(size_t)NN * H1D];   // h1, single fp16

// ---------------- utility kernels ----------------
__global__ void k_zero_u32(unsigned* p, int n) {
    int i = blockIdx.x * blockDim.x + threadIdx.x;
    if (i < n) p[i] = 0u;
}

__global__ void k_build_adj(const int* __restrict__ ei, unsigned* __restrict__ adj) {
    int e = blockIdx.x * blockDim.x + threadIdx.x;
    if (e < EE) {
        int src = ei[e];
        int dst = ei[EE + e];
        atomicOr(&adj[dst * WORDS + (src >> 5)], 1u << (src & 31));
    }
}

__global__ void k_build_list(const unsigned* __restrict__ adj,
                             int* __restrict__ nbr, int* __restrict__ cnt) {
    int u = blockIdx.x * blockDim.x + threadIdx.x;
    if (u >= NN) return;
    int c = 0;
    int* out = nbr + (size_t)u * NBMAX;
    for (int w = 0; w < WORDS; ++w) {
        unsigned bits = adj[u * WORDS + w];
        while (bits) {
            int b = __ffs(bits) - 1;
            bits &= bits - 1;
            if (c < NBMAX) out[c] = w * 32 + b;
            ++c;
        }
    }
    cnt[u] = (c < NBMAX) ? c : NBMAX;
}

__global__ void k_reach_init(const unsigned* __restrict__ adj, unsigned* __restrict__ R) {
    int i = blockIdx.x * blockDim.x + threadIdx.x;
    if (i < NN * WORDS) {
        int u = i >> 6, w = i & 63;
        unsigned v = adj[i];
        if ((u >> 5) == w) v |= 1u << (u & 31);
        R[i] = v;
    }
}

__global__ void k_reach_iter(const int* __restrict__ nbr, const int* __restrict__ cnt,
                             const unsigned* __restrict__ Rold, unsigned* __restrict__ Rnew) {
    int u = blockIdx.x;
    int w = threadIdx.x;
    int n = __ldg(&cnt[u]);
    const int* list = nbr + (size_t)u * NBMAX;
    unsigned acc = ((u >> 5) == w) ? (1u << (u & 31)) : 0u;
    int j = 0;
    for (; j + 4 <= n; j += 4) {
        int v0 = __ldg(list + j + 0), v1 = __ldg(list + j + 1);
        int v2 = __ldg(list + j + 2), v3 = __ldg(list + j + 3);
        unsigned r0 = Rold[v0 * WORDS + w];
        unsigned r1 = Rold[v1 * WORDS + w];
        unsigned r2 = Rold[v2 * WORDS + w];
        unsigned r3 = Rold[v3 * WORDS + w];
        acc |= (r0 | r1) | (r2 | r3);
    }
    for (; j < n; ++j) acc |= Rold[__ldg(list + j) * WORDS + w];
    Rnew[u * WORDS + w] = acc;
}

__global__ void k_deg(const unsigned* __restrict__ R, float* __restrict__ d) {
    int u = blockIdx.x * blockDim.x + threadIdx.x;
    if (u < NN) {
        int c = 0;
        #pragma unroll 8
        for (int w = 0; w < WORDS; ++w) c += __popc(R[u * WORDS + w]);
        d[u] = (c > 0) ? rsqrtf((float)c) : 0.0f;
    }
}

__global__ void k_scale_u(const float* __restrict__ feat, const float* __restrict__ d,
                          float* __restrict__ u, float* __restrict__ v, int C) {
    int i = blockIdx.x * blockDim.x + threadIdx.x;
    if (i < NN * C) {
        float val = d[i / C] * feat[i];
        u[i] = val;
        v[i] = val;
    }
}

// ---- SpMM large C, fp16 gather.  MODE 0: fp16 iterate out.
//      MODE 1: final fused epilogue, fp32 out = relu(w0*d*(u+wk*acc)+bias). ----
template <int MODE>
__global__ __launch_bounds__(256)
void k_spmm_h(const int* __restrict__ nbr, const int* __restrict__ cnt,
              const __half* __restrict__ vin, const float* __restrict__ uvec,
              __half* __restrict__ vout16, float* __restrict__ vout32,
              const float* __restrict__ wvec, int widx, int C,
              const float* __restrict__ dvec, const float* __restrict__ bias) {
    int u = blockIdx.x;
    int t = threadIdx.x;
    const int L = C >> 3;
    if (t >= L) return;
    int n = __ldg(&cnt[u]);
    const int* list = nbr + (size_t)u * NBMAX;
    float wk = __ldg(&wvec[widx]);

    float acc[8];
    #pragma unroll
    for (int q = 0; q < 8; ++q) acc[q] = 0.f;

    int j = 0;
    for (; j + 4 <= n; j += 4) {
        int v0 = __ldg(list + j + 0), v1 = __ldg(list + j + 1);
        int v2 = __ldg(list + j + 2), v3 = __ldg(list + j + 3);
        uint4 x0 = __ldg(reinterpret_cast<const uint4*>(vin + (size_t)v0 * C) + t);
        uint4 x1 = __ldg(reinterpret_cast<const uint4*>(vin + (size_t)v1 * C) + t);
        uint4 x2 = __ldg(reinterpret_cast<const uint4*>(vin + (size_t)v2 * C) + t);
        uint4 x3 = __ldg(reinterpret_cast<const uint4*>(vin + (size_t)v3 * C) + t);
        const __half2* h0 = reinterpret_cast<const __half2*>(&x0);
        const __half2* h1 = reinterpret_cast<const __half2*>(&x1);
        const __half2* h2 = reinterpret_cast<const __half2*>(&x2);
        const __half2* h3 = reinterpret_cast<const __half2*>(&x3);
        #pragma unroll
        for (int q = 0; q < 4; ++q) {
            float2 f0 = __half22float2(h0[q]);
            float2 f1 = __half22float2(h1[q]);
            float2 f2 = __half22float2(h2[q]);
            float2 f3 = __half22float2(h3[q]);
            acc[2 * q + 0] += (f0.x + f1.x) + (f2.x + f3.x);
            acc[2 * q + 1] += (f0.y + f1.y) + (f2.y + f3.y);
        }
    }
    for (; j < n; ++j) {
        int v = __ldg(list + j);
        uint4 x = __ldg(reinterpret_cast<const uint4*>(vin + (size_t)v * C) + t);
        const __half2* h = reinterpret_cast<const __half2*>(&x);
        #pragma unroll
        for (int q = 0; q < 4; ++q) {
            float2 f = __half22float2(h[q]);
            acc[2 * q + 0] += f.x;
            acc[2 * q + 1] += f.y;
        }
    }

    size_t base = (size_t)u * C + t * 8;
    float4 u0 = *reinterpret_cast<const float4*>(uvec + base);
    float4 u1 = *reinterpret_cast<const float4*>(uvec + base + 4);
    float o[8];
    o[0] = u0.x + wk * acc[0]; o[1] = u0.y + wk * acc[1];
    o[2] = u0.z + wk * acc[2]; o[3] = u0.w + wk * acc[3];
    o[4] = u1.x + wk * acc[4]; o[5] = u1.y + wk * acc[5];
    o[6] = u1.z + wk * acc[6]; o[7] = u1.w + wk * acc[7];
    if (MODE == 0) {
        __half2 hp[4];
        #pragma unroll
        for (int q = 0; q < 4; ++q)
            hp[q] = __floats2half2_rn(o[2 * q], o[2 * q + 1]);
        *(reinterpret_cast<uint4*>(vout16 + base)) = *reinterpret_cast<uint4*>(hp);
    } else {
        float w0d = __ldg(&wvec[0]) * __ldg(&dvec[u]);
        int cb = t * 8;
        float4 b0 = *reinterpret_cast<const float4*>(bias + cb);
        float4 b1 = *reinterpret_cast<const float4*>(bias + cb + 4);
        float r[8];
        r[0] = fmaxf(w0d * o[0] + b0.x, 0.f); r[1] = fmaxf(w0d * o[1] + b0.y, 0.f);
        r[2] = fmaxf(w0d * o[2] + b0.z, 0.f); r[3] = fmaxf(w0d * o[3] + b0.w, 0.f);
        r[4] = fmaxf(w0d * o[4] + b1.x, 0.f); r[5] = fmaxf(w0d * o[5] + b1.y, 0.f);
        r[6] = fmaxf(w0d * o[6] + b1.z, 0.f); r[7] = fmaxf(w0d * o[7] + b1.w, 0.f);
        *reinterpret_cast<float4*>(vout32 + base) = make_float4(r[0], r[1], r[2], r[3]);
        *reinterpret_cast<float4*>(vout32 + base + 4) = make_float4(r[4], r[5], r[6], r[7]);
    }
}

// ---- SpMM small C: LPR float4-lanes per row ----
template <int LPR>
__global__ __launch_bounds__(256)
void k_spmm_s(const int* __restrict__ nbr, const int* __restrict__ cnt,
              const float* __restrict__ vin, const float* __restrict__ uvec,
              float* __restrict__ vout,
              const float* __restrict__ wvec, int widx, int C) {
    const int rpb = 256 / LPR;
    const int r = blockIdx.x * rpb + threadIdx.x / LPR;
    const int lane = threadIdx.x % LPR;
    int n = __ldg(&cnt[r]);
    const int* list = nbr + (size_t)r * NBMAX;
    float wk = __ldg(&wvec[widx]);

    float4 a0 = make_float4(0.f, 0.f, 0.f, 0.f);
    float4 a1 = make_float4(0.f, 0.f, 0.f, 0.f);
    float4 a2 = make_float4(0.f, 0.f, 0.f, 0.f);
    float4 a3 = make_float4(0.f, 0.f, 0.f, 0.f);

    int j = 0;
    for (; j + 4 <= n; j += 4) {
        int v0 = __ldg(list + j + 0), v1 = __ldg(list + j + 1);
        int v2 = __ldg(list + j + 2), v3 = __ldg(list + j + 3);
        float4 x0 = __ldg(reinterpret_cast<const float4*>(vin + (size_t)v0 * C) + lane);
        float4 x1 = __ldg(reinterpret_cast<const float4*>(vin + (size_t)v1 * C) + lane);
        float4 x2 = __ldg(reinterpret_cast<const float4*>(vin + (size_t)v2 * C) + lane);
        float4 x3 = __ldg(reinterpret_cast<const float4*>(vin + (size_t)v3 * C) + lane);
        a0.x += x0.x; a0.y += x0.y; a0.z += x0.z; a0.w += x0.w;
        a1.x += x1.x; a1.y += x1.y; a1.z += x1.z; a1.w += x1.w;
        a2.x += x2.x; a2.y += x2.y; a2.z += x2.z; a2.w += x2.w;
        a3.x += x3.x; a3.y += x3.y; a3.z += x3.z; a3.w += x3.w;
    }
    for (; j < n; ++j) {
        int v = __ldg(list + j);
        float4 x = __ldg(reinterpret_cast<const float4*>(vin + (size_t)v * C) + lane);
        a0.x += x.x; a0.y += x.y; a0.z += x.z; a0.w += x.w;
    }
    float4 s;
    s.x = (a0.x + a1.x) + (a2.x + a3.x);
    s.y = (a0.y + a1.y) + (a2.y + a3.y);
    s.z = (a0.z + a1.z) + (a2.z + a3.z);
    s.w = (a0.w + a1.w) + (a2.w + a3.w);

    float4 uu = *(reinterpret_cast<const float4*>(uvec + (size_t)r * C) + lane);
    float4 o;
    o.x = uu.x + wk * s.x;
    o.y = uu.y + wk * s.y;
    o.z = uu.z + wk * s.z;
    o.w = uu.w + wk * s.w;
    *(reinterpret_cast<float4*>(vout + (size_t)r * C) + lane) = o;
}

// fused: z = w0*d*v, split to fp16 hi/lo (layer-1 pre-GEMM)
__global__ void k_scale_split(const float* __restrict__ v, const float* __restrict__ d,
                              const float* __restrict__ wvec,
                              __half* __restrict__ hi, __half* __restrict__ lo, int C) {
    int i = blockIdx.x * blockDim.x + threadIdx.x;
    if (i < NN * C) {
        float x = wvec[0] * d[i / C] * v[i];
        __half h = __float2half_rn(x);
        hi[i] = h;
        lo[i] = __float2half_rn(x - __half2float(h));
    }
}

__global__ void k_final(const float* __restrict__ v, const float* __restrict__ d,
                        const float* __restrict__ wvec, const float* __restrict__ bias,
                        float* __restrict__ out, int C) {
    int i = blockIdx.x * blockDim.x + threadIdx.x;
    if (i < NN * C) {
        float val = wvec[0] * d[i / C] * v[i] + bias[i % C];
        out[i] = fmaxf(val, 0.0f);
    }
}

__global__ void k_reduce_sk(const float* __restrict__ p, float* __restrict__ out, int n) {
    int i = blockIdx.x * blockDim.x + threadIdx.x;
    if (i < n) {
        float s = 0.f;
        #pragma unroll
        for (int k = 0; k < SK3; ++k) s += p[(size_t)k * n + i];
        out[i] = s;
    }
}

__global__ void k_tohalf(const float* __restrict__ s, __half* __restrict__ h, int n) {
    int i = blockIdx.x * blockDim.x + threadIdx.x;
    if (i < n) h[i] = __float2half_rn(s[i]);
}

// ---------------- cp.async helpers ----------------
__device__ __forceinline__ void cpasync16(void* s, const void* g, bool p) {
    unsigned sa = (unsigned)__cvta_generic_to_shared(s);
    asm volatile("cp.async.cg.shared.global [%0], [%1], 16, %2;"
                 :: "r"(sa), "l"(g), "r"(p ? 16 : 0));
}
__device__ __forceinline__ void cp_commit() { asm volatile("cp.async.commit_group;" ::: "memory"); }
__device__ __forceinline__ void cp_wait0()  { asm volatile("cp.async.wait_group 0;" ::: "memory"); }
__device__ __forceinline__ void cp_wait1()  { asm volatile("cp.async.wait_group 1;" ::: "memory"); }

// ---------------- fp16 tensor-core GEMM ----------------
#define TBM 128
#define TBN 128
#define TBK 32
#define ASTR 40
#define BSTR 136
#define ABUF (TBM * ASTR)
#define BBUF (TBK * BSTR)
#define SMEM_BYTES_2A ((4 * ABUF + 2 * BBUF) * 2)
#define SMEM_BYTES_1A ((2 * ABUF + 2 * BBUF) * 2)

__device__ __forceinline__ unsigned sptr(const void* p) {
    return (unsigned)__cvta_generic_to_shared(p);
}
__device__ __forceinline__ void ldsm4(unsigned& r0, unsigned& r1, unsigned& r2, unsigned& r3, unsigned a) {
    asm volatile("ldmatrix.sync.aligned.m8n8.x4.shared.b16 {%0,%1,%2,%3}, [%4];"
                 : "=r"(r0), "=r"(r1), "=r"(r2), "=r"(r3) : "r"(a));
}
__device__ __forceinline__ void ldsm4t(unsigned& r0, unsigned& r1, unsigned& r2, unsigned& r3, unsigned a) {
    asm volatile("ldmatrix.sync.aligned.m8n8.x4.trans.shared.b16 {%0,%1,%2,%3}, [%4];"
                 : "=r"(r0), "=r"(r1), "=r"(r2), "=r"(r3) : "r"(a));
}
__device__ __forceinline__ void mma16816h(float* c, const unsigned* a, unsigned b0, unsigned b1) {
    asm volatile("mma.sync.aligned.m16n8k16.row.col.f32.f16.f16.f32 "
                 "{%0,%1,%2,%3},{%4,%5,%6,%7},{%8,%9},{%0,%1,%2,%3};"
                 : "+f"(c[0]), "+f"(c[1]), "+f"(c[2]), "+f"(c[3])
                 : "r"(a[0]), "r"(a[1]), "r"(a[2]), "r"(a[3]), "r"(b0), "r"(b1));
}

// TWOA=1: D = (Ahi + Alo) * B.  TWOA=0: D = Ahi * B (Alo unused).
// EPI=1: +bias, relu, write single fp16 Chi.
// EPI=2: val = dv[row]*acc; write Cf (fp32 u) AND Chi (fp16 seed); col<Nd guard.  aux = dvec.
// EPI=0: fp32 out, col<Nd guard.
template<int EPI, int TWOA>
__global__ __launch_bounds__(256, 2)
void k_gemm_h(const __half* __restrict__ Ahi, const __half* __restrict__ Alo, int lda,
              const __half* __restrict__ Bh, int ldb,
              const float* __restrict__ aux,
              float* __restrict__ Cf, __half* __restrict__ Chi,
              int ldc, int Nd, int K) {
    extern __shared__ __half smh[];
    __half* sAh = smh;
    __half* sAl = sAh + 2 * ABUF;                       // only used when TWOA
    __half* sBh = TWOA ? (sAl + 2 * ABUF) : (sAh + 2 * ABUF);

    const int tid = threadIdx.x;
    const int wid = tid >> 5, lane = tid & 31;
    const int wm = (wid & 1) * 64;
    const int wn = (wid >> 1) * 32;
    const int m0 = blockIdx.y * TBM, n0 = blockIdx.x * TBN;

    const int a_r = tid >> 2;
    const int a_c = (tid & 3) << 3;
    const int b_r = tid >> 4;
    const int b_c = (tid & 15) << 3;
    const bool pb = (n0 + b_c) < Nd;

    const __half* gAh0 = Ahi + (size_t)(m0 + a_r) * lda + a_c;
    const __half* gAh1 = Ahi + (size_t)(m0 + a_r + 64) * lda + a_c;
    const __half* gAl0 = TWOA ? (Alo + (size_t)(m0 + a_r) * lda + a_c) : (const __half*)0;
    const __half* gAl1 = TWOA ? (Alo + (size_t)(m0 + a_r + 64) * lda + a_c) : (const __half*)0;
    const __half* gB0  = Bh + (size_t)b_r * ldb + n0 + b_c;
    const __half* gB1  = Bh + (size_t)(b_r + 16) * ldb + n0 + b_c;

    float acc[4][4][4];
    #pragma unroll
    for (int i = 0; i < 4; ++i)
        #pragma unroll
        for (int j = 0; j < 4; ++j)
            #pragma unroll
            for (int q = 0; q < 4; ++q) acc[i][j][q] = 0.f;

    const int KT = K / TBK;

    cpasync16(sAh + a_r * ASTR + a_c, gAh0, true);
    cpasync16(sAh + (a_r + 64) * ASTR + a_c, gAh1, true);
    if (TWOA) {
        cpasync16(sAl + a_r * ASTR + a_c, gAl0, true);
        cpasync16(sAl + (a_r + 64) * ASTR + a_c, gAl1, true);
    }
    cpasync16(sBh + b_r * BSTR + b_c, gB0, pb);
    cpasync16(sBh + (b_r + 16) * BSTR + b_c, gB1, pb);
    cp_commit();

    const int l16 = lane & 15;
    const int hsel = (lane >> 4) << 3;
    const int bg = lane >> 3, bl8 = lane & 7;
    const int bkoff = ((bg & 1) << 3) + bl8;
    const int bnoff = wn + ((bg >> 1) << 3);

    int buf = 0;
    for (int kt = 0; kt < KT; ++kt) {
        if (kt + 1 < KT) {
            int ko = (kt + 1) * TBK;
            int ob = (buf ^ 1);
            cpasync16(sAh + ob * ABUF + a_r * ASTR + a_c, gAh0 + ko, true);
            cpasync16(sAh + ob * ABUF + (a_r + 64) * ASTR + a_c, gAh1 + ko, true);
            if (TWOA) {
                cpasync16(sAl + ob * ABUF + a_r * ASTR + a_c, gAl0 + ko, true);
                cpasync16(sAl + ob * ABUF + (a_r + 64) * ASTR + a_c, gAl1 + ko, true);
            }
            cpasync16(sBh + ob * BBUF + b_r * BSTR + b_c, gB0 + (size_t)ko * ldb, pb);
            cpasync16(sBh + ob * BBUF + (b_r + 16) * BSTR + b_c, gB1 + (size_t)ko * ldb, pb);
            cp_commit();
            cp_wait1();
        } else {
            cp_wait0();
        }
        __syncthreads();

        #pragma unroll
        for (int ks = 0; ks < 2; ++ks) {
            const int ko = ks * 16;
            unsigned bh[8];
            {
                unsigned ab = sptr(sBh + buf * BBUF + (ko + bkoff) * BSTR + bnoff);
                ldsm4t(bh[0], bh[1], bh[2], bh[3], ab);
                ldsm4t(bh[4], bh[5], bh[6], bh[7], ab + 32);
            }
            #pragma unroll
            for (int mi = 0; mi < 4; ++mi) {
                unsigned ah[4];
                unsigned aa = sptr(sAh + buf * ABUF + (wm + mi * 16 + l16) * ASTR + ko + hsel);
                ldsm4(ah[0], ah[1], ah[2], ah[3], aa);
                unsigned alr[4];
                if (TWOA) {
                    unsigned aal = sptr(sAl + buf * ABUF + (wm + mi * 16 + l16) * ASTR + ko + hsel);
                    ldsm4(alr[0], alr[1], alr[2], alr[3], aal);
                }
                #pragma unroll
                for (int nj = 0; nj < 4; ++nj) {
                    int bi = (nj >> 1) * 4 + (nj & 1) * 2;
                    mma16816h(acc[mi][nj], ah, bh[bi], bh[bi + 1]);
                    if (TWOA) mma16816h(acc[mi][nj], alr, bh[bi], bh[bi + 1]);
                }
            }
        }
        __syncthreads();
        buf ^= 1;
    }

    const int er = lane >> 2;
    const int ec = (lane & 3) << 1;
    #pragma unroll
    for (int mi = 0; mi < 4; ++mi) {
        #pragma unroll
        for (int nj = 0; nj < 4; ++nj) {
            int row = m0 + wm + mi * 16 + er;
            int col = n0 + wn + nj * 8 + ec;
            float* a = acc[mi][nj];
            if (EPI == 1) {
                float bv0 = aux[col], bv1 = aux[col + 1];
                #pragma unroll
                for (int h = 0; h < 2; ++h) {
                    int r = row + h * 8;
                    float v0 = fmaxf(a[h * 2 + 0] + bv0, 0.f);
                    float v1 = fmaxf(a[h * 2 + 1] + bv1, 0.f);
                    *reinterpret_cast<__half2*>(&Chi[(size_t)r * Nd + col]) = __floats2half2_rn(v0, v1);
                }
            } else if (EPI == 2) {
                if (col < Nd) {    // guard: grid.x overshoots Nd by one partial tile
                    #pragma unroll
                    for (int h = 0; h < 2; ++h) {
                        int r = row + h * 8;
                        float dv = __ldg(&aux[r]);
                        float v0 = dv * a[h * 2 + 0];
                        float v1 = dv * a[h * 2 + 1];
                        *reinterpret_cast<float2*>(&Cf[(size_t)r * ldc + col]) = make_float2(v0, v1);
                        *reinterpret_cast<__half2*>(&Chi[(size_t)r * Nd + col]) = __floats2half2_rn(v0, v1);
                    }
                }
            } else {
                if (col < Nd) {
                    *reinterpret_cast<float2*>(&Cf[(size_t)row * ldc + col]) = make_float2(a[0], a[1]);
                    *reinterpret_cast<float2*>(&Cf[(size_t)(row + 8) * ldc + col]) = make_float2(a[2], a[3]);
                }
            }
        }
    }
}

// ---------------- fp32 GEMM (tiny GEMM3, split-K) ----------------
#define BM 128
#define BK 16

template<int BN_, int TN_>
__global__ __launch_bounds__(256)
void k_gemm(const float* __restrict__ A, int lda,
            const float* __restrict__ B, int ldb,
            float* __restrict__ Cout, int ldc,
            int Nd, int Kloop, int partStride) {
    __shared__ float As[2][BM][BK];
    __shared__ float Bs[2][BK][BN_];

    const int tid = threadIdx.x;
    const int tx = tid & 15;
    const int ty = tid >> 4;
    const int m0 = blockIdx.y * BM;
    const int n0 = blockIdx.x * BN_;

    A += (size_t)blockIdx.z * Kloop;
    B += (size_t)blockIdx.z * Kloop * ldb;
    Cout += (size_t)blockIdx.z * partStride;

    const int arow0 = tid >> 2;
    const int arow1 = arow0 + 64;
    const int ac4 = (tid & 3) * 4;
    const float* gA0 = A + (size_t)(m0 + arow0) * lda + ac4;
    const float* gA1 = A + (size_t)(m0 + arow1) * lda + ac4;

    const int BQ = BN_ / 4;
    const int bkr0 = tid / BQ;
    const int bc0 = (tid % BQ) * 4;
    const float* gB0 = B + (size_t)bkr0 * ldb + n0 + bc0;
    const bool bp0 = (n0 + bc0) < Nd;

    float acc[8][TN_];
    #pragma unroll
    for (int i = 0; i < 8; ++i)
        #pragma unroll
        for (int j = 0; j < TN_; ++j) acc[i][j] = 0.f;

    const int KT = Kloop / BK;

    cpasync16(&As[0][arow0][ac4], gA0, true);
    cpasync16(&As[0][arow1][ac4], gA1, true);
    cpasync16(&Bs[0][bkr0][bc0], gB0, bp0);
    cp_commit();

    int buf = 0;
    for (int kt = 0; kt < KT; ++kt) {
        if (kt + 1 < KT) {
            int ko = (kt + 1) * BK;
            cpasync16(&As[buf ^ 1][arow0][ac4], gA0 + ko, true);
            cpasync16(&As[buf ^ 1][arow1][ac4], gA1 + ko, true);
            cpasync16(&Bs[buf ^ 1][bkr0][bc0], gB0 + (size_t)ko * ldb, bp0);
            cp_commit();
            cp_wait1();
        } else {
            cp_wait0();
        }
        __syncthreads();

        #pragma unroll
        for (int k = 0; k < BK; ++k) {
            float a[8];
            #pragma unroll
            for (int i = 0; i < 8; ++i) a[i] = As[buf][ty * 8 + i][k];
            float b[TN_];
            #pragma unroll
            for (int j = 0; j < TN_; j += 4) {
                float4 v = *reinterpret_cast<const float4*>(&Bs[buf][k][tx * TN_ + j]);
                b[j] = v.x; b[j + 1] = v.y; b[j + 2] = v.z; b[j + 3] = v.w;
            }
            #pragma unroll
            for (int i = 0; i < 8; ++i)
                #pragma unroll
                for (int j = 0; j < TN_; ++j)
                    acc[i][j] += a[i] * b[j];
        }
        __syncthreads();
        buf ^= 1;
    }

    #pragma unroll
    for (int i = 0; i < 8; ++i) {
        int m = m0 + ty * 8 + i;
        #pragma unroll
        for (int j = 0; j < TN_; j += 4) {
            int n = n0 + tx * TN_ + j;
            if (n < Nd) {
                float4 v = make_float4(acc[i][j], acc[i][j + 1], acc[i][j + 2], acc[i][j + 3]);
                *reinterpret_cast<float4*>(&Cout[(size_t)m * ldc + n]) = v;
            }
        }
    }
}

// ---------------- host orchestration ----------------
static float* run_prop_s(const int* nbr, const int* cnt, const float* dvec,
                         const float* feat, const float* w, int C,
                         float* u, float* va, float* vb) {
    int total = NN * C;
    k_scale_u<<<(total + 255) / 256, 256>>>(feat, dvec, u, va, C);
    float* vin = va;
    float* vout = vb;
    for (int k = 5; k >= 1; --k) {
        if (C == C_IN) k_spmm_s<32><<<NN / 8, 256>>>(nbr, cnt, vin, u, vout, w, k, C);
        else           k_spmm_s<8><<<NN / 32, 256>>>(nbr, cnt, vin, u, vout, w, k, C);
        float* t = vin; vin = vout; vout = t;
    }
    return vin;
}

extern "C" void kernel_launch(void* const* d_in, const int* in_sizes, int n_in,
                              void* d_out, int out_size) {
    const float* x  = (const float*)d_in[0];
    const int*   ei = (const int*)  d_in[1];
    const float* w1 = (const float*)d_in[2];
    const float* w2 = (const float*)d_in[3];
    const float* w3 = (const float*)d_in[4];
    const float* W1 = (const float*)d_in[5];
    const float* b1 = (const float*)d_in[6];
    const float* W2 = (const float*)d_in[7];
    const float* b2 = (const float*)d_in[8];
    const float* W3 = (const float*)d_in[9];
    const float* b3 = (const float*)d_in[10];
    float* out = (float*)d_out;

    unsigned *adj, *rA, *rB;
    int *nbr, *cnt;
    float *dvec, *u, *va, *vb, *h2, *g3, *g3p;
    __half *vha, *vhb, *zhi, *zlo, *w1h, *w2h, *h1h;
    cudaGetSymbolAddress((void**)&adj,  g_adj);
    cudaGetSymbolAddress((void**)&rA,   g_rA);
    cudaGetSymbolAddress((void**)&rB,   g_rB);
    cudaGetSymbolAddress((void**)&nbr,  g_nbr);
    cudaGetSymbolAddress((void**)&cnt,  g_cnt);
    cudaGetSymbolAddress((void**)&dvec, g_dvec);
    cudaGetSymbolAddress((void**)&u,    g_u);
    cudaGetSymbolAddress((void**)&va,   g_va);
    cudaGetSymbolAddress((void**)&vb,   g_vb);
    cudaGetSymbolAddress((void**)&h2,   g_h2);
    cudaGetSymbolAddress((void**)&g3,   g_g3);
    cudaGetSymbolAddress((void**)&g3p,  g_g3p);
    cudaGetSymbolAddress((void**)&vha,  g_vha);
    cudaGetSymbolAddress((void**)&vhb,  g_vhb);
    cudaGetSymbolAddress((void**)&zhi,  g_zhi);
    cudaGetSymbolAddress((void**)&zlo,  g_zlo);
    cudaGetSymbolAddress((void**)&w1h,  g_w1h);
    cudaGetSymbolAddress((void**)&w2h,  g_w2h);
    cudaGetSymbolAddress((void**)&h1h,  g_h1h);

    cudaFuncSetAttribute((const void*)k_gemm_h<1, 1>, cudaFuncAttributeMaxDynamicSharedMemorySize, SMEM_BYTES_2A);
    cudaFuncSetAttribute((const void*)k_gemm_h<2, 0>, cudaFuncAttributeMaxDynamicSharedMemorySize, SMEM_BYTES_1A);

    // ---- adjacency + neighbor lists + reach + deg ----
    k_zero_u32<<<(NN * WORDS + 255) / 256, 256>>>(adj, NN * WORDS);
    k_build_adj<<<EE / 256, 256>>>(ei, adj);
    k_build_list<<<NN / 256, 256>>>(adj, nbr, cnt);
    k_reach_init<<<(NN * WORDS + 255) / 256, 256>>>(adj, rA);
    k_reach_iter<<<NN, 64>>>(nbr, cnt, rA, rB);
    k_reach_iter<<<NN, 64>>>(nbr, cnt, rB, rA);
    k_reach_iter<<<NN, 64>>>(nbr, cnt, rA, rB);
    k_reach_iter<<<NN, 64>>>(nbr, cnt, rB, rA);
    k_deg<<<(NN + 255) / 256, 256>>>(rA, dvec);

    // weight conversions (independent; issue early)
    k_tohalf<<<(C_IN * H1D + 255) / 256, 256>>>(W1, w1h, C_IN * H1D);
    k_tohalf<<<(H1D * H2D + 255) / 256, 256>>>(W2, w2h, H1D * H2D);

    // ---- layer 1: h1 = relu((M1_hat x) W1 + b1), single-fp16 output ----
    {
        float* v = run_prop_s(nbr, cnt, dvec, x, w1, C_IN, u, va, vb);
        k_scale_split<<<(NN * C_IN + 255) / 256, 256>>>(v, dvec, w1, zhi, zlo, C_IN);
        dim3 grid(H1D / TBN, NN / TBM, 1);
        k_gemm_h<1, 1><<<grid, 256, SMEM_BYTES_2A>>>(zhi, zlo, C_IN, w1h, H1D,
                                                     b1, (float*)0, h1h, H1D, H1D, C_IN);
    }

    // ---- layer 2: h2 = relu(M2_hat (h1 W2) + b2) ----
    // Single-A fp16 GEMM; epilogue writes u (fp32) + vha (fp16 seed). All 5
    // hops fp16; hop 1 fuses w0*d*. + bias + relu and writes h2 directly.
    {
        dim3 grid((H2D + TBN - 1) / TBN, NN / TBM, 1);
        k_gemm_h<2, 0><<<grid, 256, SMEM_BYTES_1A>>>(h1h, (const __half*)0, H1D, w2h, H2D,
                                                     dvec, u, vha, H2D, H2D, H1D);
        k_spmm_h<0><<<NN, 256>>>(nbr, cnt, vha, u, vhb, (float*)0, w2, 5, H2D, (float*)0, (float*)0);
        k_spmm_h<0><<<NN, 256>>>(nbr, cnt, vhb, u, vha, (float*)0, w2, 4, H2D, (float*)0, (float*)0);
        k_spmm_h<0><<<NN, 256>>>(nbr, cnt, vha, u, vhb, (float*)0, w2, 3, H2D, (float*)0, (float*)0);
        k_spmm_h<0><<<NN, 256>>>(nbr, cnt, vhb, u, vha, (float*)0, w2, 2, H2D, (float*)0, (float*)0);
        k_spmm_h<1><<<NN, 256>>>(nbr, cnt, vha, u, (__half*)0, h2, w2, 1, H2D, dvec, b2);
    }

    // ---- layer 3: out = relu(M3_hat (h2 W3) + b3), fp32 split-K GEMM ----
    {
        dim3 grid(1, NN / BM, SK3);
        k_gemm<64, 4><<<grid, 256>>>(h2, H2D, W3, ODIM, g3p, ODIM, ODIM, H2D / SK3, NN * ODIM);
        k_reduce_sk<<<(NN * ODIM + 255) / 256, 256>>>(g3p, g3, NN * ODIM);
        float* v = run_prop_s(nbr, cnt, dvec, g3, w3, ODIM, u, va, vb);
        k_final<<<(NN * ODIM + 255) / 256, 256>>>(v, dvec, w3, b3, out, ODIM);
    }
}

// round 12
// speedup vs baseline: 3.3731x; 1.0995x over previous
#include <cuda_runtime.h>
#include <cuda_fp16.h>

#define NN 2048
#define EE 65536
#define WORDS 64
#define NBMAX 2048
#define C_IN 128
#define H1D 3200
#define H2D 1600
#define ODIM 32
#define SK3 4

// ---------------- scratch (device globals) ----------------
__device__ unsigned g_adj[NN * WORDS];
__device__ unsigned g_rA [NN * WORDS];
__device__ unsigned g_rB [NN * WORDS];
__device__ int      g_nbr[(size_t)NN * NBMAX];
__device__ int      g_cnt[NN];
__device__ float    g_dvec[NN];
__device__ float    g_u  [NN * H2D];
__device__ float    g_va [NN * H2D];
__device__ float    g_vb [NN * H2D];
__device__ float    g_h2 [NN * H2D];
__device__ float    g_g3 [NN * ODIM];
__device__ float    g_g3p[SK3 * NN * ODIM];
// fp16 operands / iterates
__device__ __half g_vha[NN * H2D], g_vhb[NN * H2D];
__device__ __half g_zhi[NN * C_IN],  g_zlo[NN * C_IN];
__device__ __half g_w1h[C_IN * H1D];
__device__ __half g_w2h[H1D * H2D];
__device__ __half g_h1h[(size_t)NN * H1D];

// ---------------- utility kernels ----------------
__global__ void k_zero_u32(unsigned* p, int n) {
    int i = blockIdx.x * blockDim.x + threadIdx.x;
    if (i < n) p[i] = 0u;
}

__global__ void k_build_adj(const int* __restrict__ ei, unsigned* __restrict__ adj) {
    int e = blockIdx.x * blockDim.x + threadIdx.x;
    if (e < EE) {
        int src = ei[e];
        int dst = ei[EE + e];
        atomicOr(&adj[dst * WORDS + (src >> 5)], 1u << (src & 31));
    }
}

// Warp-per-row: build sorted neighbor list + write reach seed R = adj | diag.
// 8 warps/block, grid = NN/8.  Lane L owns words L and L+32.
__global__ __launch_bounds__(256)
void k_build_fused(const unsigned* __restrict__ adj,
                   int* __restrict__ nbr, int* __restrict__ cnt,
                   unsigned* __restrict__ R) {
    int warp = threadIdx.x >> 5;
    int lane = threadIdx.x & 31;
    int u = blockIdx.x * 8 + warp;
    const unsigned* row = adj + u * WORDS;
    unsigned w0 = row[lane];
    unsigned w1 = row[lane + 32];
    int dw = u >> 5;
    unsigned db = 1u << (u & 31);
    R[u * WORDS + lane]      = (dw == lane)      ? (w0 | db) : w0;
    R[u * WORDS + lane + 32] = (dw == lane + 32) ? (w1 | db) : w1;

    int c0 = __popc(w0), c1 = __popc(w1);
    int s0 = c0, s1 = c1;
    #pragma unroll
    for (int off = 1; off < 32; off <<= 1) {
        int t0 = __shfl_up_sync(0xffffffffu, s0, off);
        int t1 = __shfl_up_sync(0xffffffffu, s1, off);
        if (lane >= off) { s0 += t0; s1 += t1; }
    }
    int total_low = __shfl_sync(0xffffffffu, s0, 31);
    int total     = total_low + __shfl_sync(0xffffffffu, s1, 31);
    if (lane == 0) cnt[u] = total;   // row has <= 2048 bits, never exceeds NBMAX

    int* out = nbr + (size_t)u * NBMAX;
    int o = s0 - c0;                 // exclusive prefix for word `lane`
    unsigned bits = w0;
    while (bits) {
        int b = __ffs(bits) - 1;
        bits &= bits - 1;
        out[o++] = lane * 32 + b;
    }
    o = total_low + s1 - c1;         // exclusive prefix for word `lane+32`
    bits = w1;
    while (bits) {
        int b = __ffs(bits) - 1;
        bits &= bits - 1;
        out[o++] = (lane + 32) * 32 + b;
    }
}

// DEG=0: Rnew[u] = I_u | OR_{v in nbr(u)} Rold[v].
// DEG=1: final iteration — skip Rnew store; d[u] = popcount(row)^-1/2.
template <int DEG>
__global__ void k_reach_iter(const int* __restrict__ nbr, const int* __restrict__ cnt,
                             const unsigned* __restrict__ Rold, unsigned* __restrict__ Rnew,
                             float* __restrict__ d) {
    __shared__ int sred[64];
    int u = blockIdx.x;
    int w = threadIdx.x;
    int n = __ldg(&cnt[u]);
    const int* list = nbr + (size_t)u * NBMAX;
    unsigned acc = ((u >> 5) == w) ? (1u << (u & 31)) : 0u;
    int j = 0;
    for (; j + 4 <= n; j += 4) {
        int v0 = __ldg(list + j + 0), v1 = __ldg(list + j + 1);
        int v2 = __ldg(list + j + 2), v3 = __ldg(list + j + 3);
        unsigned r0 = Rold[v0 * WORDS + w];
        unsigned r1 = Rold[v1 * WORDS + w];
        unsigned r2 = Rold[v2 * WORDS + w];
        unsigned r3 = Rold[v3 * WORDS + w];
        acc |= (r0 | r1) | (r2 | r3);
    }
    for (; j < n; ++j) acc |= Rold[__ldg(list + j) * WORDS + w];
    if (DEG == 0) {
        Rnew[u * WORDS + w] = acc;
    } else {
        sred[w] = __popc(acc);
        __syncthreads();
        if (w < 32) {
            int v = sred[w] + sred[w + 32];
            #pragma unroll
            for (int off = 16; off > 0; off >>= 1)
                v += __shfl_down_sync(0xffffffffu, v, off);
            if (w == 0) d[u] = (v > 0) ? rsqrtf((float)v) : 0.0f;
        }
    }
}

// ---- SpMM large C, fp16 gather.  MODE 0: fp16 iterate out.
//      MODE 1: final fused epilogue, fp32 out = relu(w0*d*(u+wk*acc)+bias). ----
template <int MODE>
__global__ __launch_bounds__(256)
void k_spmm_h(const int* __restrict__ nbr, const int* __restrict__ cnt,
              const __half* __restrict__ vin, const float* __restrict__ uvec,
              __half* __restrict__ vout16, float* __restrict__ vout32,
              const float* __restrict__ wvec, int widx, int C,
              const float* __restrict__ dvec, const float* __restrict__ bias) {
    int u = blockIdx.x;
    int t = threadIdx.x;
    const int L = C >> 3;
    if (t >= L) return;
    int n = __ldg(&cnt[u]);
    const int* list = nbr + (size_t)u * NBMAX;
    float wk = __ldg(&wvec[widx]);

    float acc[8];
    #pragma unroll
    for (int q = 0; q < 8; ++q) acc[q] = 0.f;

    int j = 0;
    for (; j + 4 <= n; j += 4) {
        int v0 = __ldg(list + j + 0), v1 = __ldg(list + j + 1);
        int v2 = __ldg(list + j + 2), v3 = __ldg(list + j + 3);
        uint4 x0 = __ldg(reinterpret_cast<const uint4*>(vin + (size_t)v0 * C) + t);
        uint4 x1 = __ldg(reinterpret_cast<const uint4*>(vin + (size_t)v1 * C) + t);
        uint4 x2 = __ldg(reinterpret_cast<const uint4*>(vin + (size_t)v2 * C) + t);
        uint4 x3 = __ldg(reinterpret_cast<const uint4*>(vin + (size_t)v3 * C) + t);
        const __half2* h0 = reinterpret_cast<const __half2*>(&x0);
        const __half2* h1 = reinterpret_cast<const __half2*>(&x1);
        const __half2* h2 = reinterpret_cast<const __half2*>(&x2);
        const __half2* h3 = reinterpret_cast<const __half2*>(&x3);
        #pragma unroll
        for (int q = 0; q < 4; ++q) {
            float2 f0 = __half22float2(h0[q]);
            float2 f1 = __half22float2(h1[q]);
            float2 f2 = __half22float2(h2[q]);
            float2 f3 = __half22float2(h3[q]);
            acc[2 * q + 0] += (f0.x + f1.x) + (f2.x + f3.x);
            acc[2 * q + 1] += (f0.y + f1.y) + (f2.y + f3.y);
        }
    }
    for (; j < n; ++j) {
        int v = __ldg(list + j);
        uint4 x = __ldg(reinterpret_cast<const uint4*>(vin + (size_t)v * C) + t);
        const __half2* h = reinterpret_cast<const __half2*>(&x);
        #pragma unroll
        for (int q = 0; q < 4; ++q) {
            float2 f = __half22float2(h[q]);
            acc[2 * q + 0] += f.x;
            acc[2 * q + 1] += f.y;
        }
    }

    size_t base = (size_t)u * C + t * 8;
    float4 u0 = *reinterpret_cast<const float4*>(uvec + base);
    float4 u1 = *reinterpret_cast<const float4*>(uvec + base + 4);
    float o[8];
    o[0] = u0.x + wk * acc[0]; o[1] = u0.y + wk * acc[1];
    o[2] = u0.z + wk * acc[2]; o[3] = u0.w + wk * acc[3];
    o[4] = u1.x + wk * acc[4]; o[5] = u1.y + wk * acc[5];
    o[6] = u1.z + wk * acc[6]; o[7] = u1.w + wk * acc[7];
    if (MODE == 0) {
        __half2 hp[4];
        #pragma unroll
        for (int q = 0; q < 4; ++q)
            hp[q] = __floats2half2_rn(o[2 * q], o[2 * q + 1]);
        *(reinterpret_cast<uint4*>(vout16 + base)) = *reinterpret_cast<uint4*>(hp);
    } else {
        float w0d = __ldg(&wvec[0]) * __ldg(&dvec[u]);
        int cb = t * 8;
        float4 b0 = *reinterpret_cast<const float4*>(bias + cb);
        float4 b1 = *reinterpret_cast<const float4*>(bias + cb + 4);
        float r[8];
        r[0] = fmaxf(w0d * o[0] + b0.x, 0.f); r[1] = fmaxf(w0d * o[1] + b0.y, 0.f);
        r[2] = fmaxf(w0d * o[2] + b0.z, 0.f); r[3] = fmaxf(w0d * o[3] + b0.w, 0.f);
        r[4] = fmaxf(w0d * o[4] + b1.x, 0.f); r[5] = fmaxf(w0d * o[5] + b1.y, 0.f);
        r[6] = fmaxf(w0d * o[6] + b1.z, 0.f); r[7] = fmaxf(w0d * o[7] + b1.w, 0.f);
        *reinterpret_cast<float4*>(vout32 + base) = make_float4(r[0], r[1], r[2], r[3]);
        *reinterpret_cast<float4*>(vout32 + base + 4) = make_float4(r[4], r[5], r[6], r[7]);
    }
}

// ---- SpMM small C: LPR float4-lanes per row.
//      SEED=1: vin = raw feat; on-the-fly u = d.*feat (written to uvec). ----
template <int LPR, int SEED>
__global__ __launch_bounds__(256)
void k_spmm_s(const int* __restrict__ nbr, const int* __restrict__ cnt,
              const float* __restrict__ vin, float* __restrict__ uvec,
              float* __restrict__ vout,
              const float* __restrict__ wvec, int widx, int C,
              const float* __restrict__ dvec) {
    const int rpb = 256 / LPR;
    const int r = blockIdx.x * rpb + threadIdx.x / LPR;
    const int lane = threadIdx.x % LPR;
    int n = __ldg(&cnt[r]);
    const int* list = nbr + (size_t)r * NBMAX;
    float wk = __ldg(&wvec[widx]);

    float4 a0 = make_float4(0.f, 0.f, 0.f, 0.f);
    float4 a1 = make_float4(0.f, 0.f, 0.f, 0.f);
    float4 a2 = make_float4(0.f, 0.f, 0.f, 0.f);
    float4 a3 = make_float4(0.f, 0.f, 0.f, 0.f);

    int j = 0;
    for (; j + 4 <= n; j += 4) {
        int v0 = __ldg(list + j + 0), v1 = __ldg(list + j + 1);
        int v2 = __ldg(list + j + 2), v3 = __ldg(list + j + 3);
        float4 x0 = __ldg(reinterpret_cast<const float4*>(vin + (size_t)v0 * C) + lane);
        float4 x1 = __ldg(reinterpret_cast<const float4*>(vin + (size_t)v1 * C) + lane);
        float4 x2 = __ldg(reinterpret_cast<const float4*>(vin + (size_t)v2 * C) + lane);
        float4 x3 = __ldg(reinterpret_cast<const float4*>(vin + (size_t)v3 * C) + lane);
        if (SEED) {
            float d0 = __ldg(&dvec[v0]), d1 = __ldg(&dvec[v1]);
            float d2 = __ldg(&dvec[v2]), d3 = __ldg(&dvec[v3]);
            x0.x *= d0; x0.y *= d0; x0.z *= d0; x0.w *= d0;
            x1.x *= d1; x1.y *= d1; x1.z *= d1; x1.w *= d1;
            x2.x *= d2; x2.y *= d2; x2.z *= d2; x2.w *= d2;
            x3.x *= d3; x3.y *= d3; x3.z *= d3; x3.w *= d3;
        }
        a0.x += x0.x; a0.y += x0.y; a0.z += x0.z; a0.w += x0.w;
        a1.x += x1.x; a1.y += x1.y; a1.z += x1.z; a1.w += x1.w;
        a2.x += x2.x; a2.y += x2.y; a2.z += x2.z; a2.w += x2.w;
        a3.x += x3.x; a3.y += x3.y; a3.z += x3.z; a3.w += x3.w;
    }
    for (; j < n; ++j) {
        int v = __ldg(list + j);
        float4 x = __ldg(reinterpret_cast<const float4*>(vin + (size_t)v * C) + lane);
        if (SEED) {
            float dd = __ldg(&dvec[v]);
            x.x *= dd; x.y *= dd; x.z *= dd; x.w *= dd;
        }
        a0.x += x.x; a0.y += x.y; a0.z += x.z; a0.w += x.w;
    }
    float4 s;
    s.x = (a0.x + a1.x) + (a2.x + a3.x);
    s.y = (a0.y + a1.y) + (a2.y + a3.y);
    s.z = (a0.z + a1.z) + (a2.z + a3.z);
    s.w = (a0.w + a1.w) + (a2.w + a3.w);

    float4 uu;
    if (SEED) {
        float dr = __ldg(&dvec[r]);
        uu = *(reinterpret_cast<const float4*>(vin + (size_t)r * C) + lane);
        uu.x *= dr; uu.y *= dr; uu.z *= dr; uu.w *= dr;
        *(reinterpret_cast<float4*>(uvec + (size_t)r * C) + lane) = uu;  // materialize u
    } else {
        uu = *(reinterpret_cast<const float4*>(uvec + (size_t)r * C) + lane);
    }
    float4 o;
    o.x = uu.x + wk * s.x;
    o.y = uu.y + wk * s.y;
    o.z = uu.z + wk * s.z;
    o.w = uu.w + wk * s.w;
    *(reinterpret_cast<float4*>(vout + (size_t)r * C) + lane) = o;
}

// fused: z = w0*d*v, split to fp16 hi/lo (layer-1 pre-GEMM)
__global__ void k_scale_split(const float* __restrict__ v, const float* __restrict__ d,
                              const float* __restrict__ wvec,
                              __half* __restrict__ hi, __half* __restrict__ lo, int C) {
    int i = blockIdx.x * blockDim.x + threadIdx.x;
    if (i < NN * C) {
        float x = wvec[0] * d[i / C] * v[i];
        __half h = __float2half_rn(x);
        hi[i] = h;
        lo[i] = __float2half_rn(x - __half2float(h));
    }
}

__global__ void k_final(const float* __restrict__ v, const float* __restrict__ d,
                        const float* __restrict__ wvec, const float* __restrict__ bias,
                        float* __restrict__ out, int C) {
    int i = blockIdx.x * blockDim.x + threadIdx.x;
    if (i < NN * C) {
        float val = wvec[0] * d[i / C] * v[i] + bias[i % C];
        out[i] = fmaxf(val, 0.0f);
    }
}

__global__ void k_reduce_sk(const float* __restrict__ p, float* __restrict__ out, int n) {
    int i = blockIdx.x * blockDim.x + threadIdx.x;
    if (i < n) {
        float s = 0.f;
        #pragma unroll
        for (int k = 0; k < SK3; ++k) s += p[(size_t)k * n + i];
        out[i] = s;
    }
}

// single launch converting both weight matrices
__global__ void k_tohalf2(const float* __restrict__ s1, __half* __restrict__ d1, int n1,
                          const float* __restrict__ s2, __half* __restrict__ d2, int n2) {
    int i = blockIdx.x * blockDim.x + threadIdx.x;
    if (i < n1) d1[i] = __float2half_rn(s1[i]);
    else {
        int j = i - n1;
        if (j < n2) d2[j] = __float2half_rn(s2[j]);
    }
}

// ---------------- cp.async helpers ----------------
__device__ __forceinline__ void cpasync16(void* s, const void* g, bool p) {
    unsigned sa = (unsigned)__cvta_generic_to_shared(s);
    asm volatile("cp.async.cg.shared.global [%0], [%1], 16, %2;"
                 :: "r"(sa), "l"(g), "r"(p ? 16 : 0));
}
__device__ __forceinline__ void cp_commit() { asm volatile("cp.async.commit_group;" ::: "memory"); }
__device__ __forceinline__ void cp_wait0()  { asm volatile("cp.async.wait_group 0;" ::: "memory"); }
__device__ __forceinline__ void cp_wait1()  { asm volatile("cp.async.wait_group 1;" ::: "memory"); }

// ---------------- fp16 tensor-core GEMM ----------------
#define TBM 128
#define TBN 128
#define TBK 32
#define ASTR 40
#define BSTR 136
#define ABUF (TBM * ASTR)
#define BBUF (TBK * BSTR)
#define SMEM_BYTES_2A ((4 * ABUF + 2 * BBUF) * 2)
#define SMEM_BYTES_1A ((2 * ABUF + 2 * BBUF) * 2)

__device__ __forceinline__ unsigned sptr(const void* p) {
    return (unsigned)__cvta_generic_to_shared(p);
}
__device__ __forceinline__ void ldsm4(unsigned& r0, unsigned& r1, unsigned& r2, unsigned& r3, unsigned a) {
    asm volatile("ldmatrix.sync.aligned.m8n8.x4.shared.b16 {%0,%1,%2,%3}, [%4];"
                 : "=r"(r0), "=r"(r1), "=r"(r2), "=r"(r3) : "r"(a));
}
__device__ __forceinline__ void ldsm4t(unsigned& r0, unsigned& r1, unsigned& r2, unsigned& r3, unsigned a) {
    asm volatile("ldmatrix.sync.aligned.m8n8.x4.trans.shared.b16 {%0,%1,%2,%3}, [%4];"
                 : "=r"(r0), "=r"(r1), "=r"(r2), "=r"(r3) : "r"(a));
}
__device__ __forceinline__ void mma16816h(float* c, const unsigned* a, unsigned b0, unsigned b1) {
    asm volatile("mma.sync.aligned.m16n8k16.row.col.f32.f16.f16.f32 "
                 "{%0,%1,%2,%3},{%4,%5,%6,%7},{%8,%9},{%0,%1,%2,%3};"
                 : "+f"(c[0]), "+f"(c[1]), "+f"(c[2]), "+f"(c[3])
                 : "r"(a[0]), "r"(a[1]), "r"(a[2]), "r"(a[3]), "r"(b0), "r"(b1));
}

// TWOA=1: D = (Ahi + Alo) * B.  TWOA=0: D = Ahi * B.
// EPI=1: +bias, relu, write single fp16 Chi.
// EPI=2: val = dv[row]*acc; write Cf (fp32 u) AND Chi (fp16 seed); col<Nd guard.  aux = dvec.
// EPI=0: fp32 out, col<Nd guard.
template<int EPI, int TWOA>
__global__ __launch_bounds__(256, 2)
void k_gemm_h(const __half* __restrict__ Ahi, const __half* __restrict__ Alo, int lda,
              const __half* __restrict__ Bh, int ldb,
              const float* __restrict__ aux,
              float* __restrict__ Cf, __half* __restrict__ Chi,
              int ldc, int Nd, int K) {
    extern __shared__ __half smh[];
    __half* sAh = smh;
    __half* sAl = sAh + 2 * ABUF;
    __half* sBh = TWOA ? (sAl + 2 * ABUF) : (sAh + 2 * ABUF);

    const int tid = threadIdx.x;
    const int wid = tid >> 5, lane = tid & 31;
    const int wm = (wid & 1) * 64;
    const int wn = (wid >> 1) * 32;
    const int m0 = blockIdx.y * TBM, n0 = blockIdx.x * TBN;

    const int a_r = tid >> 2;
    const int a_c = (tid & 3) << 3;
    const int b_r = tid >> 4;
    const int b_c = (tid & 15) << 3;
    const bool pb = (n0 + b_c) < Nd;

    const __half* gAh0 = Ahi + (size_t)(m0 + a_r) * lda + a_c;
    const __half* gAh1 = Ahi + (size_t)(m0 + a_r + 64) * lda + a_c;
    const __half* gAl0 = TWOA ? (Alo + (size_t)(m0 + a_r) * lda + a_c) : (const __half*)0;
    const __half* gAl1 = TWOA ? (Alo + (size_t)(m0 + a_r + 64) * lda + a_c) : (const __half*)0;
    const __half* gB0  = Bh + (size_t)b_r * ldb + n0 + b_c;
    const __half* gB1  = Bh + (size_t)(b_r + 16) * ldb + n0 + b_c;

    float acc[4][4][4];
    #pragma unroll
    for (int i = 0; i < 4; ++i)
        #pragma unroll
        for (int j = 0; j < 4; ++j)
            #pragma unroll
            for (int q = 0; q < 4; ++q) acc[i][j][q] = 0.f;

    const int KT = K / TBK;

    cpasync16(sAh + a_r * ASTR + a_c, gAh0, true);
    cpasync16(sAh + (a_r + 64) * ASTR + a_c, gAh1, true);
    if (TWOA) {
        cpasync16(sAl + a_r * ASTR + a_c, gAl0, true);
        cpasync16(sAl + (a_r + 64) * ASTR + a_c, gAl1, true);
    }
    cpasync16(sBh + b_r * BSTR + b_c, gB0, pb);
    cpasync16(sBh + (b_r + 16) * BSTR + b_c, gB1, pb);
    cp_commit();

    const int l16 = lane & 15;
    const int hsel = (lane >> 4) << 3;
    const int bg = lane >> 3, bl8 = lane & 7;
    const int bkoff = ((bg & 1) << 3) + bl8;
    const int bnoff = wn + ((bg >> 1) << 3);

    int buf = 0;
    for (int kt = 0; kt < KT; ++kt) {
        if (kt + 1 < KT) {
            int ko = (kt + 1) * TBK;
            int ob = (buf ^ 1);
            cpasync16(sAh + ob * ABUF + a_r * ASTR + a_c, gAh0 + ko, true);
            cpasync16(sAh + ob * ABUF + (a_r + 64) * ASTR + a_c, gAh1 + ko, true);
            if (TWOA) {
                cpasync16(sAl + ob * ABUF + a_r * ASTR + a_c, gAl0 + ko, true);
                cpasync16(sAl + ob * ABUF + (a_r + 64) * ASTR + a_c, gAl1 + ko, true);
            }
            cpasync16(sBh + ob * BBUF + b_r * BSTR + b_c, gB0 + (size_t)ko * ldb, pb);
            cpasync16(sBh + ob * BBUF + (b_r + 16) * BSTR + b_c, gB1 + (size_t)ko * ldb, pb);
            cp_commit();
            cp_wait1();
        } else {
            cp_wait0();
        }
        __syncthreads();

        #pragma unroll
        for (int ks = 0; ks < 2; ++ks) {
            const int ko = ks * 16;
            unsigned bh[8];
            {
                unsigned ab = sptr(sBh + buf * BBUF + (ko + bkoff) * BSTR + bnoff);
                ldsm4t(bh[0], bh[1], bh[2], bh[3], ab);
                ldsm4t(bh[4], bh[5], bh[6], bh[7], ab + 32);
            }
            #pragma unroll
            for (int mi = 0; mi < 4; ++mi) {
                unsigned ah[4];
                unsigned aa = sptr(sAh + buf * ABUF + (wm + mi * 16 + l16) * ASTR + ko + hsel);
                ldsm4(ah[0], ah[1], ah[2], ah[3], aa);
                unsigned alr[4];
                if (TWOA) {
                    unsigned aal = sptr(sAl + buf * ABUF + (wm + mi * 16 + l16) * ASTR + ko + hsel);
                    ldsm4(alr[0], alr[1], alr[2], alr[3], aal);
                }
                #pragma unroll
                for (int nj = 0; nj < 4; ++nj) {
                    int bi = (nj >> 1) * 4 + (nj & 1) * 2;
                    mma16816h(acc[mi][nj], ah, bh[bi], bh[bi + 1]);
                    if (TWOA) mma16816h(acc[mi][nj], alr, bh[bi], bh[bi + 1]);
                }
            }
        }
        __syncthreads();
        buf ^= 1;
    }

    const int er = lane >> 2;
    const int ec = (lane & 3) << 1;
    #pragma unroll
    for (int mi = 0; mi < 4; ++mi) {
        #pragma unroll
        for (int nj = 0; nj < 4; ++nj) {
            int row = m0 + wm + mi * 16 + er;
            int col = n0 + wn + nj * 8 + ec;
            float* a = acc[mi][nj];
            if (EPI == 1) {
                float bv0 = aux[col], bv1 = aux[col + 1];
                #pragma unroll
                for (int h = 0; h < 2; ++h) {
                    int r = row + h * 8;
                    float v0 = fmaxf(a[h * 2 + 0] + bv0, 0.f);
                    float v1 = fmaxf(a[h * 2 + 1] + bv1, 0.f);
                    *reinterpret_cast<__half2*>(&Chi[(size_t)r * Nd + col]) = __floats2half2_rn(v0, v1);
                }
            } else if (EPI == 2) {
                if (col < Nd) {    // guard: grid.x overshoots Nd by one partial tile
                    #pragma unroll
                    for (int h = 0; h < 2; ++h) {
                        int r = row + h * 8;
                        float dv = __ldg(&aux[r]);
                        float v0 = dv * a[h * 2 + 0];
                        float v1 = dv * a[h * 2 + 1];
                        *reinterpret_cast<float2*>(&Cf[(size_t)r * ldc + col]) = make_float2(v0, v1);
                        *reinterpret_cast<__half2*>(&Chi[(size_t)r * Nd + col]) = __floats2half2_rn(v0, v1);
                    }
                }
            } else {
                if (col < Nd) {
                    *reinterpret_cast<float2*>(&Cf[(size_t)row * ldc + col]) = make_float2(a[0], a[1]);
                    *reinterpret_cast<float2*>(&Cf[(size_t)(row + 8) * ldc + col]) = make_float2(a[2], a[3]);
                }
            }
        }
    }
}

// ---------------- fp32 GEMM (tiny GEMM3, split-K) ----------------
#define BM 128
#define BK 16

template<int BN_, int TN_>
__global__ __launch_bounds__(256)
void k_gemm(const float* __restrict__ A, int lda,
            const float* __restrict__ B, int ldb,
            float* __restrict__ Cout, int ldc,
            int Nd, int Kloop, int partStride) {
    __shared__ float As[2][BM][BK];
    __shared__ float Bs[2][BK][BN_];

    const int tid = threadIdx.x;
    const int tx = tid & 15;
    const int ty = tid >> 4;
    const int m0 = blockIdx.y * BM;
    const int n0 = blockIdx.x * BN_;

    A += (size_t)blockIdx.z * Kloop;
    B += (size_t)blockIdx.z * Kloop * ldb;
    Cout += (size_t)blockIdx.z * partStride;

    const int arow0 = tid >> 2;
    const int arow1 = arow0 + 64;
    const int ac4 = (tid & 3) * 4;
    const float* gA0 = A + (size_t)(m0 + arow0) * lda + ac4;
    const float* gA1 = A + (size_t)(m0 + arow1) * lda + ac4;

    const int BQ = BN_ / 4;
    const int bkr0 = tid / BQ;
    const int bc0 = (tid % BQ) * 4;
    const float* gB0 = B + (size_t)bkr0 * ldb + n0 + bc0;
    const bool bp0 = (n0 + bc0) < Nd;

    float acc[8][TN_];
    #pragma unroll
    for (int i = 0; i < 8; ++i)
        #pragma unroll
        for (int j = 0; j < TN_; ++j) acc[i][j] = 0.f;

    const int KT = Kloop / BK;

    cpasync16(&As[0][arow0][ac4], gA0, true);
    cpasync16(&As[0][arow1][ac4], gA1, true);
    cpasync16(&Bs[0][bkr0][bc0], gB0, bp0);
    cp_commit();

    int buf = 0;
    for (int kt = 0; kt < KT; ++kt) {
        if (kt + 1 < KT) {
            int ko = (kt + 1) * BK;
            cpasync16(&As[buf ^ 1][arow0][ac4], gA0 + ko, true);
            cpasync16(&As[buf ^ 1][arow1][ac4], gA1 + ko, true);
            cpasync16(&Bs[buf ^ 1][bkr0][bc0], gB0 + (size_t)ko * ldb, bp0);
            cp_commit();
            cp_wait1();
        } else {
            cp_wait0();
        }
        __syncthreads();

        #pragma unroll
        for (int k = 0; k < BK; ++k) {
            float a[8];
            #pragma unroll
            for (int i = 0; i < 8; ++i) a[i] = As[buf][ty * 8 + i][k];
            float b[TN_];
            #pragma unroll
            for (int j = 0; j < TN_; j += 4) {
                float4 v = *reinterpret_cast<const float4*>(&Bs[buf][k][tx * TN_ + j]);
                b[j] = v.x; b[j + 1] = v.y; b[j + 2] = v.z; b[j + 3] = v.w;
            }
            #pragma unroll
            for (int i = 0; i < 8; ++i)
                #pragma unroll
                for (int j = 0; j < TN_; ++j)
                    acc[i][j] += a[i] * b[j];
        }
        __syncthreads();
        buf ^= 1;
    }

    #pragma unroll
    for (int i = 0; i < 8; ++i) {
        int m = m0 + ty * 8 + i;
        #pragma unroll
        for (int j = 0; j < TN_; j += 4) {
            int n = n0 + tx * TN_ + j;
            if (n < Nd) {
                float4 v = make_float4(acc[i][j], acc[i][j + 1], acc[i][j + 2], acc[i][j + 3]);
                *reinterpret_cast<float4*>(&Cout[(size_t)m * ldc + n]) = v;
            }
        }
    }
}

// ---------------- host orchestration ----------------
// fp32 propagation, small C. Seed hop fused (u computed on the fly from feat).
static float* run_prop_s(const int* nbr, const int* cnt, const float* dvec,
                         const float* feat, const float* w, int C,
                         float* u, float* va, float* vb) {
    float* vin = va;
    float* vout = vb;
    if (C == C_IN) {
        k_spmm_s<32, 1><<<NN / 8, 256>>>(nbr, cnt, feat, u, vin, w, 5, C, dvec);
        for (int k = 4; k >= 1; --k) {
            k_spmm_s<32, 0><<<NN / 8, 256>>>(nbr, cnt, vin, u, vout, w, k, C, dvec);
            float* t = vin; vin = vout; vout = t;
        }
    } else {
        k_spmm_s<8, 1><<<NN / 32, 256>>>(nbr, cnt, feat, u, vin, w, 5, C, dvec);
        for (int k = 4; k >= 1; --k) {
            k_spmm_s<8, 0><<<NN / 32, 256>>>(nbr, cnt, vin, u, vout, w, k, C, dvec);
            float* t = vin; vin = vout; vout = t;
        }
    }
    return vin;
}

extern "C" void kernel_launch(void* const* d_in, const int* in_sizes, int n_in,
                              void* d_out, int out_size) {
    const float* x  = (const float*)d_in[0];
    const int*   ei = (const int*)  d_in[1];
    const float* w1 = (const float*)d_in[2];
    const float* w2 = (const float*)d_in[3];
    const float* w3 = (const float*)d_in[4];
    const float* W1 = (const float*)d_in[5];
    const float* b1 = (const float*)d_in[6];
    const float* W2 = (const float*)d_in[7];
    const float* b2 = (const float*)d_in[8];
    const float* W3 = (const float*)d_in[9];
    const float* b3 = (const float*)d_in[10];
    float* out = (float*)d_out;

    unsigned *adj, *rA, *rB;
    int *nbr, *cnt;
    float *dvec, *u, *va, *vb, *h2, *g3, *g3p;
    __half *vha, *vhb, *zhi, *zlo, *w1h, *w2h, *h1h;
    cudaGetSymbolAddress((void**)&adj,  g_adj);
    cudaGetSymbolAddress((void**)&rA,   g_rA);
    cudaGetSymbolAddress((void**)&rB,   g_rB);
    cudaGetSymbolAddress((void**)&nbr,  g_nbr);
    cudaGetSymbolAddress((void**)&cnt,  g_cnt);
    cudaGetSymbolAddress((void**)&dvec, g_dvec);
    cudaGetSymbolAddress((void**)&u,    g_u);
    cudaGetSymbolAddress((void**)&va,   g_va);
    cudaGetSymbolAddress((void**)&vb,   g_vb);
    cudaGetSymbolAddress((void**)&h2,   g_h2);
    cudaGetSymbolAddress((void**)&g3,   g_g3);
    cudaGetSymbolAddress((void**)&g3p,  g_g3p);
    cudaGetSymbolAddress((void**)&vha,  g_vha);
    cudaGetSymbolAddress((void**)&vhb,  g_vhb);
    cudaGetSymbolAddress((void**)&zhi,  g_zhi);
    cudaGetSymbolAddress((void**)&zlo,  g_zlo);
    cudaGetSymbolAddress((void**)&w1h,  g_w1h);
    cudaGetSymbolAddress((void**)&w2h,  g_w2h);
    cudaGetSymbolAddress((void**)&h1h,  g_h1h);

    cudaFuncSetAttribute((const void*)k_gemm_h<1, 1>, cudaFuncAttributeMaxDynamicSharedMemorySize, SMEM_BYTES_2A);
    cudaFuncSetAttribute((const void*)k_gemm_h<2, 0>, cudaFuncAttributeMaxDynamicSharedMemorySize, SMEM_BYTES_1A);

    // ---- adjacency + lists + reach + deg (list build fused with reach seed) ----
    k_zero_u32<<<(NN * WORDS + 255) / 256, 256>>>(adj, NN * WORDS);
    k_build_adj<<<EE / 256, 256>>>(ei, adj);
    k_build_fused<<<NN / 8, 256>>>(adj, nbr, cnt, rA);       // list + R0 = I|A
    k_reach_iter<0><<<NN, 64>>>(nbr, cnt, rA, rB, (float*)0);
    k_reach_iter<0><<<NN, 64>>>(nbr, cnt, rB, rA, (float*)0);
    k_reach_iter<0><<<NN, 64>>>(nbr, cnt, rA, rB, (float*)0);
    k_reach_iter<1><<<NN, 64>>>(nbr, cnt, rB, rA, dvec);     // fused deg

    // weight conversions, single launch
    k_tohalf2<<<(C_IN * H1D + H1D * H2D + 255) / 256, 256>>>(W1, w1h, C_IN * H1D,
                                                             W2, w2h, H1D * H2D);

    // ---- layer 1: h1 = relu((M1_hat x) W1 + b1), single-fp16 output ----
    {
        float* v = run_prop_s(nbr, cnt, dvec, x, w1, C_IN, u, va, vb);
        k_scale_split<<<(NN * C_IN + 255) / 256, 256>>>(v, dvec, w1, zhi, zlo, C_IN);
        dim3 grid(H1D / TBN, NN / TBM, 1);
        k_gemm_h<1, 1><<<grid, 256, SMEM_BYTES_2A>>>(zhi, zlo, C_IN, w1h, H1D,
                                                     b1, (float*)0, h1h, H1D, H1D, C_IN);
    }

    // ---- layer 2: h2 = relu(M2_hat (h1 W2) + b2) ----
    {
        dim3 grid((H2D + TBN - 1) / TBN, NN / TBM, 1);
        k_gemm_h<2, 0><<<grid, 256, SMEM_BYTES_1A>>>(h1h, (const __half*)0, H1D, w2h, H2D,
                                                     dvec, u, vha, H2D, H2D, H1D);
        k_spmm_h<0><<<NN, 256>>>(nbr, cnt, vha, u, vhb, (float*)0, w2, 5, H2D, (float*)0, (float*)0);
        k_spmm_h<0><<<NN, 256>>>(nbr, cnt, vhb, u, vha, (float*)0, w2, 4, H2D, (float*)0, (float*)0);
        k_spmm_h<0><<<NN, 256>>>(nbr, cnt, vha, u, vhb, (float*)0, w2, 3, H2D, (float*)0, (float*)0);
        k_spmm_h<0><<<NN, 256>>>(nbr, cnt, vhb, u, vha, (float*)0, w2, 2, H2D, (float*)0, (float*)0);
        k_spmm_h<1><<<NN, 256>>>(nbr, cnt, vha, u, (__half*)0, h2, w2, 1, H2D, dvec, b2);
    }

    // ---- layer 3: out = relu(M3_hat (h2 W3) + b3), fp32 split-K GEMM ----
    {
        dim3 grid(1, NN / BM, SK3);
        k_gemm<64, 4><<<grid, 256>>>(h2, H2D, W3, ODIM, g3p, ODIM, ODIM, H2D / SK3, NN * ODIM);
        k_reduce_sk<<<(NN * ODIM + 255) / 256, 256>>>(g3p, g3, NN * ODIM);
        float* v = run_prop_s(nbr, cnt, dvec, g3, w3, ODIM, u, va, vb);
        k_final<<<(NN * ODIM + 255) / 256, 256>>>(v, dvec, w3, b3, out, ODIM);
    }
}